// round 8
// baseline (speedup 1.0000x reference)
#include <cuda_runtime.h>
#include <cuda_bf16.h>
#include <math.h>
#include <stdint.h>

#define BB 4
#define SS 2048
#define HH 1024
#define NHEADS 8
#define HD 128
#define ROWS (BB*SS)
#define METAD 256

typedef __nv_bfloat16 bf16;

// ---------------- scratch (device globals; uint4 => 16B aligned) ----------
__device__ float g_scr[(size_t)BB*NHEADS*SS*SS];            // fp32 scores
__device__ float g_h1 [(size_t)ROWS*METAD];
__device__ float g_h2 [(size_t)ROWS*(METAD/2)];
__device__ uint4 g_xh [(size_t)ROWS*HH/8],          g_xl [(size_t)ROWS*HH/8];
__device__ uint4 g_qh [(size_t)ROWS*3*HH/8],        g_ql [(size_t)ROWS*3*HH/8];
__device__ uint4 g_sh [(size_t)BB*NHEADS*SS*SS/8],  g_sl [(size_t)BB*NHEADS*SS*SS/8];
__device__ uint4 g_ch [(size_t)ROWS*HH/8],          g_cl [(size_t)ROWS*HH/8];
__device__ uint4 g_ah [(size_t)ROWS*HH/8],          g_al [(size_t)ROWS*HH/8];
__device__ uint4 g_hh [(size_t)ROWS*METAD/8],       g_hl [(size_t)ROWS*METAD/8];
__device__ uint4 g_iwh[(size_t)3*HH*HH/8],          g_iwl[(size_t)3*HH*HH/8];
__device__ uint4 g_owh[(size_t)HH*HH/8],            g_owl[(size_t)HH*HH/8];
__device__ uint4 g_w1h[(size_t)METAD*2*HH/8],       g_w1l[(size_t)METAD*2*HH/8];
__device__ uint4 g_w2h[(size_t)(METAD/2)*METAD/8],  g_w2l[(size_t)(METAD/2)*METAD/8];

// ---------------- helpers ----------------
__device__ __forceinline__ void sp1(float v, bf16& h, bf16& l) {
    h = __float2bfloat16_rn(v);
    l = __float2bfloat16_rn(v - __bfloat162float(h));
}
__device__ __forceinline__ void mma16(float c[4], const uint32_t a[4], const uint32_t b[2]) {
    asm volatile("mma.sync.aligned.m16n8k16.row.col.f32.bf16.bf16.f32 "
        "{%0,%1,%2,%3}, {%4,%5,%6,%7}, {%8,%9}, {%0,%1,%2,%3};"
        : "+f"(c[0]), "+f"(c[1]), "+f"(c[2]), "+f"(c[3])
        : "r"(a[0]), "r"(a[1]), "r"(a[2]), "r"(a[3]), "r"(b[0]), "r"(b[1]));
}
__device__ __forceinline__ uint32_t smem_u32(const void* p) {
    uint32_t a;
    asm("{ .reg .u64 t; cvta.to.shared.u64 t, %1; cvt.u32.u64 %0, t; }" : "=r"(a) : "l"(p));
    return a;
}
__device__ __forceinline__ void cp16(uint32_t d, const void* s) {
    asm volatile("cp.async.cg.shared.global [%0], [%1], 16;" :: "r"(d), "l"(s) : "memory");
}
__device__ __forceinline__ void cp_commit() { asm volatile("cp.async.commit_group;" ::: "memory"); }
__device__ __forceinline__ void cp_wait0()  { asm volatile("cp.async.wait_group 0;" ::: "memory"); }
__device__ __forceinline__ void cp_wait1()  { asm volatile("cp.async.wait_group 1;" ::: "memory"); }

#define LDSM4(r, a) \
    asm volatile("ldmatrix.sync.aligned.m8n8.x4.shared.b16 {%0,%1,%2,%3}, [%4];" \
        : "=r"((r)[0]), "=r"((r)[1]), "=r"((r)[2]), "=r"((r)[3]) : "r"(a))
#define LDSM4T(r, a) \
    asm volatile("ldmatrix.sync.aligned.m8n8.x4.trans.shared.b16 {%0,%1,%2,%3}, [%4];" \
        : "=r"((r)[0]), "=r"((r)[1]), "=r"((r)[2]), "=r"((r)[3]) : "r"(a))

// ---------------------------------------------------------------------------
// bf16x3 GEMM, ldmatrix + cp.async double-buffer.
//   C = alpha*(A.op(B)) + bias (+C) ; optional bf16 hi/lo outputs.
//   A: [M,K] row-major hi/lo bf16.  BT: B=[N,K] (row-major); else B=[K,N].
//   Block tile 128x128, k-tile 32, 256 thr (8 warps of 64x32). K mult of 32.
// ---------------------------------------------------------------------------
template<bool BT>
__global__ __launch_bounds__(256)
void gmma(const bf16* __restrict__ Ah, const bf16* __restrict__ Al,
          const bf16* __restrict__ Bh, const bf16* __restrict__ Bl,
          float* __restrict__ C, bf16* __restrict__ Ch, bf16* __restrict__ Cl,
          int K, int lda, int ldb, int ldc,
          long long aOuter, long long aInner, long long bOuter, long long bInner,
          long long cOuter, long long cInner, int innerCount,
          const float* __restrict__ bias, float alpha, int accumulate)
{
    extern __shared__ __align__(128) char smem[];
    constexpr int BSZ   = BT ? 8192 : 8704;        // one B buffer (hi or lo)
    constexpr int STAGE = 16384 + 2 * BSZ;
    const uint32_t sb = smem_u32(smem);
    const int t = threadIdx.x, lane = t & 31, warp = t >> 5;
    const int gid = lane >> 2, tig = lane & 3;
    const int m_off = (warp >> 2) * 64, n_off = (warp & 3) * 32;
    const int brow = blockIdx.y * 128, bcol = blockIdx.x * 128;

    const int z = blockIdx.z, zo = z / innerCount, zi = z - zo * innerCount;
    const long long ao = zo * aOuter + zi * aInner;
    const long long bo = zo * bOuter + zi * bInner;
    const long long co = zo * cOuter + zi * cInner;
    Ah += ao; Al += ao; Bh += bo; Bl += bo;
    if (C)  C  += co;
    if (Ch) { Ch += co; Cl += co; }

    // ---- ldmatrix per-thread addresses (stage 0) ----
    uint32_t aadr[4][2], badr[2][2];
#pragma unroll
    for (int mi = 0; mi < 4; mi++) {
        int ar = m_off + mi * 16 + (lane & 7) + ((lane >> 3) & 1) * 8;
        int x = (ar >> 1) & 3;
#pragma unroll
        for (int ks = 0; ks < 2; ks++) {
            int g = ks * 2 + ((lane >> 4) & 1);
            aadr[mi][ks] = sb + ar * 64 + ((g ^ x) << 4);
        }
    }
    if (BT) {
#pragma unroll
        for (int p = 0; p < 2; p++) {
            int br = n_off + p * 16 + ((lane >> 4) & 1) * 8 + (lane & 7);
            int x = (br >> 1) & 3;
#pragma unroll
            for (int ks = 0; ks < 2; ks++) {
                int g = ks * 2 + ((lane >> 3) & 1);
                badr[p][ks] = sb + 16384 + br * 64 + ((g ^ x) << 4);
            }
        }
    } else {
#pragma unroll
        for (int p = 0; p < 2; p++) {
            int ncol = n_off + p * 16 + ((lane >> 4) & 1) * 8;
            int krl = (lane & 7) + ((lane >> 3) & 1) * 8;
#pragma unroll
            for (int ks = 0; ks < 2; ks++)
                badr[p][ks] = sb + 16384 + (ks * 16 + krl) * 272 + ncol * 2;
        }
    }

    float acc[4][4][4];
#pragma unroll
    for (int mi = 0; mi < 4; mi++)
#pragma unroll
        for (int ni = 0; ni < 4; ni++)
#pragma unroll
            for (int r = 0; r < 4; r++) acc[mi][ni][r] = 0.0f;

    const int NT = K >> 5;
    auto prefetch = [&](int c) {
        const uint32_t s = sb + (c & 1) * STAGE;
        const long long kofs = (long long)c * 32;
#pragma unroll
        for (int i = 0; i < 2; i++) {          // A: 128 rows x 4 segs
            int id = t + i * 256, row = id >> 2, g = id & 3;
            uint32_t d = s + row * 64 + ((g ^ ((row >> 1) & 3)) << 4);
            long long so = (long long)(brow + row) * lda + kofs + g * 8;
            cp16(d, Ah + so);
            cp16(d + 8192, Al + so);
        }
        if (BT) {
#pragma unroll
            for (int i = 0; i < 2; i++) {
                int id = t + i * 256, row = id >> 2, g = id & 3;
                uint32_t d = s + 16384 + row * 64 + ((g ^ ((row >> 1) & 3)) << 4);
                long long so = (long long)(bcol + row) * ldb + kofs + g * 8;
                cp16(d, Bh + so);
                cp16(d + BSZ, Bl + so);
            }
        } else {
#pragma unroll
            for (int i = 0; i < 2; i++) {      // 32 k-rows x 16 segs, pitch 272B
                int id = t + i * 256, row = id >> 4, seg = id & 15;
                uint32_t d = s + 16384 + row * 272 + seg * 16;
                long long so = (kofs + row) * (long long)ldb + bcol + seg * 8;
                cp16(d, Bh + so);
                cp16(d + BSZ, Bl + so);
            }
        }
        cp_commit();
    };

    prefetch(0);
    if (NT > 1) prefetch(1);

    for (int c = 0; c < NT; c++) {
        if (c + 1 < NT) cp_wait1(); else cp_wait0();
        __syncthreads();
        const uint32_t so = (c & 1) * STAGE;
#pragma unroll
        for (int ks = 0; ks < 2; ks++) {
            uint32_t bh[2][4], bl[2][4];
#pragma unroll
            for (int p = 0; p < 2; p++) {
                if (BT) {
                    LDSM4(bh[p], badr[p][ks] + so);
                    LDSM4(bl[p], badr[p][ks] + so + BSZ);
                } else {
                    LDSM4T(bh[p], badr[p][ks] + so);
                    LDSM4T(bl[p], badr[p][ks] + so + BSZ);
                }
            }
#pragma unroll
            for (int mi = 0; mi < 4; mi++) {
                uint32_t ah4[4], al4[4];
                LDSM4(ah4, aadr[mi][ks] + so);
                LDSM4(al4, aadr[mi][ks] + so + 8192);
#pragma unroll
                for (int ni = 0; ni < 4; ni++) {
                    int p = ni >> 1, q = (ni & 1) * 2;
                    uint32_t bhh[2] = {bh[p][q], bh[p][q + 1]};
                    uint32_t bll[2] = {bl[p][q], bl[p][q + 1]};
                    mma16(acc[mi][ni], ah4, bhh);
                    mma16(acc[mi][ni], ah4, bll);
                    mma16(acc[mi][ni], al4, bhh);
                }
            }
        }
        __syncthreads();
        if (c + 2 < NT) prefetch(c + 2);
    }

    // ---- epilogue ----
#pragma unroll
    for (int mi = 0; mi < 4; mi++)
#pragma unroll
        for (int ni = 0; ni < 4; ni++) {
            int m = brow + m_off + mi * 16 + gid;
            int n = bcol + n_off + ni * 8 + 2 * tig;
            float b0 = 0.f, b1 = 0.f;
            if (bias) { b0 = bias[n]; b1 = bias[n + 1]; }
#pragma unroll
            for (int h = 0; h < 2; h++) {
                long long r = m + h * 8;
                float vx = acc[mi][ni][h * 2 + 0] * alpha + b0;
                float vy = acc[mi][ni][h * 2 + 1] * alpha + b1;
                if (accumulate) { vx += C[r * ldc + n]; vy += C[r * ldc + n + 1]; }
                if (C) *reinterpret_cast<float2*>(C + r * ldc + n) = make_float2(vx, vy);
                if (Ch) {
                    bf16 hh_, ll_;
                    sp1(vx, hh_, ll_); Ch[r * ldc + n] = hh_;     Cl[r * ldc + n] = ll_;
                    sp1(vy, hh_, ll_); Ch[r * ldc + n + 1] = hh_; Cl[r * ldc + n + 1] = ll_;
                }
            }
        }
}

// ---------------- elementwise ----------------
__global__ void split_kernel(const float* __restrict__ W, bf16* __restrict__ Wh,
                             bf16* __restrict__ Wl, int n4)
{
    int i = blockIdx.x * 256 + threadIdx.x;
    if (i >= n4) return;
    float4 v = reinterpret_cast<const float4*>(W)[i];
    bf16 h, l;
    sp1(v.x, h, l); Wh[i*4+0] = h; Wl[i*4+0] = l;
    sp1(v.y, h, l); Wh[i*4+1] = h; Wl[i*4+1] = l;
    sp1(v.z, h, l); Wh[i*4+2] = h; Wl[i*4+2] = l;
    sp1(v.w, h, l); Wh[i*4+3] = h; Wl[i*4+3] = l;
}

__global__ void add_pos_split(const float* __restrict__ h, const float* __restrict__ p,
                              bf16* __restrict__ xh, bf16* __restrict__ xl)
{
    long long i = (long long)blockIdx.x * 256 + threadIdx.x;
    const long long P4 = (long long)SS * HH / 4;
    float4 hv = reinterpret_cast<const float4*>(h)[i];
    float4 pv = reinterpret_cast<const float4*>(p)[i % P4];
    hv.x += pv.x; hv.y += pv.y; hv.z += pv.z; hv.w += pv.w;
    bf16 hb, lb;
    sp1(hv.x, hb, lb); xh[i*4+0] = hb; xl[i*4+0] = lb;
    sp1(hv.y, hb, lb); xh[i*4+1] = hb; xl[i*4+1] = lb;
    sp1(hv.z, hb, lb); xh[i*4+2] = hb; xl[i*4+2] = lb;
    sp1(hv.w, hb, lb); xh[i*4+3] = hb; xl[i*4+3] = lb;
}

// softmax: fp32 scores in, bf16 hi/lo probs out
__global__ __launch_bounds__(256)
void softmax_kernel(const float* __restrict__ S, const int* __restrict__ mask,
                    bf16* __restrict__ Ph, bf16* __restrict__ Pl)
{
    const long long row = blockIdx.x;
    const int b = (int)(row >> 14);
    const float* p = S + row * (long long)SS;
    const int* mrow = mask + (long long)b * SS;
    const int t = threadIdx.x;
    float vals[8], m = -1e30f;
#pragma unroll
    for (int k = 0; k < 8; k++) {
        int j = t + k * 256;
        float v = p[j];
        v = (mrow[j] != 0) ? v : -1e9f;
        vals[k] = v; m = fmaxf(m, v);
    }
    __shared__ float red[256];
    red[t] = m; __syncthreads();
    for (int s = 128; s > 0; s >>= 1) { if (t < s) red[t] = fmaxf(red[t], red[t + s]); __syncthreads(); }
    const float rmax = red[0]; __syncthreads();
    float sum = 0.0f;
#pragma unroll
    for (int k = 0; k < 8; k++) { vals[k] = expf(vals[k] - rmax); sum += vals[k]; }
    red[t] = sum; __syncthreads();
    for (int s = 128; s > 0; s >>= 1) { if (t < s) red[t] += red[t + s]; __syncthreads(); }
    const float inv = 1.0f / red[0];
#pragma unroll
    for (int k = 0; k < 8; k++) {
        float v = vals[k] * inv;
        bf16 h, l; sp1(v, h, l);
        long long o = row * SS + t + k * 256;
        Ph[o] = h; Pl[o] = l;
    }
}

__global__ void ln_relu_kernel(float* __restrict__ X, const float* __restrict__ g,
                               const float* __restrict__ beta, int width,
                               bf16* Xh, bf16* Xl)
{
    const int row = blockIdx.x, t = threadIdx.x;
    float v = X[(long long)row * width + t];
    __shared__ float red[256];
    red[t] = v; __syncthreads();
    for (int s = blockDim.x >> 1; s > 0; s >>= 1) { if (t < s) red[t] += red[t + s]; __syncthreads(); }
    const float mu = red[0] / width; __syncthreads();
    const float d = v - mu;
    red[t] = d * d; __syncthreads();
    for (int s = blockDim.x >> 1; s > 0; s >>= 1) { if (t < s) red[t] += red[t + s]; __syncthreads(); }
    const float var = red[0] / width;
    float y = d * rsqrtf(var + 1e-5f) * g[t] + beta[t];
    y = fmaxf(y, 0.0f);
    X[(long long)row * width + t] = y;
    if (Xh) { bf16 h, l; sp1(y, h, l); Xh[(long long)row * width + t] = h; Xl[(long long)row * width + t] = l; }
}

__global__ void final_kernel(const float* __restrict__ H2, const float* __restrict__ w3,
                             const float* __restrict__ b3, const int* __restrict__ tok,
                             const int* __restrict__ mask, const float* __restrict__ table,
                             float* __restrict__ out)
{
    const int row = blockIdx.x, t = threadIdx.x;
    float v = H2[(long long)row * 128 + t] * w3[t];
    __shared__ float red[128];
    red[t] = v; __syncthreads();
    for (int s = 64; s > 0; s >>= 1) { if (t < s) red[t] += red[t + s]; __syncthreads(); }
    if (t == 0) {
        float base = red[0] + b3[0];
        float w = base * (1.0f + table[tok[row]]);
        w = fminf(fmaxf(w, 0.1f), 5.0f);
        out[row] = (mask[row] != 0) ? w : 0.0f;
    }
}

// ---------------- launch ----------------
extern "C" void kernel_launch(void* const* d_in, const int* in_sizes, int n_in,
                              void* d_out, int out_size)
{
    const float* hidden = (const float*)d_in[0];
    const int*   tok    = (const int*)d_in[1];
    const int*   mask   = (const int*)d_in[2];
    const float* pos    = (const float*)d_in[3];
    const float* in_w   = (const float*)d_in[4];
    const float* in_b   = (const float*)d_in[5];
    const float* out_w  = (const float*)d_in[6];
    const float* out_b  = (const float*)d_in[7];
    const float* w1     = (const float*)d_in[8];
    const float* b1     = (const float*)d_in[9];
    const float* g1     = (const float*)d_in[10];
    const float* be1    = (const float*)d_in[11];
    const float* w2     = (const float*)d_in[12];
    const float* b2     = (const float*)d_in[13];
    const float* g2     = (const float*)d_in[14];
    const float* be2    = (const float*)d_in[15];
    const float* w3     = (const float*)d_in[16];
    const float* b3     = (const float*)d_in[17];
    const float* table  = (const float*)d_in[18];
    float* out = (float*)d_out;

    float *scr, *h1, *h2;
    bf16 *xh,*xl,*qh,*ql,*sh,*sl,*ch,*cl,*ah,*al,*hh,*hl;
    bf16 *iwh,*iwl,*owh,*owl,*w1h,*w1l,*w2h,*w2l;
    { void* p;
      cudaGetSymbolAddress(&p, g_scr); scr = (float*)p;
      cudaGetSymbolAddress(&p, g_h1);  h1  = (float*)p;
      cudaGetSymbolAddress(&p, g_h2);  h2  = (float*)p;
      cudaGetSymbolAddress(&p, g_xh); xh=(bf16*)p;  cudaGetSymbolAddress(&p, g_xl); xl=(bf16*)p;
      cudaGetSymbolAddress(&p, g_qh); qh=(bf16*)p;  cudaGetSymbolAddress(&p, g_ql); ql=(bf16*)p;
      cudaGetSymbolAddress(&p, g_sh); sh=(bf16*)p;  cudaGetSymbolAddress(&p, g_sl); sl=(bf16*)p;
      cudaGetSymbolAddress(&p, g_ch); ch=(bf16*)p;  cudaGetSymbolAddress(&p, g_cl); cl=(bf16*)p;
      cudaGetSymbolAddress(&p, g_ah); ah=(bf16*)p;  cudaGetSymbolAddress(&p, g_al); al=(bf16*)p;
      cudaGetSymbolAddress(&p, g_hh); hh=(bf16*)p;  cudaGetSymbolAddress(&p, g_hl); hl=(bf16*)p;
      cudaGetSymbolAddress(&p, g_iwh); iwh=(bf16*)p; cudaGetSymbolAddress(&p, g_iwl); iwl=(bf16*)p;
      cudaGetSymbolAddress(&p, g_owh); owh=(bf16*)p; cudaGetSymbolAddress(&p, g_owl); owl=(bf16*)p;
      cudaGetSymbolAddress(&p, g_w1h); w1h=(bf16*)p; cudaGetSymbolAddress(&p, g_w1l); w1l=(bf16*)p;
      cudaGetSymbolAddress(&p, g_w2h); w2h=(bf16*)p; cudaGetSymbolAddress(&p, g_w2l); w2l=(bf16*)p;
    }
    cudaFuncSetAttribute(gmma<true>,  cudaFuncAttributeMaxDynamicSharedMemorySize, 65536);
    cudaFuncSetAttribute(gmma<false>, cudaFuncAttributeMaxDynamicSharedMemorySize, 67584);

    const long long SH_  = (long long)SS * 3 * HH;
    const long long SSQ  = (long long)SS * SS;

    split_kernel<<<(3*HH*HH/4 + 255)/256, 256>>>(in_w, iwh, iwl, 3*HH*HH/4);
    split_kernel<<<(HH*HH/4 + 255)/256, 256>>>(out_w, owh, owl, HH*HH/4);
    split_kernel<<<(METAD*2*HH/4 + 255)/256, 256>>>(w1, w1h, w1l, METAD*2*HH/4);
    split_kernel<<<((METAD/2)*METAD/4 + 255)/256, 256>>>(w2, w2h, w2l, (METAD/2)*METAD/4);
    add_pos_split<<<ROWS*HH/4/256, 256>>>(hidden, pos, xh, xl);

    // qkv = x @ in_w^T + in_b  -> hi/lo only
    gmma<true><<<dim3(24, 64, 1), 256, 65536>>>(
        xh, xl, iwh, iwl, nullptr, qh, ql,
        HH, HH, HH, 3*HH, 0,0, 0,0, 0,0, 1, in_b, 1.0f, 0);

    // scores = Q K^T / sqrt(128) -> fp32
    gmma<true><<<dim3(16, 16, BB*NHEADS), 256, 65536>>>(
        qh, ql, qh + HH, ql + HH, scr, nullptr, nullptr,
        HD, 3*HH, 3*HH, SS,
        SH_, HD, SH_, HD, (long long)NHEADS*SSQ, SSQ, NHEADS,
        nullptr, 0.08838834764831843f, 0);

    softmax_kernel<<<BB*NHEADS*SS, 256>>>(scr, mask, sh, sl);

    // ctx = P @ V -> hi/lo
    gmma<false><<<dim3(1, 16, BB*NHEADS), 256, 67584>>>(
        sh, sl, qh + 2*HH, ql + 2*HH, nullptr, ch, cl,
        SS, SS, 3*HH, HH,
        (long long)NHEADS*SSQ, SSQ, SH_, HD, (long long)SS*HH, HD, NHEADS,
        nullptr, 1.0f, 0);

    // attended = ctx @ out_w^T + out_b -> hi/lo
    gmma<true><<<dim3(8, 64, 1), 256, 65536>>>(
        ch, cl, owh, owl, nullptr, ah, al,
        HH, HH, HH, HH, 0,0, 0,0, 0,0, 1, out_b, 1.0f, 0);

    // h1 = x @ w1a^T + b1 ; += att @ w1b^T   (fp32)
    gmma<true><<<dim3(2, 64, 1), 256, 65536>>>(
        xh, xl, w1h, w1l, h1, nullptr, nullptr,
        HH, HH, 2*HH, METAD, 0,0, 0,0, 0,0, 1, b1, 1.0f, 0);
    gmma<true><<<dim3(2, 64, 1), 256, 65536>>>(
        ah, al, w1h + HH, w1l + HH, h1, nullptr, nullptr,
        HH, HH, 2*HH, METAD, 0,0, 0,0, 0,0, 1, nullptr, 1.0f, 1);

    ln_relu_kernel<<<ROWS, METAD>>>(h1, g1, be1, METAD, hh, hl);

    // h2 = h1 @ w2^T + b2 (fp32)
    gmma<true><<<dim3(1, 64, 1), 256, 65536>>>(
        hh, hl, w2h, w2l, h2, nullptr, nullptr,
        METAD, METAD, METAD, METAD/2, 0,0, 0,0, 0,0, 1, b2, 1.0f, 0);

    ln_relu_kernel<<<ROWS, METAD/2>>>(h2, g2, be2, METAD/2, nullptr, nullptr);
    final_kernel<<<ROWS, 128>>>(h2, w3, b3, tok, mask, table, out);
}

// round 9
// speedup vs baseline: 1.3670x; 1.3670x over previous
#include <cuda_runtime.h>
#include <cuda_bf16.h>
#include <math.h>
#include <stdint.h>

#define BB 4
#define SS 2048
#define HH 1024
#define NHEADS 8
#define HD 128
#define ROWS (BB*SS)
#define METAD 256

typedef __nv_bfloat16 bf16;

// ---------------- scratch ----------------
__device__ float g_scr[(size_t)BB*NHEADS*SS*SS];
__device__ float g_h1 [(size_t)ROWS*METAD];
__device__ float g_h2 [(size_t)ROWS*(METAD/2)];
__device__ uint4 g_xh [(size_t)ROWS*HH/8],          g_xl [(size_t)ROWS*HH/8];
__device__ uint4 g_qh [(size_t)ROWS*3*HH/8],        g_ql [(size_t)ROWS*3*HH/8];
__device__ uint4 g_sh [(size_t)BB*NHEADS*SS*SS/8],  g_sl [(size_t)BB*NHEADS*SS*SS/8];
__device__ uint4 g_ch [(size_t)ROWS*HH/8],          g_cl [(size_t)ROWS*HH/8];
__device__ uint4 g_ah [(size_t)ROWS*HH/8],          g_al [(size_t)ROWS*HH/8];
__device__ uint4 g_hh [(size_t)ROWS*METAD/8],       g_hl [(size_t)ROWS*METAD/8];
__device__ uint4 g_iwh[(size_t)3*HH*HH/8],          g_iwl[(size_t)3*HH*HH/8];
__device__ uint4 g_owh[(size_t)HH*HH/8],            g_owl[(size_t)HH*HH/8];
__device__ uint4 g_w1h[(size_t)METAD*2*HH/8],       g_w1l[(size_t)METAD*2*HH/8];
__device__ uint4 g_w2h[(size_t)(METAD/2)*METAD/8],  g_w2l[(size_t)(METAD/2)*METAD/8];

// ---------------- helpers ----------------
__device__ __forceinline__ void sp1(float v, bf16& h, bf16& l) {
    h = __float2bfloat16_rn(v);
    l = __float2bfloat16_rn(v - __bfloat162float(h));
}
__device__ __forceinline__ void mma16(float c[4], const uint32_t a[4], const uint32_t b[2]) {
    asm volatile("mma.sync.aligned.m16n8k16.row.col.f32.bf16.bf16.f32 "
        "{%0,%1,%2,%3}, {%4,%5,%6,%7}, {%8,%9}, {%0,%1,%2,%3};"
        : "+f"(c[0]), "+f"(c[1]), "+f"(c[2]), "+f"(c[3])
        : "r"(a[0]), "r"(a[1]), "r"(a[2]), "r"(a[3]), "r"(b[0]), "r"(b[1]));
}
// swizzled [m][kw] layout, 16 packed words/row
__device__ __forceinline__ int swz(int m, int kw) {
    int g = kw >> 2, j = kw & 3;
    return m * 16 + ((g ^ ((m >> 1) & 3)) << 2) + j;
}

// ---------------------------------------------------------------------------
// bf16x3 GEMM (R5 structure, precomputed hi/lo operands):
//   C = alpha*(A.op(B)) + bias (+C); optional bf16 hi/lo outputs.
//   BT: B=[N,K] row-major hi/lo; else B=[K,N]. Tile 128x128, ktile 32, 256 thr.
// ---------------------------------------------------------------------------
template<bool BT>
__global__ __launch_bounds__(256)
void gmma(const bf16* __restrict__ Ah, const bf16* __restrict__ Al,
          const bf16* __restrict__ Bh, const bf16* __restrict__ Bl,
          float* __restrict__ C, bf16* __restrict__ Ch, bf16* __restrict__ Cl,
          int K, int lda, int ldb, int ldc,
          long long aOuter, long long aInner, long long bOuter, long long bInner,
          long long cOuter, long long cInner, int innerCount,
          const float* __restrict__ bias, float alpha, int accumulate)
{
    const int z = blockIdx.z, zo = z / innerCount, zi = z - zo * innerCount;
    const long long ao = zo * aOuter + zi * aInner;
    const long long bo = zo * bOuter + zi * bInner;
    const long long co = zo * cOuter + zi * cInner;
    Ah += ao; Al += ao; Bh += bo; Bl += bo;
    if (C)  C  += co;
    if (Ch) { Ch += co; Cl += co; }

    __shared__ __align__(16) uint32_t AsH[128 * 16], AsL[128 * 16];
    __shared__ __align__(16) uint32_t BsH[16 * 136], BsL[16 * 136];

    const int t = threadIdx.x, lane = t & 31, warp = t >> 5;
    const int gid = lane >> 2, tig = lane & 3;
    const int m_off = (warp >> 2) * 64, n_off = (warp & 3) * 32;
    const int brow = blockIdx.y * 128, bcol = blockIdx.x * 128;

    float acc[4][4][4];
#pragma unroll
    for (int mi = 0; mi < 4; mi++)
#pragma unroll
        for (int ni = 0; ni < 4; ni++)
#pragma unroll
            for (int r = 0; r < 4; r++) acc[mi][ni][r] = 0.0f;

    uint4 cAh[2], cAl[2], nAh[2], nAl[2];
    uint4 cBh[2], cBl[2], nBh[2], nBl[2];            // BT
    uint2 cB2[2][4], nB2[2][4];                      // NN: [i][h0,h1,l0,l1]

    auto ldg = [&](int kt, uint4* bAh, uint4* bAl, uint4* bBh, uint4* bBl,
                   uint2 (*bB2)[4]) {
#pragma unroll
        for (int i = 0; i < 2; i++) {
            int idx = t + i * 256, row = idx >> 2, quad = idx & 3;
            long long o = (long long)(brow + row) * lda + kt + quad * 8;
            bAh[i] = *reinterpret_cast<const uint4*>(Ah + o);
            bAl[i] = *reinterpret_cast<const uint4*>(Al + o);
        }
        if (BT) {
#pragma unroll
            for (int i = 0; i < 2; i++) {
                int idx = t + i * 256, row = idx >> 2, quad = idx & 3;
                long long o = (long long)(bcol + row) * ldb + kt + quad * 8;
                bBh[i] = *reinterpret_cast<const uint4*>(Bh + o);
                bBl[i] = *reinterpret_cast<const uint4*>(Bl + o);
            }
        } else {
#pragma unroll
            for (int i = 0; i < 2; i++) {
                int idx = t + i * 256, kp = idx >> 5, q = idx & 31;
                long long o = (long long)(kt + 2 * kp) * ldb + bcol + q * 4;
                bB2[i][0] = *reinterpret_cast<const uint2*>(Bh + o);
                bB2[i][1] = *reinterpret_cast<const uint2*>(Bh + o + ldb);
                bB2[i][2] = *reinterpret_cast<const uint2*>(Bl + o);
                bB2[i][3] = *reinterpret_cast<const uint2*>(Bl + o + ldb);
            }
        }
    };
    auto sts = [&](const uint4* bAh, const uint4* bAl, const uint4* bBh,
                   const uint4* bBl, const uint2 (*bB2)[4]) {
#pragma unroll
        for (int i = 0; i < 2; i++) {
            int idx = t + i * 256, row = idx >> 2, quad = idx & 3;
            int base = row * 16 + ((quad ^ ((row >> 1) & 3)) << 2);
            *reinterpret_cast<uint4*>(&AsH[base]) = bAh[i];
            *reinterpret_cast<uint4*>(&AsL[base]) = bAl[i];
        }
        if (BT) {
#pragma unroll
            for (int i = 0; i < 2; i++) {
                int idx = t + i * 256, row = idx >> 2, quad = idx & 3;
                int base = row * 16 + ((quad ^ ((row >> 1) & 3)) << 2);
                *reinterpret_cast<uint4*>(&BsH[base]) = bBh[i];
                *reinterpret_cast<uint4*>(&BsL[base]) = bBl[i];
            }
        } else {
#pragma unroll
            for (int i = 0; i < 2; i++) {
                int idx = t + i * 256, kp = idx >> 5, q = idx & 31;
                int base = kp * 136 + q * 4;
                uint4 h, l;
                h.x = __byte_perm(bB2[i][0].x, bB2[i][1].x, 0x5410);
                h.y = __byte_perm(bB2[i][0].x, bB2[i][1].x, 0x7632);
                h.z = __byte_perm(bB2[i][0].y, bB2[i][1].y, 0x5410);
                h.w = __byte_perm(bB2[i][0].y, bB2[i][1].y, 0x7632);
                l.x = __byte_perm(bB2[i][2].x, bB2[i][3].x, 0x5410);
                l.y = __byte_perm(bB2[i][2].x, bB2[i][3].x, 0x7632);
                l.z = __byte_perm(bB2[i][2].y, bB2[i][3].y, 0x5410);
                l.w = __byte_perm(bB2[i][2].y, bB2[i][3].y, 0x7632);
                *reinterpret_cast<uint4*>(&BsH[base]) = h;
                *reinterpret_cast<uint4*>(&BsL[base]) = l;
            }
        }
    };

    ldg(0, cAh, cAl, cBh, cBl, cB2);
    sts(cAh, cAl, cBh, cBl, cB2);
    __syncthreads();

    for (int kt = 0; kt < K; kt += 32) {
        const bool more = (kt + 32) < K;
        if (more) ldg(kt + 32, nAh, nAl, nBh, nBl, nB2);
#pragma unroll
        for (int ks = 0; ks < 2; ks++) {
            const int k0 = ks * 8 + tig, k1 = k0 + 4;
            uint32_t bH[4][2], bL[4][2];
#pragma unroll
            for (int ni = 0; ni < 4; ni++) {
                int n0 = n_off + ni * 8 + gid;
                int j0, j1;
                if (BT) { j0 = swz(n0, k0); j1 = swz(n0, k1); }
                else    { j0 = k0 * 136 + n0; j1 = k1 * 136 + n0; }
                bH[ni][0] = BsH[j0]; bH[ni][1] = BsH[j1];
                bL[ni][0] = BsL[j0]; bL[ni][1] = BsL[j1];
            }
#pragma unroll
            for (int mi = 0; mi < 4; mi++) {
                int m0 = m_off + mi * 16 + gid;
                int i00 = swz(m0, k0), i10 = swz(m0 + 8, k0);
                int i01 = swz(m0, k1), i11 = swz(m0 + 8, k1);
                uint32_t aH[4] = {AsH[i00], AsH[i10], AsH[i01], AsH[i11]};
                uint32_t aL[4] = {AsL[i00], AsL[i10], AsL[i01], AsL[i11]};
#pragma unroll
                for (int ni = 0; ni < 4; ni++) {
                    mma16(acc[mi][ni], aH, bH[ni]);
                    mma16(acc[mi][ni], aH, bL[ni]);
                    mma16(acc[mi][ni], aL, bH[ni]);
                }
            }
        }
        __syncthreads();
        if (more) { sts(nAh, nAl, nBh, nBl, nB2); __syncthreads(); }
    }

    // ---- epilogue ----
#pragma unroll
    for (int mi = 0; mi < 4; mi++)
#pragma unroll
        for (int ni = 0; ni < 4; ni++) {
            int m = brow + m_off + mi * 16 + gid;
            int n = bcol + n_off + ni * 8 + 2 * tig;
            float b0 = 0.f, b1 = 0.f;
            if (bias) { b0 = bias[n]; b1 = bias[n + 1]; }
#pragma unroll
            for (int h = 0; h < 2; h++) {
                long long r = m + h * 8;
                float vx = acc[mi][ni][h * 2 + 0] * alpha + b0;
                float vy = acc[mi][ni][h * 2 + 1] * alpha + b1;
                if (accumulate) { vx += C[r * ldc + n]; vy += C[r * ldc + n + 1]; }
                if (C) *reinterpret_cast<float2*>(C + r * ldc + n) = make_float2(vx, vy);
                if (Ch) {
                    bf16 hh_, ll_;
                    sp1(vx, hh_, ll_); Ch[r * ldc + n] = hh_;     Cl[r * ldc + n] = ll_;
                    sp1(vy, hh_, ll_); Ch[r * ldc + n + 1] = hh_; Cl[r * ldc + n + 1] = ll_;
                }
            }
        }
}

// ---------------- elementwise ----------------
__global__ void split_kernel(const float* __restrict__ W, bf16* __restrict__ Wh,
                             bf16* __restrict__ Wl, int n4)
{
    int i = blockIdx.x * 256 + threadIdx.x;
    if (i >= n4) return;
    float4 v = reinterpret_cast<const float4*>(W)[i];
    bf16 h, l;
    sp1(v.x, h, l); Wh[i*4+0] = h; Wl[i*4+0] = l;
    sp1(v.y, h, l); Wh[i*4+1] = h; Wl[i*4+1] = l;
    sp1(v.z, h, l); Wh[i*4+2] = h; Wl[i*4+2] = l;
    sp1(v.w, h, l); Wh[i*4+3] = h; Wl[i*4+3] = l;
}

__global__ void add_pos_split(const float* __restrict__ h, const float* __restrict__ p,
                              bf16* __restrict__ xh, bf16* __restrict__ xl)
{
    long long i = (long long)blockIdx.x * 256 + threadIdx.x;
    const long long P4 = (long long)SS * HH / 4;
    float4 hv = reinterpret_cast<const float4*>(h)[i];
    float4 pv = reinterpret_cast<const float4*>(p)[i % P4];
    hv.x += pv.x; hv.y += pv.y; hv.z += pv.z; hv.w += pv.w;
    bf16 hb, lb;
    sp1(hv.x, hb, lb); xh[i*4+0] = hb; xl[i*4+0] = lb;
    sp1(hv.y, hb, lb); xh[i*4+1] = hb; xl[i*4+1] = lb;
    sp1(hv.z, hb, lb); xh[i*4+2] = hb; xl[i*4+2] = lb;
    sp1(hv.w, hb, lb); xh[i*4+3] = hb; xl[i*4+3] = lb;
}

__global__ __launch_bounds__(256)
void softmax_kernel(const float* __restrict__ S, const int* __restrict__ mask,
                    bf16* __restrict__ Ph, bf16* __restrict__ Pl)
{
    const long long row = blockIdx.x;
    const int b = (int)(row >> 14);
    const float* p = S + row * (long long)SS;
    const int* mrow = mask + (long long)b * SS;
    const int t = threadIdx.x;
    float vals[8], m = -1e30f;
#pragma unroll
    for (int k = 0; k < 8; k++) {
        int j = t + k * 256;
        float v = p[j];
        v = (mrow[j] != 0) ? v : -1e9f;
        vals[k] = v; m = fmaxf(m, v);
    }
    __shared__ float red[256];
    red[t] = m; __syncthreads();
    for (int s = 128; s > 0; s >>= 1) { if (t < s) red[t] = fmaxf(red[t], red[t + s]); __syncthreads(); }
    const float rmax = red[0]; __syncthreads();
    float sum = 0.0f;
#pragma unroll
    for (int k = 0; k < 8; k++) { vals[k] = expf(vals[k] - rmax); sum += vals[k]; }
    red[t] = sum; __syncthreads();
    for (int s = 128; s > 0; s >>= 1) { if (t < s) red[t] += red[t + s]; __syncthreads(); }
    const float inv = 1.0f / red[0];
#pragma unroll
    for (int k = 0; k < 8; k++) {
        float v = vals[k] * inv;
        bf16 h, l; sp1(v, h, l);
        long long o = row * SS + t + k * 256;
        Ph[o] = h; Pl[o] = l;
    }
}

__global__ void ln_relu_kernel(float* __restrict__ X, const float* __restrict__ g,
                               const float* __restrict__ beta, int width,
                               bf16* Xh, bf16* Xl)
{
    const int row = blockIdx.x, t = threadIdx.x;
    float v = X[(long long)row * width + t];
    __shared__ float red[256];
    red[t] = v; __syncthreads();
    for (int s = blockDim.x >> 1; s > 0; s >>= 1) { if (t < s) red[t] += red[t + s]; __syncthreads(); }
    const float mu = red[0] / width; __syncthreads();
    const float d = v - mu;
    red[t] = d * d; __syncthreads();
    for (int s = blockDim.x >> 1; s > 0; s >>= 1) { if (t < s) red[t] += red[t + s]; __syncthreads(); }
    const float var = red[0] / width;
    float y = d * rsqrtf(var + 1e-5f) * g[t] + beta[t];
    y = fmaxf(y, 0.0f);
    X[(long long)row * width + t] = y;
    if (Xh) { bf16 h, l; sp1(y, h, l); Xh[(long long)row * width + t] = h; Xl[(long long)row * width + t] = l; }
}

__global__ void final_kernel(const float* __restrict__ H2, const float* __restrict__ w3,
                             const float* __restrict__ b3, const int* __restrict__ tok,
                             const int* __restrict__ mask, const float* __restrict__ table,
                             float* __restrict__ out)
{
    const int row = blockIdx.x, t = threadIdx.x;
    float v = H2[(long long)row * 128 + t] * w3[t];
    __shared__ float red[128];
    red[t] = v; __syncthreads();
    for (int s = 64; s > 0; s >>= 1) { if (t < s) red[t] += red[t + s]; __syncthreads(); }
    if (t == 0) {
        float base = red[0] + b3[0];
        float w = base * (1.0f + table[tok[row]]);
        w = fminf(fmaxf(w, 0.1f), 5.0f);
        out[row] = (mask[row] != 0) ? w : 0.0f;
    }
}

// ---------------- launch ----------------
extern "C" void kernel_launch(void* const* d_in, const int* in_sizes, int n_in,
                              void* d_out, int out_size)
{
    const float* hidden = (const float*)d_in[0];
    const int*   tok    = (const int*)d_in[1];
    const int*   mask   = (const int*)d_in[2];
    const float* pos    = (const float*)d_in[3];
    const float* in_w   = (const float*)d_in[4];
    const float* in_b   = (const float*)d_in[5];
    const float* out_w  = (const float*)d_in[6];
    const float* out_b  = (const float*)d_in[7];
    const float* w1     = (const float*)d_in[8];
    const float* b1     = (const float*)d_in[9];
    const float* g1     = (const float*)d_in[10];
    const float* be1    = (const float*)d_in[11];
    const float* w2     = (const float*)d_in[12];
    const float* b2     = (const float*)d_in[13];
    const float* g2     = (const float*)d_in[14];
    const float* be2    = (const float*)d_in[15];
    const float* w3     = (const float*)d_in[16];
    const float* b3     = (const float*)d_in[17];
    const float* table  = (const float*)d_in[18];
    float* out = (float*)d_out;

    float *scr, *h1, *h2;
    bf16 *xh,*xl,*qh,*ql,*sh,*sl,*ch,*cl,*ah,*al,*hh,*hl;
    bf16 *iwh,*iwl,*owh,*owl,*w1h,*w1l,*w2h,*w2l;
    { void* p;
      cudaGetSymbolAddress(&p, g_scr); scr = (float*)p;
      cudaGetSymbolAddress(&p, g_h1);  h1  = (float*)p;
      cudaGetSymbolAddress(&p, g_h2);  h2  = (float*)p;
      cudaGetSymbolAddress(&p, g_xh); xh=(bf16*)p;  cudaGetSymbolAddress(&p, g_xl); xl=(bf16*)p;
      cudaGetSymbolAddress(&p, g_qh); qh=(bf16*)p;  cudaGetSymbolAddress(&p, g_ql); ql=(bf16*)p;
      cudaGetSymbolAddress(&p, g_sh); sh=(bf16*)p;  cudaGetSymbolAddress(&p, g_sl); sl=(bf16*)p;
      cudaGetSymbolAddress(&p, g_ch); ch=(bf16*)p;  cudaGetSymbolAddress(&p, g_cl); cl=(bf16*)p;
      cudaGetSymbolAddress(&p, g_ah); ah=(bf16*)p;  cudaGetSymbolAddress(&p, g_al); al=(bf16*)p;
      cudaGetSymbolAddress(&p, g_hh); hh=(bf16*)p;  cudaGetSymbolAddress(&p, g_hl); hl=(bf16*)p;
      cudaGetSymbolAddress(&p, g_iwh); iwh=(bf16*)p; cudaGetSymbolAddress(&p, g_iwl); iwl=(bf16*)p;
      cudaGetSymbolAddress(&p, g_owh); owh=(bf16*)p; cudaGetSymbolAddress(&p, g_owl); owl=(bf16*)p;
      cudaGetSymbolAddress(&p, g_w1h); w1h=(bf16*)p; cudaGetSymbolAddress(&p, g_w1l); w1l=(bf16*)p;
      cudaGetSymbolAddress(&p, g_w2h); w2h=(bf16*)p; cudaGetSymbolAddress(&p, g_w2l); w2l=(bf16*)p;
    }

    const long long SH_ = (long long)SS * 3 * HH;
    const long long SSQ = (long long)SS * SS;

    split_kernel<<<(3*HH*HH/4 + 255)/256, 256>>>(in_w, iwh, iwl, 3*HH*HH/4);
    split_kernel<<<(HH*HH/4 + 255)/256, 256>>>(out_w, owh, owl, HH*HH/4);
    split_kernel<<<(METAD*2*HH/4 + 255)/256, 256>>>(w1, w1h, w1l, METAD*2*HH/4);
    split_kernel<<<((METAD/2)*METAD/4 + 255)/256, 256>>>(w2, w2h, w2l, (METAD/2)*METAD/4);
    add_pos_split<<<ROWS*HH/4/256, 256>>>(hidden, pos, xh, xl);

    // qkv = x @ in_w^T + in_b  -> hi/lo only
    gmma<true><<<dim3(24, 64, 1), 256>>>(
        xh, xl, iwh, iwl, nullptr, qh, ql,
        HH, HH, HH, 3*HH, 0,0, 0,0, 0,0, 1, in_b, 1.0f, 0);

    // scores = Q K^T / sqrt(128) -> fp32
    gmma<true><<<dim3(16, 16, BB*NHEADS), 256>>>(
        qh, ql, qh + HH, ql + HH, scr, nullptr, nullptr,
        HD, 3*HH, 3*HH, SS,
        SH_, HD, SH_, HD, (long long)NHEADS*SSQ, SSQ, NHEADS,
        nullptr, 0.08838834764831843f, 0);

    softmax_kernel<<<BB*NHEADS*SS, 256>>>(scr, mask, sh, sl);

    // ctx = P @ V -> hi/lo
    gmma<false><<<dim3(1, 16, BB*NHEADS), 256>>>(
        sh, sl, qh + 2*HH, ql + 2*HH, nullptr, ch, cl,
        SS, SS, 3*HH, HH,
        (long long)NHEADS*SSQ, SSQ, SH_, HD, (long long)SS*HH, HD, NHEADS,
        nullptr, 1.0f, 0);

    // attended = ctx @ out_w^T + out_b -> hi/lo
    gmma<true><<<dim3(8, 64, 1), 256>>>(
        ch, cl, owh, owl, nullptr, ah, al,
        HH, HH, HH, HH, 0,0, 0,0, 0,0, 1, out_b, 1.0f, 0);

    // h1 = x @ w1a^T + b1 ; += att @ w1b^T (fp32)
    gmma<true><<<dim3(2, 64, 1), 256>>>(
        xh, xl, w1h, w1l, h1, nullptr, nullptr,
        HH, HH, 2*HH, METAD, 0,0, 0,0, 0,0, 1, b1, 1.0f, 0);
    gmma<true><<<dim3(2, 64, 1), 256>>>(
        ah, al, w1h + HH, w1l + HH, h1, nullptr, nullptr,
        HH, HH, 2*HH, METAD, 0,0, 0,0, 0,0, 1, nullptr, 1.0f, 1);

    ln_relu_kernel<<<ROWS, METAD>>>(h1, g1, be1, METAD, hh, hl);

    // h2 = h1 @ w2^T + b2 (fp32)
    gmma<true><<<dim3(1, 64, 1), 256>>>(
        hh, hl, w2h, w2l, h2, nullptr, nullptr,
        METAD, METAD, METAD, METAD/2, 0,0, 0,0, 0,0, 1, b2, 1.0f, 0);

    ln_relu_kernel<<<ROWS, METAD/2>>>(h2, g2, be2, METAD/2, nullptr, nullptr);
    final_kernel<<<ROWS, 128>>>(h2, w3, b3, tok, mask, table, out);
}

// round 10
// speedup vs baseline: 1.5328x; 1.1213x over previous
#include <cuda_runtime.h>
#include <cuda_fp16.h>
#include <math.h>
#include <stdint.h>

#define BB 4
#define SS 2048
#define HH 1024
#define NHEADS 8
#define HD 128
#define ROWS (BB*SS)
#define METAD 256

typedef __half hf;

// ---------------- scratch ----------------
__device__ float g_scr[(size_t)BB*NHEADS*SS*SS];
__device__ float g_h1 [(size_t)ROWS*METAD];
__device__ float g_h2 [(size_t)ROWS*(METAD/2)];
__device__ uint4 g_xh [(size_t)ROWS*HH/8],          g_xl [(size_t)ROWS*HH/8];
__device__ uint4 g_qh [(size_t)ROWS*3*HH/8],        g_ql [(size_t)ROWS*3*HH/8];
__device__ uint4 g_sh [(size_t)BB*NHEADS*SS*SS/8],  g_sl [(size_t)BB*NHEADS*SS*SS/8];
__device__ uint4 g_ch [(size_t)ROWS*HH/8],          g_cl [(size_t)ROWS*HH/8];
__device__ uint4 g_ah [(size_t)ROWS*HH/8],          g_al [(size_t)ROWS*HH/8];
__device__ uint4 g_hh [(size_t)ROWS*METAD/8],       g_hl [(size_t)ROWS*METAD/8];
__device__ uint4 g_iwh[(size_t)3*HH*HH/8];
__device__ uint4 g_owh[(size_t)HH*HH/8];
__device__ uint4 g_w1h[(size_t)METAD*2*HH/8],       g_w1l[(size_t)METAD*2*HH/8];
__device__ uint4 g_w2h[(size_t)(METAD/2)*METAD/8],  g_w2l[(size_t)(METAD/2)*METAD/8];

// ---------------- helpers ----------------
__device__ __forceinline__ void sp1(float v, hf& h, hf& l) {
    h = __float2half_rn(v);
    l = __float2half_rn(v - __half2float(h));
}
__device__ __forceinline__ void mma16(float c[4], const uint32_t a[4], const uint32_t b[2]) {
    asm volatile("mma.sync.aligned.m16n8k16.row.col.f32.f16.f16.f32 "
        "{%0,%1,%2,%3}, {%4,%5,%6,%7}, {%8,%9}, {%0,%1,%2,%3};"
        : "+f"(c[0]), "+f"(c[1]), "+f"(c[2]), "+f"(c[3])
        : "r"(a[0]), "r"(a[1]), "r"(a[2]), "r"(a[3]), "r"(b[0]), "r"(b[1]));
}
__device__ __forceinline__ int swz(int m, int kw) {
    int g = kw >> 2, j = kw & 3;
    return m * 16 + ((g ^ ((m >> 1) & 3)) << 2) + j;
}

// ---------------------------------------------------------------------------
// fp16 compensated GEMM:
//   TERMS==3: D = AhiBhi + AhiBlo + AloBhi  (err ~u^2)
//   TERMS==2: D = AhiBhi + AloBhi = A.fl16(B)  (err ~u; B-lo never loaded)
//   BT: B=[N,K] row-major hi(/lo); else B=[K,N]. Tile 128x128, ktile 32, 256 thr.
// ---------------------------------------------------------------------------
template<bool BT, int TERMS>
__global__ __launch_bounds__(256)
void gmma(const hf* __restrict__ Ah, const hf* __restrict__ Al,
          const hf* __restrict__ Bh, const hf* __restrict__ Bl,
          float* __restrict__ C, hf* __restrict__ Ch, hf* __restrict__ Cl,
          int K, int lda, int ldb, int ldc,
          long long aOuter, long long aInner, long long bOuter, long long bInner,
          long long cOuter, long long cInner, int innerCount,
          const float* __restrict__ bias, float alpha, int accumulate)
{
    const int z = blockIdx.z, zo = z / innerCount, zi = z - zo * innerCount;
    const long long ao = zo * aOuter + zi * aInner;
    const long long bo = zo * bOuter + zi * bInner;
    const long long co = zo * cOuter + zi * cInner;
    Ah += ao; Al += ao; Bh += bo;
    if (TERMS == 3) Bl += bo;
    if (C)  C  += co;
    if (Ch) { Ch += co; Cl += co; }

    __shared__ __align__(16) uint32_t AsH[128 * 16], AsL[128 * 16];
    __shared__ __align__(16) uint32_t BsH[16 * 136], BsL[16 * 136];

    const int t = threadIdx.x, lane = t & 31, warp = t >> 5;
    const int gid = lane >> 2, tig = lane & 3;
    const int m_off = (warp >> 2) * 64, n_off = (warp & 3) * 32;
    const int brow = blockIdx.y * 128, bcol = blockIdx.x * 128;

    float acc[4][4][4];
#pragma unroll
    for (int mi = 0; mi < 4; mi++)
#pragma unroll
        for (int ni = 0; ni < 4; ni++)
#pragma unroll
            for (int r = 0; r < 4; r++) acc[mi][ni][r] = 0.0f;

    uint4 cAh[2], cAl[2], nAh[2], nAl[2];
    uint4 cBh[2], cBl[2], nBh[2], nBl[2];            // BT
    uint2 cB2[2][4], nB2[2][4];                      // NN

    auto ldg = [&](int kt, uint4* bAh, uint4* bAl, uint4* bBh, uint4* bBl,
                   uint2 (*bB2)[4]) {
#pragma unroll
        for (int i = 0; i < 2; i++) {
            int idx = t + i * 256, row = idx >> 2, quad = idx & 3;
            long long o = (long long)(brow + row) * lda + kt + quad * 8;
            bAh[i] = *reinterpret_cast<const uint4*>(Ah + o);
            bAl[i] = *reinterpret_cast<const uint4*>(Al + o);
        }
        if (BT) {
#pragma unroll
            for (int i = 0; i < 2; i++) {
                int idx = t + i * 256, row = idx >> 2, quad = idx & 3;
                long long o = (long long)(bcol + row) * ldb + kt + quad * 8;
                bBh[i] = *reinterpret_cast<const uint4*>(Bh + o);
                if (TERMS == 3) bBl[i] = *reinterpret_cast<const uint4*>(Bl + o);
            }
        } else {
#pragma unroll
            for (int i = 0; i < 2; i++) {
                int idx = t + i * 256, kp = idx >> 5, q = idx & 31;
                long long o = (long long)(kt + 2 * kp) * ldb + bcol + q * 4;
                bB2[i][0] = *reinterpret_cast<const uint2*>(Bh + o);
                bB2[i][1] = *reinterpret_cast<const uint2*>(Bh + o + ldb);
                if (TERMS == 3) {
                    bB2[i][2] = *reinterpret_cast<const uint2*>(Bl + o);
                    bB2[i][3] = *reinterpret_cast<const uint2*>(Bl + o + ldb);
                }
            }
        }
    };
    auto sts = [&](const uint4* bAh, const uint4* bAl, const uint4* bBh,
                   const uint4* bBl, const uint2 (*bB2)[4]) {
#pragma unroll
        for (int i = 0; i < 2; i++) {
            int idx = t + i * 256, row = idx >> 2, quad = idx & 3;
            int base = row * 16 + ((quad ^ ((row >> 1) & 3)) << 2);
            *reinterpret_cast<uint4*>(&AsH[base]) = bAh[i];
            *reinterpret_cast<uint4*>(&AsL[base]) = bAl[i];
        }
        if (BT) {
#pragma unroll
            for (int i = 0; i < 2; i++) {
                int idx = t + i * 256, row = idx >> 2, quad = idx & 3;
                int base = row * 16 + ((quad ^ ((row >> 1) & 3)) << 2);
                *reinterpret_cast<uint4*>(&BsH[base]) = bBh[i];
                if (TERMS == 3) *reinterpret_cast<uint4*>(&BsL[base]) = bBl[i];
            }
        } else {
#pragma unroll
            for (int i = 0; i < 2; i++) {
                int idx = t + i * 256, kp = idx >> 5, q = idx & 31;
                int base = kp * 136 + q * 4;
                uint4 h;
                h.x = __byte_perm(bB2[i][0].x, bB2[i][1].x, 0x5410);
                h.y = __byte_perm(bB2[i][0].x, bB2[i][1].x, 0x7632);
                h.z = __byte_perm(bB2[i][0].y, bB2[i][1].y, 0x5410);
                h.w = __byte_perm(bB2[i][0].y, bB2[i][1].y, 0x7632);
                *reinterpret_cast<uint4*>(&BsH[base]) = h;
                if (TERMS == 3) {
                    uint4 l;
                    l.x = __byte_perm(bB2[i][2].x, bB2[i][3].x, 0x5410);
                    l.y = __byte_perm(bB2[i][2].x, bB2[i][3].x, 0x7632);
                    l.z = __byte_perm(bB2[i][2].y, bB2[i][3].y, 0x5410);
                    l.w = __byte_perm(bB2[i][2].y, bB2[i][3].y, 0x7632);
                    *reinterpret_cast<uint4*>(&BsL[base]) = l;
                }
            }
        }
    };

    ldg(0, cAh, cAl, cBh, cBl, cB2);
    sts(cAh, cAl, cBh, cBl, cB2);
    __syncthreads();

    for (int kt = 0; kt < K; kt += 32) {
        const bool more = (kt + 32) < K;
        if (more) ldg(kt + 32, nAh, nAl, nBh, nBl, nB2);
#pragma unroll
        for (int ks = 0; ks < 2; ks++) {
            const int k0 = ks * 8 + tig, k1 = k0 + 4;
            uint32_t bH[4][2], bL[4][2];
#pragma unroll
            for (int ni = 0; ni < 4; ni++) {
                int n0 = n_off + ni * 8 + gid;
                int j0, j1;
                if (BT) { j0 = swz(n0, k0); j1 = swz(n0, k1); }
                else    { j0 = k0 * 136 + n0; j1 = k1 * 136 + n0; }
                bH[ni][0] = BsH[j0]; bH[ni][1] = BsH[j1];
                if (TERMS == 3) { bL[ni][0] = BsL[j0]; bL[ni][1] = BsL[j1]; }
            }
#pragma unroll
            for (int mi = 0; mi < 4; mi++) {
                int m0 = m_off + mi * 16 + gid;
                int i00 = swz(m0, k0), i10 = swz(m0 + 8, k0);
                int i01 = swz(m0, k1), i11 = swz(m0 + 8, k1);
                uint32_t aH[4] = {AsH[i00], AsH[i10], AsH[i01], AsH[i11]};
                uint32_t aL[4] = {AsL[i00], AsL[i10], AsL[i01], AsL[i11]};
#pragma unroll
                for (int ni = 0; ni < 4; ni++) {
                    mma16(acc[mi][ni], aH, bH[ni]);
                    if (TERMS == 3) mma16(acc[mi][ni], aH, bL[ni]);
                    mma16(acc[mi][ni], aL, bH[ni]);
                }
            }
        }
        __syncthreads();
        if (more) { sts(nAh, nAl, nBh, nBl, nB2); __syncthreads(); }
    }

    // ---- epilogue ----
#pragma unroll
    for (int mi = 0; mi < 4; mi++)
#pragma unroll
        for (int ni = 0; ni < 4; ni++) {
            int m = brow + m_off + mi * 16 + gid;
            int n = bcol + n_off + ni * 8 + 2 * tig;
            float b0 = 0.f, b1 = 0.f;
            if (bias) { b0 = bias[n]; b1 = bias[n + 1]; }
#pragma unroll
            for (int h = 0; h < 2; h++) {
                long long r = m + h * 8;
                float vx = acc[mi][ni][h * 2 + 0] * alpha + b0;
                float vy = acc[mi][ni][h * 2 + 1] * alpha + b1;
                if (accumulate) { vx += C[r * ldc + n]; vy += C[r * ldc + n + 1]; }
                if (C) *reinterpret_cast<float2*>(C + r * ldc + n) = make_float2(vx, vy);
                if (Ch) {
                    hf hh_, ll_;
                    sp1(vx, hh_, ll_); Ch[r * ldc + n] = hh_;     Cl[r * ldc + n] = ll_;
                    sp1(vy, hh_, ll_); Ch[r * ldc + n + 1] = hh_; Cl[r * ldc + n + 1] = ll_;
                }
            }
        }
}

// ---------------- elementwise ----------------
__global__ void split_kernel(const float* __restrict__ W, hf* __restrict__ Wh,
                             hf* __restrict__ Wl, int n4)
{
    int i = blockIdx.x * 256 + threadIdx.x;
    if (i >= n4) return;
    float4 v = reinterpret_cast<const float4*>(W)[i];
    hf h, l;
    sp1(v.x, h, l); Wh[i*4+0] = h; if (Wl) Wl[i*4+0] = l;
    sp1(v.y, h, l); Wh[i*4+1] = h; if (Wl) Wl[i*4+1] = l;
    sp1(v.z, h, l); Wh[i*4+2] = h; if (Wl) Wl[i*4+2] = l;
    sp1(v.w, h, l); Wh[i*4+3] = h; if (Wl) Wl[i*4+3] = l;
}

__global__ void add_pos_split(const float* __restrict__ h, const float* __restrict__ p,
                              hf* __restrict__ xh, hf* __restrict__ xl)
{
    long long i = (long long)blockIdx.x * 256 + threadIdx.x;
    const long long P4 = (long long)SS * HH / 4;
    float4 hv = reinterpret_cast<const float4*>(h)[i];
    float4 pv = reinterpret_cast<const float4*>(p)[i % P4];
    hv.x += pv.x; hv.y += pv.y; hv.z += pv.z; hv.w += pv.w;
    hf hb, lb;
    sp1(hv.x, hb, lb); xh[i*4+0] = hb; xl[i*4+0] = lb;
    sp1(hv.y, hb, lb); xh[i*4+1] = hb; xl[i*4+1] = lb;
    sp1(hv.z, hb, lb); xh[i*4+2] = hb; xl[i*4+2] = lb;
    sp1(hv.w, hb, lb); xh[i*4+3] = hb; xl[i*4+3] = lb;
}

__global__ __launch_bounds__(256)
void softmax_kernel(const float* __restrict__ S, const int* __restrict__ mask,
                    hf* __restrict__ Ph, hf* __restrict__ Pl)
{
    const long long row = blockIdx.x;
    const int b = (int)(row >> 14);
    const float* p = S + row * (long long)SS;
    const int* mrow = mask + (long long)b * SS;
    const int t = threadIdx.x;
    float vals[8], m = -1e30f;
#pragma unroll
    for (int k = 0; k < 8; k++) {
        int j = t + k * 256;
        float v = p[j];
        v = (mrow[j] != 0) ? v : -1e9f;
        vals[k] = v; m = fmaxf(m, v);
    }
    __shared__ float red[256];
    red[t] = m; __syncthreads();
    for (int s = 128; s > 0; s >>= 1) { if (t < s) red[t] = fmaxf(red[t], red[t + s]); __syncthreads(); }
    const float rmax = red[0]; __syncthreads();
    float sum = 0.0f;
#pragma unroll
    for (int k = 0; k < 8; k++) { vals[k] = expf(vals[k] - rmax); sum += vals[k]; }
    red[t] = sum; __syncthreads();
    for (int s = 128; s > 0; s >>= 1) { if (t < s) red[t] += red[t + s]; __syncthreads(); }
    const float inv = 1.0f / red[0];
#pragma unroll
    for (int k = 0; k < 8; k++) {
        float v = vals[k] * inv;
        hf h, l; sp1(v, h, l);
        long long o = row * SS + t + k * 256;
        Ph[o] = h; Pl[o] = l;
    }
}

__global__ void ln_relu_kernel(float* __restrict__ X, const float* __restrict__ g,
                               const float* __restrict__ beta, int width,
                               hf* Xh, hf* Xl)
{
    const int row = blockIdx.x, t = threadIdx.x;
    float v = X[(long long)row * width + t];
    __shared__ float red[256];
    red[t] = v; __syncthreads();
    for (int s = blockDim.x >> 1; s > 0; s >>= 1) { if (t < s) red[t] += red[t + s]; __syncthreads(); }
    const float mu = red[0] / width; __syncthreads();
    const float d = v - mu;
    red[t] = d * d; __syncthreads();
    for (int s = blockDim.x >> 1; s > 0; s >>= 1) { if (t < s) red[t] += red[t + s]; __syncthreads(); }
    const float var = red[0] / width;
    float y = d * rsqrtf(var + 1e-5f) * g[t] + beta[t];
    y = fmaxf(y, 0.0f);
    X[(long long)row * width + t] = y;
    if (Xh) { hf h, l; sp1(y, h, l); Xh[(long long)row * width + t] = h; Xl[(long long)row * width + t] = l; }
}

__global__ void final_kernel(const float* __restrict__ H2, const float* __restrict__ w3,
                             const float* __restrict__ b3, const int* __restrict__ tok,
                             const int* __restrict__ mask, const float* __restrict__ table,
                             float* __restrict__ out)
{
    const int row = blockIdx.x, t = threadIdx.x;
    float v = H2[(long long)row * 128 + t] * w3[t];
    __shared__ float red[128];
    red[t] = v; __syncthreads();
    for (int s = 64; s > 0; s >>= 1) { if (t < s) red[t] += red[t + s]; __syncthreads(); }
    if (t == 0) {
        float base = red[0] + b3[0];
        float w = base * (1.0f + table[tok[row]]);
        w = fminf(fmaxf(w, 0.1f), 5.0f);
        out[row] = (mask[row] != 0) ? w : 0.0f;
    }
}

// ---------------- launch ----------------
extern "C" void kernel_launch(void* const* d_in, const int* in_sizes, int n_in,
                              void* d_out, int out_size)
{
    const float* hidden = (const float*)d_in[0];
    const int*   tok    = (const int*)d_in[1];
    const int*   mask   = (const int*)d_in[2];
    const float* pos    = (const float*)d_in[3];
    const float* in_w   = (const float*)d_in[4];
    const float* in_b   = (const float*)d_in[5];
    const float* out_w  = (const float*)d_in[6];
    const float* out_b  = (const float*)d_in[7];
    const float* w1     = (const float*)d_in[8];
    const float* b1     = (const float*)d_in[9];
    const float* g1     = (const float*)d_in[10];
    const float* be1    = (const float*)d_in[11];
    const float* w2     = (const float*)d_in[12];
    const float* b2     = (const float*)d_in[13];
    const float* g2     = (const float*)d_in[14];
    const float* be2    = (const float*)d_in[15];
    const float* w3     = (const float*)d_in[16];
    const float* b3     = (const float*)d_in[17];
    const float* table  = (const float*)d_in[18];
    float* out = (float*)d_out;

    float *scr, *h1, *h2;
    hf *xh,*xl,*qh,*ql,*sh,*sl,*ch,*cl,*ah,*al,*hh,*hl;
    hf *iwh,*owh,*w1h,*w1l,*w2h,*w2l;
    { void* p;
      cudaGetSymbolAddress(&p, g_scr); scr = (float*)p;
      cudaGetSymbolAddress(&p, g_h1);  h1  = (float*)p;
      cudaGetSymbolAddress(&p, g_h2);  h2  = (float*)p;
      cudaGetSymbolAddress(&p, g_xh); xh=(hf*)p;  cudaGetSymbolAddress(&p, g_xl); xl=(hf*)p;
      cudaGetSymbolAddress(&p, g_qh); qh=(hf*)p;  cudaGetSymbolAddress(&p, g_ql); ql=(hf*)p;
      cudaGetSymbolAddress(&p, g_sh); sh=(hf*)p;  cudaGetSymbolAddress(&p, g_sl); sl=(hf*)p;
      cudaGetSymbolAddress(&p, g_ch); ch=(hf*)p;  cudaGetSymbolAddress(&p, g_cl); cl=(hf*)p;
      cudaGetSymbolAddress(&p, g_ah); ah=(hf*)p;  cudaGetSymbolAddress(&p, g_al); al=(hf*)p;
      cudaGetSymbolAddress(&p, g_hh); hh=(hf*)p;  cudaGetSymbolAddress(&p, g_hl); hl=(hf*)p;
      cudaGetSymbolAddress(&p, g_iwh); iwh=(hf*)p;
      cudaGetSymbolAddress(&p, g_owh); owh=(hf*)p;
      cudaGetSymbolAddress(&p, g_w1h); w1h=(hf*)p; cudaGetSymbolAddress(&p, g_w1l); w1l=(hf*)p;
      cudaGetSymbolAddress(&p, g_w2h); w2h=(hf*)p; cudaGetSymbolAddress(&p, g_w2l); w2l=(hf*)p;
    }

    const long long SH_ = (long long)SS * 3 * HH;
    const long long SSQ = (long long)SS * SS;

    split_kernel<<<(3*HH*HH/4 + 255)/256, 256>>>(in_w, iwh, nullptr, 3*HH*HH/4);
    split_kernel<<<(HH*HH/4 + 255)/256, 256>>>(out_w, owh, nullptr, HH*HH/4);
    split_kernel<<<(METAD*2*HH/4 + 255)/256, 256>>>(w1, w1h, w1l, METAD*2*HH/4);
    split_kernel<<<((METAD/2)*METAD/4 + 255)/256, 256>>>(w2, w2h, w2l, (METAD/2)*METAD/4);
    add_pos_split<<<ROWS*HH/4/256, 256>>>(hidden, pos, xh, xl);

    // qkv = x @ fl16(in_w)^T + in_b  -> hi/lo (2-term)
    gmma<true,2><<<dim3(24, 64, 1), 256>>>(
        xh, xl, iwh, nullptr, nullptr, qh, ql,
        HH, HH, HH, 3*HH, 0,0, 0,0, 0,0, 1, in_b, 1.0f, 0);

    // scores = Q . fl16(K)^T / sqrt(128) -> fp32 (2-term)
    gmma<true,2><<<dim3(16, 16, BB*NHEADS), 256>>>(
        qh, ql, qh + HH, nullptr, scr, nullptr, nullptr,
        HD, 3*HH, 3*HH, SS,
        SH_, HD, SH_, HD, (long long)NHEADS*SSQ, SSQ, NHEADS,
        nullptr, 0.08838834764831843f, 0);

    softmax_kernel<<<BB*NHEADS*SS, 256>>>(scr, mask, sh, sl);

    // ctx = P . fl16(V) -> hi/lo (2-term)
    gmma<false,2><<<dim3(1, 16, BB*NHEADS), 256>>>(
        sh, sl, qh + 2*HH, nullptr, nullptr, ch, cl,
        SS, SS, 3*HH, HH,
        (long long)NHEADS*SSQ, SSQ, SH_, HD, (long long)SS*HH, HD, NHEADS,
        nullptr, 1.0f, 0);

    // attended = ctx . fl16(out_w)^T + out_b -> hi/lo (2-term)
    gmma<true,2><<<dim3(8, 64, 1), 256>>>(
        ch, cl, owh, nullptr, nullptr, ah, al,
        HH, HH, HH, HH, 0,0, 0,0, 0,0, 1, out_b, 1.0f, 0);

    // h1 = x @ w1a^T + b1 ; += att @ w1b^T (fp32, 3-term)
    gmma<true,3><<<dim3(2, 64, 1), 256>>>(
        xh, xl, w1h, w1l, h1, nullptr, nullptr,
        HH, HH, 2*HH, METAD, 0,0, 0,0, 0,0, 1, b1, 1.0f, 0);
    gmma<true,3><<<dim3(2, 64, 1), 256>>>(
        ah, al, w1h + HH, w1l + HH, h1, nullptr, nullptr,
        HH, HH, 2*HH, METAD, 0,0, 0,0, 0,0, 1, nullptr, 1.0f, 1);

    ln_relu_kernel<<<ROWS, METAD>>>(h1, g1, be1, METAD, hh, hl);

    // h2 = h1 @ w2^T + b2 (fp32, 3-term)
    gmma<true,3><<<dim3(1, 64, 1), 256>>>(
        hh, hl, w2h, w2l, h2, nullptr, nullptr,
        METAD, METAD, METAD, METAD/2, 0,0, 0,0, 0,0, 1, b2, 1.0f, 0);

    ln_relu_kernel<<<ROWS, METAD/2>>>(h2, g2, be2, METAD/2, nullptr, nullptr);
    final_kernel<<<ROWS, 128>>>(h2, w3, b3, tok, mask, table, out);
}

// round 11
// speedup vs baseline: 1.8673x; 1.2182x over previous
#include <cuda_runtime.h>
#include <cuda_fp16.h>
#include <math.h>
#include <stdint.h>

#define BB 4
#define SS 2048
#define HH 1024
#define NHEADS 8
#define HD 128
#define ROWS (BB*SS)
#define METAD 256

typedef __half hf;

// ---------------- scratch ----------------
__device__ float g_scr[(size_t)BB*NHEADS*SS*SS];
__device__ float g_h1 [(size_t)ROWS*METAD];
__device__ float g_h2 [(size_t)ROWS*(METAD/2)];
__device__ uint4 g_xh [(size_t)ROWS*HH/8],          g_xl [(size_t)ROWS*HH/8];
__device__ uint4 g_qh [(size_t)ROWS*3*HH/8];
__device__ uint4 g_sh [(size_t)BB*NHEADS*SS*SS/8];
__device__ uint4 g_ch [(size_t)ROWS*HH/8];
__device__ uint4 g_ah [(size_t)ROWS*HH/8],          g_al [(size_t)ROWS*HH/8];
__device__ uint4 g_hh [(size_t)ROWS*METAD/8],       g_hl [(size_t)ROWS*METAD/8];
__device__ uint4 g_iwh[(size_t)3*HH*HH/8];
__device__ uint4 g_owh[(size_t)HH*HH/8];
__device__ uint4 g_w1h[(size_t)METAD*2*HH/8],       g_w1l[(size_t)METAD*2*HH/8];
__device__ uint4 g_w2h[(size_t)(METAD/2)*METAD/8],  g_w2l[(size_t)(METAD/2)*METAD/8];

// ---------------- helpers ----------------
__device__ __forceinline__ void sp1(float v, hf& h, hf& l) {
    h = __float2half_rn(v);
    l = __float2half_rn(v - __half2float(h));
}
__device__ __forceinline__ void mma16(float c[4], const uint32_t a[4], const uint32_t b[2]) {
    asm volatile("mma.sync.aligned.m16n8k16.row.col.f32.f16.f16.f32 "
        "{%0,%1,%2,%3}, {%4,%5,%6,%7}, {%8,%9}, {%0,%1,%2,%3};"
        : "+f"(c[0]), "+f"(c[1]), "+f"(c[2]), "+f"(c[3])
        : "r"(a[0]), "r"(a[1]), "r"(a[2]), "r"(a[3]), "r"(b[0]), "r"(b[1]));
}
__device__ __forceinline__ int swz(int m, int kw) {
    int g = kw >> 2, j = kw & 3;
    return m * 16 + ((g ^ ((m >> 1) & 3)) << 2) + j;
}

// ---------------------------------------------------------------------------
// fp16 compensated GEMM:
//   TERMS==3: D = AhiBhi + AhiBlo + AloBhi   (err ~u^2)
//   TERMS==2: D = AhiBhi + AloBhi            (err ~u, B-lo never loaded)
//   TERMS==1: D = AhiBhi                     (plain fp16)
//   BT: B=[N,K] row-major; else B=[K,N]. Tile 128x128, ktile 32, 256 thr.
// ---------------------------------------------------------------------------
template<bool BT, int TERMS>
__global__ __launch_bounds__(256)
void gmma(const hf* __restrict__ Ah, const hf* __restrict__ Al,
          const hf* __restrict__ Bh, const hf* __restrict__ Bl,
          float* __restrict__ C, hf* __restrict__ Ch, hf* __restrict__ Cl,
          int K, int lda, int ldb, int ldc,
          long long aOuter, long long aInner, long long bOuter, long long bInner,
          long long cOuter, long long cInner, int innerCount,
          const float* __restrict__ bias, float alpha, int accumulate)
{
    const int z = blockIdx.z, zo = z / innerCount, zi = z - zo * innerCount;
    const long long ao = zo * aOuter + zi * aInner;
    const long long bo = zo * bOuter + zi * bInner;
    const long long co = zo * cOuter + zi * cInner;
    Ah += ao; Bh += bo;
    if (TERMS >= 2) Al += ao;
    if (TERMS == 3) Bl += bo;
    if (C)  C  += co;
    if (Ch) Ch += co;
    if (Cl) Cl += co;

    __shared__ __align__(16) uint32_t AsH[128 * 16];
    __shared__ __align__(16) uint32_t AsL[(TERMS >= 2) ? 128 * 16 : 4];
    __shared__ __align__(16) uint32_t BsH[16 * 136];
    __shared__ __align__(16) uint32_t BsL[(TERMS == 3) ? 16 * 136 : 4];

    const int t = threadIdx.x, lane = t & 31, warp = t >> 5;
    const int gid = lane >> 2, tig = lane & 3;
    const int m_off = (warp >> 2) * 64, n_off = (warp & 3) * 32;
    const int brow = blockIdx.y * 128, bcol = blockIdx.x * 128;

    float acc[4][4][4];
#pragma unroll
    for (int mi = 0; mi < 4; mi++)
#pragma unroll
        for (int ni = 0; ni < 4; ni++)
#pragma unroll
            for (int r = 0; r < 4; r++) acc[mi][ni][r] = 0.0f;

    uint4 cAh[2], cAl[2], nAh[2], nAl[2];
    uint4 cBh[2], cBl[2], nBh[2], nBl[2];            // BT
    uint2 cB2[2][4], nB2[2][4];                      // NN

    auto ldg = [&](int kt, uint4* bAh, uint4* bAl, uint4* bBh, uint4* bBl,
                   uint2 (*bB2)[4]) {
#pragma unroll
        for (int i = 0; i < 2; i++) {
            int idx = t + i * 256, row = idx >> 2, quad = idx & 3;
            long long o = (long long)(brow + row) * lda + kt + quad * 8;
            bAh[i] = *reinterpret_cast<const uint4*>(Ah + o);
            if (TERMS >= 2) bAl[i] = *reinterpret_cast<const uint4*>(Al + o);
        }
        if (BT) {
#pragma unroll
            for (int i = 0; i < 2; i++) {
                int idx = t + i * 256, row = idx >> 2, quad = idx & 3;
                long long o = (long long)(bcol + row) * ldb + kt + quad * 8;
                bBh[i] = *reinterpret_cast<const uint4*>(Bh + o);
                if (TERMS == 3) bBl[i] = *reinterpret_cast<const uint4*>(Bl + o);
            }
        } else {
#pragma unroll
            for (int i = 0; i < 2; i++) {
                int idx = t + i * 256, kp = idx >> 5, q = idx & 31;
                long long o = (long long)(kt + 2 * kp) * ldb + bcol + q * 4;
                bB2[i][0] = *reinterpret_cast<const uint2*>(Bh + o);
                bB2[i][1] = *reinterpret_cast<const uint2*>(Bh + o + ldb);
                if (TERMS == 3) {
                    bB2[i][2] = *reinterpret_cast<const uint2*>(Bl + o);
                    bB2[i][3] = *reinterpret_cast<const uint2*>(Bl + o + ldb);
                }
            }
        }
    };
    auto sts = [&](const uint4* bAh, const uint4* bAl, const uint4* bBh,
                   const uint4* bBl, const uint2 (*bB2)[4]) {
#pragma unroll
        for (int i = 0; i < 2; i++) {
            int idx = t + i * 256, row = idx >> 2, quad = idx & 3;
            int base = row * 16 + ((quad ^ ((row >> 1) & 3)) << 2);
            *reinterpret_cast<uint4*>(&AsH[base]) = bAh[i];
            if (TERMS >= 2) *reinterpret_cast<uint4*>(&AsL[base]) = bAl[i];
        }
        if (BT) {
#pragma unroll
            for (int i = 0; i < 2; i++) {
                int idx = t + i * 256, row = idx >> 2, quad = idx & 3;
                int base = row * 16 + ((quad ^ ((row >> 1) & 3)) << 2);
                *reinterpret_cast<uint4*>(&BsH[base]) = bBh[i];
                if (TERMS == 3) *reinterpret_cast<uint4*>(&BsL[base]) = bBl[i];
            }
        } else {
#pragma unroll
            for (int i = 0; i < 2; i++) {
                int idx = t + i * 256, kp = idx >> 5, q = idx & 31;
                int base = kp * 136 + q * 4;
                uint4 h;
                h.x = __byte_perm(bB2[i][0].x, bB2[i][1].x, 0x5410);
                h.y = __byte_perm(bB2[i][0].x, bB2[i][1].x, 0x7632);
                h.z = __byte_perm(bB2[i][0].y, bB2[i][1].y, 0x5410);
                h.w = __byte_perm(bB2[i][0].y, bB2[i][1].y, 0x7632);
                *reinterpret_cast<uint4*>(&BsH[base]) = h;
                if (TERMS == 3) {
                    uint4 l;
                    l.x = __byte_perm(bB2[i][2].x, bB2[i][3].x, 0x5410);
                    l.y = __byte_perm(bB2[i][2].x, bB2[i][3].x, 0x7632);
                    l.z = __byte_perm(bB2[i][2].y, bB2[i][3].y, 0x5410);
                    l.w = __byte_perm(bB2[i][2].y, bB2[i][3].y, 0x7632);
                    *reinterpret_cast<uint4*>(&BsL[base]) = l;
                }
            }
        }
    };

    ldg(0, cAh, cAl, cBh, cBl, cB2);
    sts(cAh, cAl, cBh, cBl, cB2);
    __syncthreads();

    for (int kt = 0; kt < K; kt += 32) {
        const bool more = (kt + 32) < K;
        if (more) ldg(kt + 32, nAh, nAl, nBh, nBl, nB2);
#pragma unroll
        for (int ks = 0; ks < 2; ks++) {
            const int k0 = ks * 8 + tig, k1 = k0 + 4;
            uint32_t bH[4][2], bL[4][2];
#pragma unroll
            for (int ni = 0; ni < 4; ni++) {
                int n0 = n_off + ni * 8 + gid;
                int j0, j1;
                if (BT) { j0 = swz(n0, k0); j1 = swz(n0, k1); }
                else    { j0 = k0 * 136 + n0; j1 = k1 * 136 + n0; }
                bH[ni][0] = BsH[j0]; bH[ni][1] = BsH[j1];
                if (TERMS == 3) { bL[ni][0] = BsL[j0]; bL[ni][1] = BsL[j1]; }
            }
#pragma unroll
            for (int mi = 0; mi < 4; mi++) {
                int m0 = m_off + mi * 16 + gid;
                int i00 = swz(m0, k0), i10 = swz(m0 + 8, k0);
                int i01 = swz(m0, k1), i11 = swz(m0 + 8, k1);
                uint32_t aH[4] = {AsH[i00], AsH[i10], AsH[i01], AsH[i11]};
                uint32_t aL[4];
                if (TERMS >= 2) { aL[0] = AsL[i00]; aL[1] = AsL[i10]; aL[2] = AsL[i01]; aL[3] = AsL[i11]; }
#pragma unroll
                for (int ni = 0; ni < 4; ni++) {
                    mma16(acc[mi][ni], aH, bH[ni]);
                    if (TERMS == 3) mma16(acc[mi][ni], aH, bL[ni]);
                    if (TERMS >= 2) mma16(acc[mi][ni], aL, bH[ni]);
                }
            }
        }
        __syncthreads();
        if (more) { sts(nAh, nAl, nBh, nBl, nB2); __syncthreads(); }
    }

    // ---- epilogue ----
#pragma unroll
    for (int mi = 0; mi < 4; mi++)
#pragma unroll
        for (int ni = 0; ni < 4; ni++) {
            int m = brow + m_off + mi * 16 + gid;
            int n = bcol + n_off + ni * 8 + 2 * tig;
            float b0 = 0.f, b1 = 0.f;
            if (bias) { b0 = bias[n]; b1 = bias[n + 1]; }
#pragma unroll
            for (int h = 0; h < 2; h++) {
                long long r = m + h * 8;
                float vx = acc[mi][ni][h * 2 + 0] * alpha + b0;
                float vy = acc[mi][ni][h * 2 + 1] * alpha + b1;
                if (accumulate) { vx += C[r * ldc + n]; vy += C[r * ldc + n + 1]; }
                if (C) *reinterpret_cast<float2*>(C + r * ldc + n) = make_float2(vx, vy);
                if (Ch) {
                    hf hh_, ll_;
                    sp1(vx, hh_, ll_); Ch[r * ldc + n] = hh_;
                    if (Cl) Cl[r * ldc + n] = ll_;
                    sp1(vy, hh_, ll_); Ch[r * ldc + n + 1] = hh_;
                    if (Cl) Cl[r * ldc + n + 1] = ll_;
                }
            }
        }
}

// ---------------- elementwise ----------------
__global__ void split_kernel(const float* __restrict__ W, hf* __restrict__ Wh,
                             hf* __restrict__ Wl, int n4)
{
    int i = blockIdx.x * 256 + threadIdx.x;
    if (i >= n4) return;
    float4 v = reinterpret_cast<const float4*>(W)[i];
    hf h, l;
    sp1(v.x, h, l); Wh[i*4+0] = h; if (Wl) Wl[i*4+0] = l;
    sp1(v.y, h, l); Wh[i*4+1] = h; if (Wl) Wl[i*4+1] = l;
    sp1(v.z, h, l); Wh[i*4+2] = h; if (Wl) Wl[i*4+2] = l;
    sp1(v.w, h, l); Wh[i*4+3] = h; if (Wl) Wl[i*4+3] = l;
}

__global__ void add_pos_split(const float* __restrict__ h, const float* __restrict__ p,
                              hf* __restrict__ xh, hf* __restrict__ xl)
{
    long long i = (long long)blockIdx.x * 256 + threadIdx.x;
    const long long P4 = (long long)SS * HH / 4;
    float4 hv = reinterpret_cast<const float4*>(h)[i];
    float4 pv = reinterpret_cast<const float4*>(p)[i % P4];
    hv.x += pv.x; hv.y += pv.y; hv.z += pv.z; hv.w += pv.w;
    hf hb, lb;
    sp1(hv.x, hb, lb); xh[i*4+0] = hb; xl[i*4+0] = lb;
    sp1(hv.y, hb, lb); xh[i*4+1] = hb; xl[i*4+1] = lb;
    sp1(hv.z, hb, lb); xh[i*4+2] = hb; xl[i*4+2] = lb;
    sp1(hv.w, hb, lb); xh[i*4+3] = hb; xl[i*4+3] = lb;
}

__global__ __launch_bounds__(256)
void softmax_kernel(const float* __restrict__ S, const int* __restrict__ mask,
                    hf* __restrict__ Ph)
{
    const long long row = blockIdx.x;
    const int b = (int)(row >> 14);
    const float* p = S + row * (long long)SS;
    const int* mrow = mask + (long long)b * SS;
    const int t = threadIdx.x;
    float vals[8], m = -1e30f;
#pragma unroll
    for (int k = 0; k < 8; k++) {
        int j = t + k * 256;
        float v = p[j];
        v = (mrow[j] != 0) ? v : -1e9f;
        vals[k] = v; m = fmaxf(m, v);
    }
    __shared__ float red[256];
    red[t] = m; __syncthreads();
    for (int s = 128; s > 0; s >>= 1) { if (t < s) red[t] = fmaxf(red[t], red[t + s]); __syncthreads(); }
    const float rmax = red[0]; __syncthreads();
    float sum = 0.0f;
#pragma unroll
    for (int k = 0; k < 8; k++) { vals[k] = expf(vals[k] - rmax); sum += vals[k]; }
    red[t] = sum; __syncthreads();
    for (int s = 128; s > 0; s >>= 1) { if (t < s) red[t] += red[t + s]; __syncthreads(); }
    const float inv = 1.0f / red[0];
#pragma unroll
    for (int k = 0; k < 8; k++)
        Ph[row * SS + t + k * 256] = __float2half_rn(vals[k] * inv);
}

__global__ void ln_relu_kernel(float* __restrict__ X, const float* __restrict__ g,
                               const float* __restrict__ beta, int width,
                               hf* Xh, hf* Xl)
{
    const int row = blockIdx.x, t = threadIdx.x;
    float v = X[(long long)row * width + t];
    __shared__ float red[256];
    red[t] = v; __syncthreads();
    for (int s = blockDim.x >> 1; s > 0; s >>= 1) { if (t < s) red[t] += red[t + s]; __syncthreads(); }
    const float mu = red[0] / width; __syncthreads();
    const float d = v - mu;
    red[t] = d * d; __syncthreads();
    for (int s = blockDim.x >> 1; s > 0; s >>= 1) { if (t < s) red[t] += red[t + s]; __syncthreads(); }
    const float var = red[0] / width;
    float y = d * rsqrtf(var + 1e-5f) * g[t] + beta[t];
    y = fmaxf(y, 0.0f);
    X[(long long)row * width + t] = y;
    if (Xh) { hf h, l; sp1(y, h, l); Xh[(long long)row * width + t] = h; Xl[(long long)row * width + t] = l; }
}

__global__ void final_kernel(const float* __restrict__ H2, const float* __restrict__ w3,
                             const float* __restrict__ b3, const int* __restrict__ tok,
                             const int* __restrict__ mask, const float* __restrict__ table,
                             float* __restrict__ out)
{
    const int row = blockIdx.x, t = threadIdx.x;
    float v = H2[(long long)row * 128 + t] * w3[t];
    __shared__ float red[128];
    red[t] = v; __syncthreads();
    for (int s = 64; s > 0; s >>= 1) { if (t < s) red[t] += red[t + s]; __syncthreads(); }
    if (t == 0) {
        float base = red[0] + b3[0];
        float w = base * (1.0f + table[tok[row]]);
        w = fminf(fmaxf(w, 0.1f), 5.0f);
        out[row] = (mask[row] != 0) ? w : 0.0f;
    }
}

// ---------------- launch ----------------
extern "C" void kernel_launch(void* const* d_in, const int* in_sizes, int n_in,
                              void* d_out, int out_size)
{
    const float* hidden = (const float*)d_in[0];
    const int*   tok    = (const int*)d_in[1];
    const int*   mask   = (const int*)d_in[2];
    const float* pos    = (const float*)d_in[3];
    const float* in_w   = (const float*)d_in[4];
    const float* in_b   = (const float*)d_in[5];
    const float* out_w  = (const float*)d_in[6];
    const float* out_b  = (const float*)d_in[7];
    const float* w1     = (const float*)d_in[8];
    const float* b1     = (const float*)d_in[9];
    const float* g1     = (const float*)d_in[10];
    const float* be1    = (const float*)d_in[11];
    const float* w2     = (const float*)d_in[12];
    const float* b2     = (const float*)d_in[13];
    const float* g2     = (const float*)d_in[14];
    const float* be2    = (const float*)d_in[15];
    const float* w3     = (const float*)d_in[16];
    const float* b3     = (const float*)d_in[17];
    const float* table  = (const float*)d_in[18];
    float* out = (float*)d_out;

    float *scr, *h1, *h2;
    hf *xh,*xl,*qh,*sh,*ch,*ah,*al,*hh,*hl;
    hf *iwh,*owh,*w1h,*w1l,*w2h,*w2l;
    { void* p;
      cudaGetSymbolAddress(&p, g_scr); scr = (float*)p;
      cudaGetSymbolAddress(&p, g_h1);  h1  = (float*)p;
      cudaGetSymbolAddress(&p, g_h2);  h2  = (float*)p;
      cudaGetSymbolAddress(&p, g_xh); xh=(hf*)p;  cudaGetSymbolAddress(&p, g_xl); xl=(hf*)p;
      cudaGetSymbolAddress(&p, g_qh); qh=(hf*)p;
      cudaGetSymbolAddress(&p, g_sh); sh=(hf*)p;
      cudaGetSymbolAddress(&p, g_ch); ch=(hf*)p;
      cudaGetSymbolAddress(&p, g_ah); ah=(hf*)p;  cudaGetSymbolAddress(&p, g_al); al=(hf*)p;
      cudaGetSymbolAddress(&p, g_hh); hh=(hf*)p;  cudaGetSymbolAddress(&p, g_hl); hl=(hf*)p;
      cudaGetSymbolAddress(&p, g_iwh); iwh=(hf*)p;
      cudaGetSymbolAddress(&p, g_owh); owh=(hf*)p;
      cudaGetSymbolAddress(&p, g_w1h); w1h=(hf*)p; cudaGetSymbolAddress(&p, g_w1l); w1l=(hf*)p;
      cudaGetSymbolAddress(&p, g_w2h); w2h=(hf*)p; cudaGetSymbolAddress(&p, g_w2l); w2l=(hf*)p;
    }

    const long long SH_ = (long long)SS * 3 * HH;
    const long long SSQ = (long long)SS * SS;

    split_kernel<<<(3*HH*HH/4 + 255)/256, 256>>>(in_w, iwh, nullptr, 3*HH*HH/4);
    split_kernel<<<(HH*HH/4 + 255)/256, 256>>>(out_w, owh, nullptr, HH*HH/4);
    split_kernel<<<(METAD*2*HH/4 + 255)/256, 256>>>(w1, w1h, w1l, METAD*2*HH/4);
    split_kernel<<<((METAD/2)*METAD/4 + 255)/256, 256>>>(w2, w2h, w2l, (METAD/2)*METAD/4);
    add_pos_split<<<ROWS*HH/4/256, 256>>>(hidden, pos, xh, xl);

    // qkv = fl16(x) @ fl16(in_w)^T + in_b  -> hi only (1-term)
    gmma<true,1><<<dim3(24, 64, 1), 256>>>(
        xh, nullptr, iwh, nullptr, nullptr, qh, nullptr,
        HH, HH, HH, 3*HH, 0,0, 0,0, 0,0, 1, in_b, 1.0f, 0);

    // scores = Q K^T / sqrt(128) -> fp32 (1-term)
    gmma<true,1><<<dim3(16, 16, BB*NHEADS), 256>>>(
        qh, nullptr, qh + HH, nullptr, scr, nullptr, nullptr,
        HD, 3*HH, 3*HH, SS,
        SH_, HD, SH_, HD, (long long)NHEADS*SSQ, SSQ, NHEADS,
        nullptr, 0.08838834764831843f, 0);

    softmax_kernel<<<BB*NHEADS*SS, 256>>>(scr, mask, sh);

    // ctx = P V -> hi only (1-term)
    gmma<false,1><<<dim3(1, 16, BB*NHEADS), 256>>>(
        sh, nullptr, qh + 2*HH, nullptr, nullptr, ch, nullptr,
        SS, SS, 3*HH, HH,
        (long long)NHEADS*SSQ, SSQ, SH_, HD, (long long)SS*HH, HD, NHEADS,
        nullptr, 1.0f, 0);

    // attended = ctx @ out_w^T + out_b -> hi/lo (1-term; lo out needed by h1 3-term)
    gmma<true,1><<<dim3(8, 64, 1), 256>>>(
        ch, nullptr, owh, nullptr, nullptr, ah, al,
        HH, HH, HH, HH, 0,0, 0,0, 0,0, 1, out_b, 1.0f, 0);

    // h1 = x @ w1a^T + b1 ; += att @ w1b^T (fp32, 3-term)
    gmma<true,3><<<dim3(2, 64, 1), 256>>>(
        xh, xl, w1h, w1l, h1, nullptr, nullptr,
        HH, HH, 2*HH, METAD, 0,0, 0,0, 0,0, 1, b1, 1.0f, 0);
    gmma<true,3><<<dim3(2, 64, 1), 256>>>(
        ah, al, w1h + HH, w1l + HH, h1, nullptr, nullptr,
        HH, HH, 2*HH, METAD, 0,0, 0,0, 0,0, 1, nullptr, 1.0f, 1);

    ln_relu_kernel<<<ROWS, METAD>>>(h1, g1, be1, METAD, hh, hl);

    // h2 = h1 @ w2^T + b2 (fp32, 3-term)
    gmma<true,3><<<dim3(1, 64, 1), 256>>>(
        hh, hl, w2h, w2l, h2, nullptr, nullptr,
        METAD, METAD, METAD, METAD/2, 0,0, 0,0, 0,0, 1, b2, 1.0f, 0);

    ln_relu_kernel<<<ROWS, METAD/2>>>(h2, g2, be2, METAD/2, nullptr, nullptr);
    final_kernel<<<ROWS, 128>>>(h2, w3, b3, tok, mask, table, out);
}

// round 12
// speedup vs baseline: 1.8979x; 1.0164x over previous
#include <cuda_runtime.h>
#include <cuda_fp16.h>
#include <math.h>
#include <stdint.h>

#define BB 4
#define SS 2048
#define HH 1024
#define NHEADS 8
#define HD 128
#define ROWS (BB*SS)
#define METAD 256

typedef __half hf;

// ---------------- scratch ----------------
__device__ float g_h1 [(size_t)ROWS*METAD];
__device__ float g_h2 [(size_t)ROWS*(METAD/2)];
__device__ uint4 g_xh [(size_t)ROWS*HH/8];
__device__ uint4 g_qh [(size_t)ROWS*3*HH/8];
__device__ uint4 g_sh [(size_t)BB*NHEADS*SS*SS/8];   // fp16 scores -> probs (in place)
__device__ uint4 g_ch [(size_t)ROWS*HH/8];
__device__ uint4 g_ah [(size_t)ROWS*HH/8];
__device__ uint4 g_hh [(size_t)ROWS*METAD/8];
__device__ uint4 g_iwh[(size_t)3*HH*HH/8];
__device__ uint4 g_owh[(size_t)HH*HH/8];
__device__ uint4 g_w1h[(size_t)METAD*2*HH/8];
__device__ uint4 g_w2h[(size_t)(METAD/2)*METAD/8];

// ---------------- helpers ----------------
__device__ __forceinline__ void sp1(float v, hf& h, hf& l) {
    h = __float2half_rn(v);
    l = __float2half_rn(v - __half2float(h));
}
__device__ __forceinline__ void mma16(float c[4], const uint32_t a[4], const uint32_t b[2]) {
    asm volatile("mma.sync.aligned.m16n8k16.row.col.f32.f16.f16.f32 "
        "{%0,%1,%2,%3}, {%4,%5,%6,%7}, {%8,%9}, {%0,%1,%2,%3};"
        : "+f"(c[0]), "+f"(c[1]), "+f"(c[2]), "+f"(c[3])
        : "r"(a[0]), "r"(a[1]), "r"(a[2]), "r"(a[3]), "r"(b[0]), "r"(b[1]));
}
__device__ __forceinline__ int swz(int m, int kw) {
    int g = kw >> 2, j = kw & 3;
    return m * 16 + ((g ^ ((m >> 1) & 3)) << 2) + j;
}

// ---------------------------------------------------------------------------
// fp16 GEMM (TERMS kept for flexibility; all calls now TERMS=1):
//   TERMS==1: D = AhiBhi. BT: B=[N,K]; else B=[K,N].
//   Tile 128x128, ktile 32, 256 thr. Optional fp32 C and/or fp16 Ch out.
// ---------------------------------------------------------------------------
template<bool BT, int TERMS>
__global__ __launch_bounds__(256)
void gmma(const hf* __restrict__ Ah, const hf* __restrict__ Al,
          const hf* __restrict__ Bh, const hf* __restrict__ Bl,
          float* __restrict__ C, hf* __restrict__ Ch, hf* __restrict__ Cl,
          int K, int lda, int ldb, int ldc,
          long long aOuter, long long aInner, long long bOuter, long long bInner,
          long long cOuter, long long cInner, int innerCount,
          const float* __restrict__ bias, float alpha, int accumulate)
{
    const int z = blockIdx.z, zo = z / innerCount, zi = z - zo * innerCount;
    const long long ao = zo * aOuter + zi * aInner;
    const long long bo = zo * bOuter + zi * bInner;
    const long long co = zo * cOuter + zi * cInner;
    Ah += ao; Bh += bo;
    if (TERMS >= 2) Al += ao;
    if (TERMS == 3) Bl += bo;
    if (C)  C  += co;
    if (Ch) Ch += co;
    if (Cl) Cl += co;

    __shared__ __align__(16) uint32_t AsH[128 * 16];
    __shared__ __align__(16) uint32_t AsL[(TERMS >= 2) ? 128 * 16 : 4];
    __shared__ __align__(16) uint32_t BsH[16 * 136];
    __shared__ __align__(16) uint32_t BsL[(TERMS == 3) ? 16 * 136 : 4];

    const int t = threadIdx.x, lane = t & 31, warp = t >> 5;
    const int gid = lane >> 2, tig = lane & 3;
    const int m_off = (warp >> 2) * 64, n_off = (warp & 3) * 32;
    const int brow = blockIdx.y * 128, bcol = blockIdx.x * 128;

    float acc[4][4][4];
#pragma unroll
    for (int mi = 0; mi < 4; mi++)
#pragma unroll
        for (int ni = 0; ni < 4; ni++)
#pragma unroll
            for (int r = 0; r < 4; r++) acc[mi][ni][r] = 0.0f;

    uint4 cAh[2], cAl[2], nAh[2], nAl[2];
    uint4 cBh[2], cBl[2], nBh[2], nBl[2];            // BT
    uint2 cB2[2][4], nB2[2][4];                      // NN

    auto ldg = [&](int kt, uint4* bAh, uint4* bAl, uint4* bBh, uint4* bBl,
                   uint2 (*bB2)[4]) {
#pragma unroll
        for (int i = 0; i < 2; i++) {
            int idx = t + i * 256, row = idx >> 2, quad = idx & 3;
            long long o = (long long)(brow + row) * lda + kt + quad * 8;
            bAh[i] = *reinterpret_cast<const uint4*>(Ah + o);
            if (TERMS >= 2) bAl[i] = *reinterpret_cast<const uint4*>(Al + o);
        }
        if (BT) {
#pragma unroll
            for (int i = 0; i < 2; i++) {
                int idx = t + i * 256, row = idx >> 2, quad = idx & 3;
                long long o = (long long)(bcol + row) * ldb + kt + quad * 8;
                bBh[i] = *reinterpret_cast<const uint4*>(Bh + o);
                if (TERMS == 3) bBl[i] = *reinterpret_cast<const uint4*>(Bl + o);
            }
        } else {
#pragma unroll
            for (int i = 0; i < 2; i++) {
                int idx = t + i * 256, kp = idx >> 5, q = idx & 31;
                long long o = (long long)(kt + 2 * kp) * ldb + bcol + q * 4;
                bB2[i][0] = *reinterpret_cast<const uint2*>(Bh + o);
                bB2[i][1] = *reinterpret_cast<const uint2*>(Bh + o + ldb);
                if (TERMS == 3) {
                    bB2[i][2] = *reinterpret_cast<const uint2*>(Bl + o);
                    bB2[i][3] = *reinterpret_cast<const uint2*>(Bl + o + ldb);
                }
            }
        }
    };
    auto sts = [&](const uint4* bAh, const uint4* bAl, const uint4* bBh,
                   const uint4* bBl, const uint2 (*bB2)[4]) {
#pragma unroll
        for (int i = 0; i < 2; i++) {
            int idx = t + i * 256, row = idx >> 2, quad = idx & 3;
            int base = row * 16 + ((quad ^ ((row >> 1) & 3)) << 2);
            *reinterpret_cast<uint4*>(&AsH[base]) = bAh[i];
            if (TERMS >= 2) *reinterpret_cast<uint4*>(&AsL[base]) = bAl[i];
        }
        if (BT) {
#pragma unroll
            for (int i = 0; i < 2; i++) {
                int idx = t + i * 256, row = idx >> 2, quad = idx & 3;
                int base = row * 16 + ((quad ^ ((row >> 1) & 3)) << 2);
                *reinterpret_cast<uint4*>(&BsH[base]) = bBh[i];
                if (TERMS == 3) *reinterpret_cast<uint4*>(&BsL[base]) = bBl[i];
            }
        } else {
#pragma unroll
            for (int i = 0; i < 2; i++) {
                int idx = t + i * 256, kp = idx >> 5, q = idx & 31;
                int base = kp * 136 + q * 4;
                uint4 h;
                h.x = __byte_perm(bB2[i][0].x, bB2[i][1].x, 0x5410);
                h.y = __byte_perm(bB2[i][0].x, bB2[i][1].x, 0x7632);
                h.z = __byte_perm(bB2[i][0].y, bB2[i][1].y, 0x5410);
                h.w = __byte_perm(bB2[i][0].y, bB2[i][1].y, 0x7632);
                *reinterpret_cast<uint4*>(&BsH[base]) = h;
                if (TERMS == 3) {
                    uint4 l;
                    l.x = __byte_perm(bB2[i][2].x, bB2[i][3].x, 0x5410);
                    l.y = __byte_perm(bB2[i][2].x, bB2[i][3].x, 0x7632);
                    l.z = __byte_perm(bB2[i][2].y, bB2[i][3].y, 0x5410);
                    l.w = __byte_perm(bB2[i][2].y, bB2[i][3].y, 0x7632);
                    *reinterpret_cast<uint4*>(&BsL[base]) = l;
                }
            }
        }
    };

    ldg(0, cAh, cAl, cBh, cBl, cB2);
    sts(cAh, cAl, cBh, cBl, cB2);
    __syncthreads();

    for (int kt = 0; kt < K; kt += 32) {
        const bool more = (kt + 32) < K;
        if (more) ldg(kt + 32, nAh, nAl, nBh, nBl, nB2);
#pragma unroll
        for (int ks = 0; ks < 2; ks++) {
            const int k0 = ks * 8 + tig, k1 = k0 + 4;
            uint32_t bH[4][2], bL[4][2];
#pragma unroll
            for (int ni = 0; ni < 4; ni++) {
                int n0 = n_off + ni * 8 + gid;
                int j0, j1;
                if (BT) { j0 = swz(n0, k0); j1 = swz(n0, k1); }
                else    { j0 = k0 * 136 + n0; j1 = k1 * 136 + n0; }
                bH[ni][0] = BsH[j0]; bH[ni][1] = BsH[j1];
                if (TERMS == 3) { bL[ni][0] = BsL[j0]; bL[ni][1] = BsL[j1]; }
            }
#pragma unroll
            for (int mi = 0; mi < 4; mi++) {
                int m0 = m_off + mi * 16 + gid;
                int i00 = swz(m0, k0), i10 = swz(m0 + 8, k0);
                int i01 = swz(m0, k1), i11 = swz(m0 + 8, k1);
                uint32_t aH[4] = {AsH[i00], AsH[i10], AsH[i01], AsH[i11]};
                uint32_t aL[4];
                if (TERMS >= 2) { aL[0] = AsL[i00]; aL[1] = AsL[i10]; aL[2] = AsL[i01]; aL[3] = AsL[i11]; }
#pragma unroll
                for (int ni = 0; ni < 4; ni++) {
                    mma16(acc[mi][ni], aH, bH[ni]);
                    if (TERMS == 3) mma16(acc[mi][ni], aH, bL[ni]);
                    if (TERMS >= 2) mma16(acc[mi][ni], aL, bH[ni]);
                }
            }
        }
        __syncthreads();
        if (more) { sts(nAh, nAl, nBh, nBl, nB2); __syncthreads(); }
    }

    // ---- epilogue ----
#pragma unroll
    for (int mi = 0; mi < 4; mi++)
#pragma unroll
        for (int ni = 0; ni < 4; ni++) {
            int m = brow + m_off + mi * 16 + gid;
            int n = bcol + n_off + ni * 8 + 2 * tig;
            float b0 = 0.f, b1 = 0.f;
            if (bias) { b0 = bias[n]; b1 = bias[n + 1]; }
#pragma unroll
            for (int h = 0; h < 2; h++) {
                long long r = m + h * 8;
                float vx = acc[mi][ni][h * 2 + 0] * alpha + b0;
                float vy = acc[mi][ni][h * 2 + 1] * alpha + b1;
                if (accumulate) { vx += C[r * ldc + n]; vy += C[r * ldc + n + 1]; }
                if (C) *reinterpret_cast<float2*>(C + r * ldc + n) = make_float2(vx, vy);
                if (Ch) {
                    hf hh_, ll_;
                    sp1(vx, hh_, ll_); Ch[r * ldc + n] = hh_;
                    if (Cl) Cl[r * ldc + n] = ll_;
                    sp1(vy, hh_, ll_); Ch[r * ldc + n + 1] = hh_;
                    if (Cl) Cl[r * ldc + n + 1] = ll_;
                }
            }
        }
}

// ---------------- elementwise ----------------
__global__ void split_kernel(const float* __restrict__ W, hf* __restrict__ Wh,
                             hf* __restrict__ Wl, int n4)
{
    int i = blockIdx.x * 256 + threadIdx.x;
    if (i >= n4) return;
    float4 v = reinterpret_cast<const float4*>(W)[i];
    hf h, l;
    sp1(v.x, h, l); Wh[i*4+0] = h; if (Wl) Wl[i*4+0] = l;
    sp1(v.y, h, l); Wh[i*4+1] = h; if (Wl) Wl[i*4+1] = l;
    sp1(v.z, h, l); Wh[i*4+2] = h; if (Wl) Wl[i*4+2] = l;
    sp1(v.w, h, l); Wh[i*4+3] = h; if (Wl) Wl[i*4+3] = l;
}

__global__ void add_pos_split(const float* __restrict__ h, const float* __restrict__ p,
                              hf* __restrict__ xh)
{
    long long i = (long long)blockIdx.x * 256 + threadIdx.x;
    const long long P4 = (long long)SS * HH / 4;
    float4 hv = reinterpret_cast<const float4*>(h)[i];
    float4 pv = reinterpret_cast<const float4*>(p)[i % P4];
    hv.x += pv.x; hv.y += pv.y; hv.z += pv.z; hv.w += pv.w;
    xh[i*4+0] = __float2half_rn(hv.x);
    xh[i*4+1] = __float2half_rn(hv.y);
    xh[i*4+2] = __float2half_rn(hv.z);
    xh[i*4+3] = __float2half_rn(hv.w);
}

// in-place fp16 softmax (fp32 internal), key-masked
__global__ __launch_bounds__(256)
void softmax_kernel(hf* __restrict__ S, const int* __restrict__ mask)
{
    const long long row = blockIdx.x;
    const int b = (int)(row >> 14);
    hf* p = S + row * (long long)SS;
    const int* mrow = mask + (long long)b * SS;
    const int t = threadIdx.x;
    float vals[8], m = -1e30f;
#pragma unroll
    for (int k = 0; k < 8; k++) {
        int j = t + k * 256;
        float v = __half2float(p[j]);
        v = (mrow[j] != 0) ? v : -1e9f;
        vals[k] = v; m = fmaxf(m, v);
    }
    __shared__ float red[256];
    red[t] = m; __syncthreads();
    for (int s = 128; s > 0; s >>= 1) { if (t < s) red[t] = fmaxf(red[t], red[t + s]); __syncthreads(); }
    const float rmax = red[0]; __syncthreads();
    float sum = 0.0f;
#pragma unroll
    for (int k = 0; k < 8; k++) { vals[k] = expf(vals[k] - rmax); sum += vals[k]; }
    red[t] = sum; __syncthreads();
    for (int s = 128; s > 0; s >>= 1) { if (t < s) red[t] += red[t + s]; __syncthreads(); }
    const float inv = 1.0f / red[0];
#pragma unroll
    for (int k = 0; k < 8; k++)
        p[t + k * 256] = __float2half_rn(vals[k] * inv);
}

__global__ void ln_relu_kernel(float* __restrict__ X, const float* __restrict__ g,
                               const float* __restrict__ beta, int width,
                               hf* Xh)
{
    const int row = blockIdx.x, t = threadIdx.x;
    float v = X[(long long)row * width + t];
    __shared__ float red[256];
    red[t] = v; __syncthreads();
    for (int s = blockDim.x >> 1; s > 0; s >>= 1) { if (t < s) red[t] += red[t + s]; __syncthreads(); }
    const float mu = red[0] / width; __syncthreads();
    const float d = v - mu;
    red[t] = d * d; __syncthreads();
    for (int s = blockDim.x >> 1; s > 0; s >>= 1) { if (t < s) red[t] += red[t + s]; __syncthreads(); }
    const float var = red[0] / width;
    float y = d * rsqrtf(var + 1e-5f) * g[t] + beta[t];
    y = fmaxf(y, 0.0f);
    X[(long long)row * width + t] = y;
    if (Xh) Xh[(long long)row * width + t] = __float2half_rn(y);
}

__global__ void final_kernel(const float* __restrict__ H2, const float* __restrict__ w3,
                             const float* __restrict__ b3, const int* __restrict__ tok,
                             const int* __restrict__ mask, const float* __restrict__ table,
                             float* __restrict__ out)
{
    const int row = blockIdx.x, t = threadIdx.x;
    float v = H2[(long long)row * 128 + t] * w3[t];
    __shared__ float red[128];
    red[t] = v; __syncthreads();
    for (int s = 64; s > 0; s >>= 1) { if (t < s) red[t] += red[t + s]; __syncthreads(); }
    if (t == 0) {
        float base = red[0] + b3[0];
        float w = base * (1.0f + table[tok[row]]);
        w = fminf(fmaxf(w, 0.1f), 5.0f);
        out[row] = (mask[row] != 0) ? w : 0.0f;
    }
}

// ---------------- launch ----------------
extern "C" void kernel_launch(void* const* d_in, const int* in_sizes, int n_in,
                              void* d_out, int out_size)
{
    const float* hidden = (const float*)d_in[0];
    const int*   tok    = (const int*)d_in[1];
    const int*   mask   = (const int*)d_in[2];
    const float* pos    = (const float*)d_in[3];
    const float* in_w   = (const float*)d_in[4];
    const float* in_b   = (const float*)d_in[5];
    const float* out_w  = (const float*)d_in[6];
    const float* out_b  = (const float*)d_in[7];
    const float* w1     = (const float*)d_in[8];
    const float* b1     = (const float*)d_in[9];
    const float* g1     = (const float*)d_in[10];
    const float* be1    = (const float*)d_in[11];
    const float* w2     = (const float*)d_in[12];
    const float* b2     = (const float*)d_in[13];
    const float* g2     = (const float*)d_in[14];
    const float* be2    = (const float*)d_in[15];
    const float* w3     = (const float*)d_in[16];
    const float* b3     = (const float*)d_in[17];
    const float* table  = (const float*)d_in[18];
    float* out = (float*)d_out;

    float *h1, *h2;
    hf *xh,*qh,*sh,*ch,*ah,*hh;
    hf *iwh,*owh,*w1h,*w2h;
    { void* p;
      cudaGetSymbolAddress(&p, g_h1);  h1  = (float*)p;
      cudaGetSymbolAddress(&p, g_h2);  h2  = (float*)p;
      cudaGetSymbolAddress(&p, g_xh); xh=(hf*)p;
      cudaGetSymbolAddress(&p, g_qh); qh=(hf*)p;
      cudaGetSymbolAddress(&p, g_sh); sh=(hf*)p;
      cudaGetSymbolAddress(&p, g_ch); ch=(hf*)p;
      cudaGetSymbolAddress(&p, g_ah); ah=(hf*)p;
      cudaGetSymbolAddress(&p, g_hh); hh=(hf*)p;
      cudaGetSymbolAddress(&p, g_iwh); iwh=(hf*)p;
      cudaGetSymbolAddress(&p, g_owh); owh=(hf*)p;
      cudaGetSymbolAddress(&p, g_w1h); w1h=(hf*)p;
      cudaGetSymbolAddress(&p, g_w2h); w2h=(hf*)p;
    }

    const long long SH_ = (long long)SS * 3 * HH;
    const long long SSQ = (long long)SS * SS;

    split_kernel<<<(3*HH*HH/4 + 255)/256, 256>>>(in_w, iwh, nullptr, 3*HH*HH/4);
    split_kernel<<<(HH*HH/4 + 255)/256, 256>>>(out_w, owh, nullptr, HH*HH/4);
    split_kernel<<<(METAD*2*HH/4 + 255)/256, 256>>>(w1, w1h, nullptr, METAD*2*HH/4);
    split_kernel<<<((METAD/2)*METAD/4 + 255)/256, 256>>>(w2, w2h, nullptr, (METAD/2)*METAD/4);
    add_pos_split<<<ROWS*HH/4/256, 256>>>(hidden, pos, xh);

    // qkv = fl16(x) @ fl16(in_w)^T + in_b  (fp16 out)
    gmma<true,1><<<dim3(24, 64, 1), 256>>>(
        xh, nullptr, iwh, nullptr, nullptr, qh, nullptr,
        HH, HH, HH, 3*HH, 0,0, 0,0, 0,0, 1, in_b, 1.0f, 0);

    // scores = Q K^T / sqrt(128)  (fp16 out, in-place softmax next)
    gmma<true,1><<<dim3(16, 16, BB*NHEADS), 256>>>(
        qh, nullptr, qh + HH, nullptr, nullptr, sh, nullptr,
        HD, 3*HH, 3*HH, SS,
        SH_, HD, SH_, HD, (long long)NHEADS*SSQ, SSQ, NHEADS,
        nullptr, 0.08838834764831843f, 0);

    softmax_kernel<<<BB*NHEADS*SS, 256>>>(sh, mask);

    // ctx = P V  (fp16 out)
    gmma<false,1><<<dim3(1, 16, BB*NHEADS), 256>>>(
        sh, nullptr, qh + 2*HH, nullptr, nullptr, ch, nullptr,
        SS, SS, 3*HH, HH,
        (long long)NHEADS*SSQ, SSQ, SH_, HD, (long long)SS*HH, HD, NHEADS,
        nullptr, 1.0f, 0);

    // attended = ctx @ out_w^T + out_b  (fp16 out)
    gmma<true,1><<<dim3(8, 64, 1), 256>>>(
        ch, nullptr, owh, nullptr, nullptr, ah, nullptr,
        HH, HH, HH, HH, 0,0, 0,0, 0,0, 1, out_b, 1.0f, 0);

    // h1 = x @ w1a^T + b1 ; += att @ w1b^T  (fp32 accum buffer)
    gmma<true,1><<<dim3(2, 64, 1), 256>>>(
        xh, nullptr, w1h, nullptr, h1, nullptr, nullptr,
        HH, HH, 2*HH, METAD, 0,0, 0,0, 0,0, 1, b1, 1.0f, 0);
    gmma<true,1><<<dim3(2, 64, 1), 256>>>(
        ah, nullptr, w1h + HH, nullptr, h1, nullptr, nullptr,
        HH, HH, 2*HH, METAD, 0,0, 0,0, 0,0, 1, nullptr, 1.0f, 1);

    ln_relu_kernel<<<ROWS, METAD>>>(h1, g1, be1, METAD, hh);

    // h2 = h1 @ w2^T + b2
    gmma<true,1><<<dim3(1, 64, 1), 256>>>(
        hh, nullptr, w2h, nullptr, h2, nullptr, nullptr,
        METAD, METAD, METAD, METAD/2, 0,0, 0,0, 0,0, 1, b2, 1.0f, 0);

    ln_relu_kernel<<<ROWS, METAD/2>>>(h2, g2, be2, METAD/2, nullptr);
    final_kernel<<<ROWS, 128>>>(h2, w3, b3, tok, mask, table, out);
}

// round 13
// speedup vs baseline: 2.1441x; 1.1297x over previous
#include <cuda_runtime.h>
#include <cuda_fp16.h>
#include <math.h>
#include <stdint.h>

#define BB 4
#define SS 2048
#define HH 1024
#define NHEADS 8
#define HD 128
#define ROWS (BB*SS)
#define METAD 256

typedef __half hf;

// ---------------- scratch ----------------
__device__ float g_h1 [(size_t)ROWS*METAD];
__device__ float g_h2 [(size_t)ROWS*(METAD/2)];
__device__ uint4 g_xh [(size_t)ROWS*HH/8];
__device__ uint4 g_qh [(size_t)ROWS*3*HH/8];
__device__ uint4 g_ch [(size_t)ROWS*HH/8];
__device__ uint4 g_ah [(size_t)ROWS*HH/8];
__device__ uint4 g_hh [(size_t)ROWS*METAD/8];
__device__ uint4 g_iwh[(size_t)3*HH*HH/8];
__device__ uint4 g_owh[(size_t)HH*HH/8];
__device__ uint4 g_w1h[(size_t)METAD*2*HH/8];
__device__ uint4 g_w2h[(size_t)(METAD/2)*METAD/8];

// ---------------- helpers ----------------
__device__ __forceinline__ void mma16(float c[4], const uint32_t a[4], const uint32_t b[2]) {
    asm volatile("mma.sync.aligned.m16n8k16.row.col.f32.f16.f16.f32 "
        "{%0,%1,%2,%3}, {%4,%5,%6,%7}, {%8,%9}, {%0,%1,%2,%3};"
        : "+f"(c[0]), "+f"(c[1]), "+f"(c[2]), "+f"(c[3])
        : "r"(a[0]), "r"(a[1]), "r"(a[2]), "r"(a[3]), "r"(b[0]), "r"(b[1]));
}
__device__ __forceinline__ int swz(int m, int kw) {
    int g = kw >> 2, j = kw & 3;
    return m * 16 + ((g ^ ((m >> 1) & 3)) << 2) + j;
}

// ---------------------------------------------------------------------------
// fp16 GEMM (BT only used):  C/Ch = A.B^T (+bias) (+C). From R12 (validated).
// ---------------------------------------------------------------------------
template<bool BT>
__global__ __launch_bounds__(256)
void gmma(const hf* __restrict__ Ah, const hf* __restrict__ Bh,
          float* __restrict__ C, hf* __restrict__ Ch,
          int K, int lda, int ldb, int ldc,
          long long aOuter, long long aInner, long long bOuter, long long bInner,
          long long cOuter, long long cInner, int innerCount,
          const float* __restrict__ bias, float alpha, int accumulate)
{
    const int z = blockIdx.z, zo = z / innerCount, zi = z - zo * innerCount;
    Ah += zo * aOuter + zi * aInner;
    Bh += zo * bOuter + zi * bInner;
    const long long co = zo * cOuter + zi * cInner;
    if (C)  C  += co;
    if (Ch) Ch += co;

    __shared__ __align__(16) uint32_t AsH[128 * 16];
    __shared__ __align__(16) uint32_t BsH[16 * 136];

    const int t = threadIdx.x, lane = t & 31, warp = t >> 5;
    const int gid = lane >> 2, tig = lane & 3;
    const int m_off = (warp >> 2) * 64, n_off = (warp & 3) * 32;
    const int brow = blockIdx.y * 128, bcol = blockIdx.x * 128;

    float acc[4][4][4];
#pragma unroll
    for (int mi = 0; mi < 4; mi++)
#pragma unroll
        for (int ni = 0; ni < 4; ni++)
#pragma unroll
            for (int r = 0; r < 4; r++) acc[mi][ni][r] = 0.0f;

    uint4 cA[2], nA[2], cB[2], nB[2];

    auto ldg = [&](int kt, uint4* bA, uint4* bB) {
#pragma unroll
        for (int i = 0; i < 2; i++) {
            int idx = t + i * 256, row = idx >> 2, quad = idx & 3;
            bA[i] = *reinterpret_cast<const uint4*>(Ah + (long long)(brow + row) * lda + kt + quad * 8);
            bB[i] = *reinterpret_cast<const uint4*>(Bh + (long long)(bcol + row) * ldb + kt + quad * 8);
        }
    };
    auto sts = [&](const uint4* bA, const uint4* bB) {
#pragma unroll
        for (int i = 0; i < 2; i++) {
            int idx = t + i * 256, row = idx >> 2, quad = idx & 3;
            int base = row * 16 + ((quad ^ ((row >> 1) & 3)) << 2);
            *reinterpret_cast<uint4*>(&AsH[base]) = bA[i];
            *reinterpret_cast<uint4*>(&BsH[base]) = bB[i];
        }
    };

    ldg(0, cA, cB);
    sts(cA, cB);
    __syncthreads();

    for (int kt = 0; kt < K; kt += 32) {
        const bool more = (kt + 32) < K;
        if (more) ldg(kt + 32, nA, nB);
#pragma unroll
        for (int ks = 0; ks < 2; ks++) {
            const int k0 = ks * 8 + tig, k1 = k0 + 4;
            uint32_t bH[4][2];
#pragma unroll
            for (int ni = 0; ni < 4; ni++) {
                int n0 = n_off + ni * 8 + gid;
                bH[ni][0] = BsH[swz(n0, k0)];
                bH[ni][1] = BsH[swz(n0, k1)];
            }
#pragma unroll
            for (int mi = 0; mi < 4; mi++) {
                int m0 = m_off + mi * 16 + gid;
                uint32_t aH[4] = {AsH[swz(m0, k0)], AsH[swz(m0 + 8, k0)],
                                  AsH[swz(m0, k1)], AsH[swz(m0 + 8, k1)]};
#pragma unroll
                for (int ni = 0; ni < 4; ni++)
                    mma16(acc[mi][ni], aH, bH[ni]);
            }
        }
        __syncthreads();
        if (more) { sts(nA, nB); __syncthreads(); }
    }

#pragma unroll
    for (int mi = 0; mi < 4; mi++)
#pragma unroll
        for (int ni = 0; ni < 4; ni++) {
            int m = brow + m_off + mi * 16 + gid;
            int n = bcol + n_off + ni * 8 + 2 * tig;
            float b0 = 0.f, b1 = 0.f;
            if (bias) { b0 = bias[n]; b1 = bias[n + 1]; }
#pragma unroll
            for (int h = 0; h < 2; h++) {
                long long r = m + h * 8;
                float vx = acc[mi][ni][h * 2 + 0] * alpha + b0;
                float vy = acc[mi][ni][h * 2 + 1] * alpha + b1;
                if (accumulate) { vx += C[r * ldc + n]; vy += C[r * ldc + n + 1]; }
                if (C) *reinterpret_cast<float2*>(C + r * ldc + n) = make_float2(vx, vy);
                if (Ch) {
                    __half2 p = __floats2half2_rn(vx, vy);
                    *reinterpret_cast<uint32_t*>(Ch + r * ldc + n) = *reinterpret_cast<uint32_t*>(&p);
                }
            }
        }
}

// ---------------------------------------------------------------------------
// Flash attention: per CTA one (b, h, q-tile of 128). 256 thr, 8 warps (2x4).
// Online softmax, all smem layouts identical to validated gmma panels.
// ---------------------------------------------------------------------------
#define FSM_WORDS 34432   // 8192*3 + 8704 + 1152 floats
#define FSM_BYTES (FSM_WORDS*4)

__global__ __launch_bounds__(256, 1)
void flash_kernel(const hf* __restrict__ qkv, const int* __restrict__ mask,
                  hf* __restrict__ ctx)
{
    extern __shared__ __align__(16) uint32_t sm[];
    uint32_t* Qs = sm;              // 4 panels x 2048
    uint32_t* Ks = sm + 8192;       // 4 panels x 2048
    uint32_t* Vs = sm + 16384;      // 4 panels x 2176 (NN)
    uint32_t* Ps = sm + 25088;      // 4 panels x 2048
    float* fs      = (float*)(sm + 33280);
    float* m_arr   = fs;            // [128]
    float* l_arr   = fs + 128;
    float* f_arr   = fs + 256;
    float* mn_arr  = fs + 384;
    float* redp    = fs + 512;      // [128*4]
    float* maskadd = fs + 1024;     // [128]

    const int t = threadIdx.x, lane = t & 31, warp = t >> 5;
    const int gid = lane >> 2, tig = lane & 3;
    const int m_off = (warp >> 2) * 64, n_off = (warp & 3) * 32, nwarp = warp & 3;
    const int bh = blockIdx.y, b = bh >> 3, h = bh & 7;
    const int q0 = blockIdx.x * 128;
    const long long ld = 3 * HH;
    const hf* Qg = qkv + ((long long)(b * SS) + q0) * ld + h * HD;
    const hf* Kg = qkv + (long long)(b * SS) * ld + HH + h * HD;
    const hf* Vg = qkv + (long long)(b * SS) * ld + 2 * HH + h * HD;

    // load Q (once)
#pragma unroll
    for (int c = 0; c < 4; c++)
#pragma unroll
        for (int i = 0; i < 2; i++) {
            int idx = t + i * 256, row = idx >> 2, quad = idx & 3;
            int base = row * 16 + ((quad ^ ((row >> 1) & 3)) << 2);
            *reinterpret_cast<uint4*>(&Qs[c * 2048 + base]) =
                *reinterpret_cast<const uint4*>(Qg + (long long)row * ld + c * 32 + quad * 8);
        }
    if (t < 128) { m_arr[t] = -1e30f; l_arr[t] = 0.0f; }

    float oacc[4][4][4];
#pragma unroll
    for (int mi = 0; mi < 4; mi++)
#pragma unroll
        for (int ni = 0; ni < 4; ni++)
#pragma unroll
            for (int r = 0; r < 4; r++) oacc[mi][ni][r] = 0.0f;

    __syncthreads();

    for (int kt = 0; kt < 16; kt++) {
        const int key0 = kt * 128;
        // K tile (BT panels)
#pragma unroll
        for (int c = 0; c < 4; c++)
#pragma unroll
            for (int i = 0; i < 2; i++) {
                int idx = t + i * 256, row = idx >> 2, quad = idx & 3;
                int base = row * 16 + ((quad ^ ((row >> 1) & 3)) << 2);
                *reinterpret_cast<uint4*>(&Ks[c * 2048 + base]) =
                    *reinterpret_cast<const uint4*>(Kg + (long long)(key0 + row) * ld + c * 32 + quad * 8);
            }
        // V tile (NN panels)
#pragma unroll
        for (int c = 0; c < 4; c++)
#pragma unroll
            for (int i = 0; i < 2; i++) {
                int idx = t + i * 256, kp = idx >> 5, q = idx & 31;
                const hf* p0 = Vg + (long long)(key0 + c * 32 + 2 * kp) * ld + q * 4;
                uint2 e = *reinterpret_cast<const uint2*>(p0);
                uint2 o = *reinterpret_cast<const uint2*>(p0 + ld);
                uint4 w;
                w.x = __byte_perm(e.x, o.x, 0x5410);
                w.y = __byte_perm(e.x, o.x, 0x7632);
                w.z = __byte_perm(e.y, o.y, 0x5410);
                w.w = __byte_perm(e.y, o.y, 0x7632);
                *reinterpret_cast<uint4*>(&Vs[c * 2176 + kp * 136 + q * 4]) = w;
            }
        if (t < 128) maskadd[t] = (mask[b * SS + key0 + t] != 0) ? 0.0f : -1e9f;
        __syncthreads();   // A

        // ---- S = Q K^T ----
        float acc[4][4][4];
#pragma unroll
        for (int mi = 0; mi < 4; mi++)
#pragma unroll
            for (int ni = 0; ni < 4; ni++)
#pragma unroll
                for (int r = 0; r < 4; r++) acc[mi][ni][r] = 0.0f;
#pragma unroll
        for (int c = 0; c < 4; c++) {
            const uint32_t* As = Qs + c * 2048;
            const uint32_t* Bs = Ks + c * 2048;
#pragma unroll
            for (int ks = 0; ks < 2; ks++) {
                const int k0 = ks * 8 + tig, k1 = k0 + 4;
                uint32_t bH[4][2];
#pragma unroll
                for (int ni = 0; ni < 4; ni++) {
                    int n0 = n_off + ni * 8 + gid;
                    bH[ni][0] = Bs[swz(n0, k0)];
                    bH[ni][1] = Bs[swz(n0, k1)];
                }
#pragma unroll
                for (int mi = 0; mi < 4; mi++) {
                    int m0 = m_off + mi * 16 + gid;
                    uint32_t aH[4] = {As[swz(m0, k0)], As[swz(m0 + 8, k0)],
                                      As[swz(m0, k1)], As[swz(m0 + 8, k1)]};
#pragma unroll
                    for (int ni = 0; ni < 4; ni++)
                        mma16(acc[mi][ni], aH, bH[ni]);
                }
            }
        }

        // ---- scale + mask + row-max partials ----
        float pmax[4][2];
#pragma unroll
        for (int mi = 0; mi < 4; mi++) { pmax[mi][0] = -1e30f; pmax[mi][1] = -1e30f; }
#pragma unroll
        for (int mi = 0; mi < 4; mi++)
#pragma unroll
            for (int ni = 0; ni < 4; ni++)
#pragma unroll
                for (int hh = 0; hh < 2; hh++)
#pragma unroll
                    for (int cc = 0; cc < 2; cc++) {
                        int col = n_off + ni * 8 + 2 * tig + cc;
                        float s = acc[mi][ni][hh * 2 + cc] * 0.08838834764831843f + maskadd[col];
                        acc[mi][ni][hh * 2 + cc] = s;
                        pmax[mi][hh] = fmaxf(pmax[mi][hh], s);
                    }
#pragma unroll
        for (int mi = 0; mi < 4; mi++)
#pragma unroll
            for (int hh = 0; hh < 2; hh++) {
                float v = pmax[mi][hh];
                v = fmaxf(v, __shfl_xor_sync(0xffffffff, v, 1));
                v = fmaxf(v, __shfl_xor_sync(0xffffffff, v, 2));
                pmax[mi][hh] = v;
            }
        if (tig == 0)
#pragma unroll
            for (int mi = 0; mi < 4; mi++)
#pragma unroll
                for (int hh = 0; hh < 2; hh++)
                    redp[(m_off + mi * 16 + gid + hh * 8) * 4 + nwarp] = pmax[mi][hh];
        __syncthreads();   // B

        if (t < 128) {
            float mt = fmaxf(fmaxf(redp[t * 4 + 0], redp[t * 4 + 1]),
                             fmaxf(redp[t * 4 + 2], redp[t * 4 + 3]));
            float mo = m_arr[t];
            float mn = fmaxf(mo, mt);
            mn_arr[t] = mn;
            f_arr[t] = __expf(mo - mn);
            m_arr[t] = mn;
        }
        __syncthreads();   // C

        // ---- P = exp(S - m), rescale O, write P to smem, row-sum partials ----
        float psum[4][2];
#pragma unroll
        for (int mi = 0; mi < 4; mi++) { psum[mi][0] = 0.f; psum[mi][1] = 0.f; }
#pragma unroll
        for (int mi = 0; mi < 4; mi++)
#pragma unroll
            for (int hh = 0; hh < 2; hh++) {
                int row = m_off + mi * 16 + gid + hh * 8;
                float mn = mn_arr[row], f = f_arr[row];
#pragma unroll
                for (int ni = 0; ni < 4; ni++) {
                    float p0 = __expf(acc[mi][ni][hh * 2 + 0] - mn);
                    float p1 = __expf(acc[mi][ni][hh * 2 + 1] - mn);
                    psum[mi][hh] += p0 + p1;
                    oacc[mi][ni][hh * 2 + 0] *= f;
                    oacc[mi][ni][hh * 2 + 1] *= f;
                    __half2 pk = __floats2half2_rn(p0, p1);
                    Ps[nwarp * 2048 + swz(row, ni * 4 + tig)] = *reinterpret_cast<uint32_t*>(&pk);
                }
            }
#pragma unroll
        for (int mi = 0; mi < 4; mi++)
#pragma unroll
            for (int hh = 0; hh < 2; hh++) {
                float v = psum[mi][hh];
                v += __shfl_xor_sync(0xffffffff, v, 1);
                v += __shfl_xor_sync(0xffffffff, v, 2);
                psum[mi][hh] = v;
            }
        if (tig == 0)
#pragma unroll
            for (int mi = 0; mi < 4; mi++)
#pragma unroll
                for (int hh = 0; hh < 2; hh++)
                    redp[(m_off + mi * 16 + gid + hh * 8) * 4 + nwarp] = psum[mi][hh];
        __syncthreads();   // D

        if (t < 128)
            l_arr[t] = l_arr[t] * f_arr[t] +
                (redp[t * 4 + 0] + redp[t * 4 + 1] + redp[t * 4 + 2] + redp[t * 4 + 3]);

        // ---- O += P V ----
#pragma unroll
        for (int c = 0; c < 4; c++) {
            const uint32_t* As = Ps + c * 2048;
            const uint32_t* Bs = Vs + c * 2176;
#pragma unroll
            for (int ks = 0; ks < 2; ks++) {
                const int k0 = ks * 8 + tig, k1 = k0 + 4;
                uint32_t bH[4][2];
#pragma unroll
                for (int ni = 0; ni < 4; ni++) {
                    int n0 = n_off + ni * 8 + gid;
                    bH[ni][0] = Bs[k0 * 136 + n0];
                    bH[ni][1] = Bs[k1 * 136 + n0];
                }
#pragma unroll
                for (int mi = 0; mi < 4; mi++) {
                    int m0 = m_off + mi * 16 + gid;
                    uint32_t aH[4] = {As[swz(m0, k0)], As[swz(m0 + 8, k0)],
                                      As[swz(m0, k1)], As[swz(m0 + 8, k1)]};
#pragma unroll
                    for (int ni = 0; ni < 4; ni++)
                        mma16(oacc[mi][ni], aH, bH[ni]);
                }
            }
        }
        __syncthreads();   // E (protect Ks/Vs/Ps/maskadd for next tile)
    }

    // ---- epilogue: ctx = O / l ----
#pragma unroll
    for (int mi = 0; mi < 4; mi++)
#pragma unroll
        for (int hh = 0; hh < 2; hh++) {
            int row = m_off + mi * 16 + gid + hh * 8;
            float inv = 1.0f / l_arr[row];
            long long gr = (long long)(b * SS + q0 + row) * HH + h * HD;
#pragma unroll
            for (int ni = 0; ni < 4; ni++) {
                int n = n_off + ni * 8 + 2 * tig;
                __half2 pk = __floats2half2_rn(oacc[mi][ni][hh * 2 + 0] * inv,
                                               oacc[mi][ni][hh * 2 + 1] * inv);
                *reinterpret_cast<uint32_t*>(ctx + gr + n) = *reinterpret_cast<uint32_t*>(&pk);
            }
        }
}

// ---------------- elementwise ----------------
__global__ void cvt_kernel(const float* __restrict__ W, hf* __restrict__ Wh, int n4)
{
    int i = blockIdx.x * 256 + threadIdx.x;
    if (i >= n4) return;
    float4 v = reinterpret_cast<const float4*>(W)[i];
    __half2 a = __floats2half2_rn(v.x, v.y);
    __half2 b = __floats2half2_rn(v.z, v.w);
    reinterpret_cast<uint32_t*>(Wh)[i * 2 + 0] = *reinterpret_cast<uint32_t*>(&a);
    reinterpret_cast<uint32_t*>(Wh)[i * 2 + 1] = *reinterpret_cast<uint32_t*>(&b);
}

__global__ void add_pos_cvt(const float* __restrict__ h, const float* __restrict__ p,
                            hf* __restrict__ xh)
{
    long long i = (long long)blockIdx.x * 256 + threadIdx.x;
    const long long P4 = (long long)SS * HH / 4;
    float4 hv = reinterpret_cast<const float4*>(h)[i];
    float4 pv = reinterpret_cast<const float4*>(p)[i % P4];
    __half2 a = __floats2half2_rn(hv.x + pv.x, hv.y + pv.y);
    __half2 b = __floats2half2_rn(hv.z + pv.z, hv.w + pv.w);
    reinterpret_cast<uint32_t*>(xh)[i * 2 + 0] = *reinterpret_cast<uint32_t*>(&a);
    reinterpret_cast<uint32_t*>(xh)[i * 2 + 1] = *reinterpret_cast<uint32_t*>(&b);
}

__global__ void ln_relu_kernel(float* __restrict__ X, const float* __restrict__ g,
                               const float* __restrict__ beta, int width, hf* Xh)
{
    const int row = blockIdx.x, t = threadIdx.x;
    float v = X[(long long)row * width + t];
    __shared__ float red[256];
    red[t] = v; __syncthreads();
    for (int s = blockDim.x >> 1; s > 0; s >>= 1) { if (t < s) red[t] += red[t + s]; __syncthreads(); }
    const float mu = red[0] / width; __syncthreads();
    const float d = v - mu;
    red[t] = d * d; __syncthreads();
    for (int s = blockDim.x >> 1; s > 0; s >>= 1) { if (t < s) red[t] += red[t + s]; __syncthreads(); }
    const float var = red[0] / width;
    float y = d * rsqrtf(var + 1e-5f) * g[t] + beta[t];
    y = fmaxf(y, 0.0f);
    X[(long long)row * width + t] = y;
    if (Xh) Xh[(long long)row * width + t] = __float2half_rn(y);
}

__global__ void final_kernel(const float* __restrict__ H2, const float* __restrict__ w3,
                             const float* __restrict__ b3, const int* __restrict__ tok,
                             const int* __restrict__ mask, const float* __restrict__ table,
                             float* __restrict__ out)
{
    const int row = blockIdx.x, t = threadIdx.x;
    float v = H2[(long long)row * 128 + t] * w3[t];
    __shared__ float red[128];
    red[t] = v; __syncthreads();
    for (int s = 64; s > 0; s >>= 1) { if (t < s) red[t] += red[t + s]; __syncthreads(); }
    if (t == 0) {
        float base = red[0] + b3[0];
        float w = base * (1.0f + table[tok[row]]);
        w = fminf(fmaxf(w, 0.1f), 5.0f);
        out[row] = (mask[row] != 0) ? w : 0.0f;
    }
}

// ---------------- launch ----------------
extern "C" void kernel_launch(void* const* d_in, const int* in_sizes, int n_in,
                              void* d_out, int out_size)
{
    const float* hidden = (const float*)d_in[0];
    const int*   tok    = (const int*)d_in[1];
    const int*   mask   = (const int*)d_in[2];
    const float* pos    = (const float*)d_in[3];
    const float* in_w   = (const float*)d_in[4];
    const float* in_b   = (const float*)d_in[5];
    const float* out_w  = (const float*)d_in[6];
    const float* out_b  = (const float*)d_in[7];
    const float* w1     = (const float*)d_in[8];
    const float* b1     = (const float*)d_in[9];
    const float* g1     = (const float*)d_in[10];
    const float* be1    = (const float*)d_in[11];
    const float* w2     = (const float*)d_in[12];
    const float* b2     = (const float*)d_in[13];
    const float* g2     = (const float*)d_in[14];
    const float* be2    = (const float*)d_in[15];
    const float* w3     = (const float*)d_in[16];
    const float* b3     = (const float*)d_in[17];
    const float* table  = (const float*)d_in[18];
    float* out = (float*)d_out;

    float *h1, *h2;
    hf *xh,*qh,*ch,*ah,*hh;
    hf *iwh,*owh,*w1h,*w2h;
    { void* p;
      cudaGetSymbolAddress(&p, g_h1);  h1  = (float*)p;
      cudaGetSymbolAddress(&p, g_h2);  h2  = (float*)p;
      cudaGetSymbolAddress(&p, g_xh); xh=(hf*)p;
      cudaGetSymbolAddress(&p, g_qh); qh=(hf*)p;
      cudaGetSymbolAddress(&p, g_ch); ch=(hf*)p;
      cudaGetSymbolAddress(&p, g_ah); ah=(hf*)p;
      cudaGetSymbolAddress(&p, g_hh); hh=(hf*)p;
      cudaGetSymbolAddress(&p, g_iwh); iwh=(hf*)p;
      cudaGetSymbolAddress(&p, g_owh); owh=(hf*)p;
      cudaGetSymbolAddress(&p, g_w1h); w1h=(hf*)p;
      cudaGetSymbolAddress(&p, g_w2h); w2h=(hf*)p;
    }
    cudaFuncSetAttribute(flash_kernel, cudaFuncAttributeMaxDynamicSharedMemorySize, FSM_BYTES);

    cvt_kernel<<<(3*HH*HH/4 + 255)/256, 256>>>(in_w, iwh, 3*HH*HH/4);
    cvt_kernel<<<(HH*HH/4 + 255)/256, 256>>>(out_w, owh, HH*HH/4);
    cvt_kernel<<<(METAD*2*HH/4 + 255)/256, 256>>>(w1, w1h, METAD*2*HH/4);
    cvt_kernel<<<((METAD/2)*METAD/4 + 255)/256, 256>>>(w2, w2h, (METAD/2)*METAD/4);
    add_pos_cvt<<<ROWS*HH/4/256, 256>>>(hidden, pos, xh);

    // qkv = fl16(x) @ fl16(in_w)^T + in_b  (fp16 out)
    gmma<true><<<dim3(24, 64, 1), 256>>>(
        xh, iwh, nullptr, qh,
        HH, HH, HH, 3*HH, 0,0, 0,0, 0,0, 1, in_b, 1.0f, 0);

    // fused attention: ctx = softmax(QK^T/sqrt(d), mask) V
    flash_kernel<<<dim3(SS/128, BB*NHEADS), 256, FSM_BYTES>>>(qh, mask, ch);

    // attended = ctx @ out_w^T + out_b  (fp16 out)
    gmma<true><<<dim3(8, 64, 1), 256>>>(
        ch, owh, nullptr, ah,
        HH, HH, HH, HH, 0,0, 0,0, 0,0, 1, out_b, 1.0f, 0);

    // h1 = x @ w1a^T + b1 ; += att @ w1b^T
    gmma<true><<<dim3(2, 64, 1), 256>>>(
        xh, w1h, h1, nullptr,
        HH, HH, 2*HH, METAD, 0,0, 0,0, 0,0, 1, b1, 1.0f, 0);
    gmma<true><<<dim3(2, 64, 1), 256>>>(
        ah, w1h + HH, h1, nullptr,
        HH, HH, 2*HH, METAD, 0,0, 0,0, 0,0, 1, nullptr, 1.0f, 1);

    ln_relu_kernel<<<ROWS, METAD>>>(h1, g1, be1, METAD, hh);

    // h2 = h1 @ w2^T + b2
    gmma<true><<<dim3(1, 64, 1), 256>>>(
        hh, w2h, h2, nullptr,
        METAD, METAD, METAD, METAD/2, 0,0, 0,0, 0,0, 1, b2, 1.0f, 0);

    ln_relu_kernel<<<ROWS, METAD/2>>>(h2, g2, be2, METAD/2, nullptr);
    final_kernel<<<ROWS, 128>>>(h2, w3, b3, tok, mask, table, out);
}

// round 14
// speedup vs baseline: 3.9608x; 1.8473x over previous
#include <cuda_runtime.h>
#include <cuda_fp16.h>
#include <math.h>
#include <stdint.h>

#define BB 4
#define SS 2048
#define HH 1024
#define NHEADS 8
#define HD 128
#define ROWS (BB*SS)
#define METAD 256

typedef __half hf;

// ---------------- scratch ----------------
__device__ float g_h1 [(size_t)ROWS*METAD];
__device__ float g_h2 [(size_t)ROWS*(METAD/2)];
__device__ uint4 g_xa [(size_t)ROWS*2*HH/8];     // [x | attended] fp16, ld 2048
__device__ uint4 g_qh [(size_t)ROWS*3*HH/8];
__device__ uint4 g_ch [(size_t)ROWS*HH/8];
__device__ uint4 g_hh [(size_t)ROWS*METAD/8];
__device__ uint4 g_iwh[(size_t)3*HH*HH/8];
__device__ uint4 g_owh[(size_t)HH*HH/8];
__device__ uint4 g_w1h[(size_t)METAD*2*HH/8];
__device__ uint4 g_w2h[(size_t)(METAD/2)*METAD/8];

// ---------------- helpers ----------------
__device__ __forceinline__ void mma16(float c[4], const uint32_t a[4], const uint32_t b[2]) {
    asm volatile("mma.sync.aligned.m16n8k16.row.col.f32.f16.f16.f32 "
        "{%0,%1,%2,%3}, {%4,%5,%6,%7}, {%8,%9}, {%0,%1,%2,%3};"
        : "+f"(c[0]), "+f"(c[1]), "+f"(c[2]), "+f"(c[3])
        : "r"(a[0]), "r"(a[1]), "r"(a[2]), "r"(a[3]), "r"(b[0]), "r"(b[1]));
}
__device__ __forceinline__ int swz(int m, int kw) {
    int g = kw >> 2, j = kw & 3;
    return m * 16 + ((g ^ ((m >> 1) & 3)) << 2) + j;
}
__device__ __forceinline__ uint32_t h2pack(float a, float b) {
    __half2 p = __floats2half2_rn(a, b);
    return *reinterpret_cast<uint32_t*>(&p);
}

// ---------------------------------------------------------------------------
// fp16 GEMM (BT):  C/Ch = A.B^T (+bias). Validated (R12/R13).
// ---------------------------------------------------------------------------
__global__ __launch_bounds__(256)
void gmma(const hf* __restrict__ Ah, const hf* __restrict__ Bh,
          float* __restrict__ C, hf* __restrict__ Ch,
          int K, int lda, int ldb, int ldc,
          const float* __restrict__ bias)
{
    __shared__ __align__(16) uint32_t AsH[128 * 16];
    __shared__ __align__(16) uint32_t BsH[16 * 136];

    const int t = threadIdx.x, lane = t & 31, warp = t >> 5;
    const int gid = lane >> 2, tig = lane & 3;
    const int m_off = (warp >> 2) * 64, n_off = (warp & 3) * 32;
    const int brow = blockIdx.y * 128, bcol = blockIdx.x * 128;

    float acc[4][4][4];
#pragma unroll
    for (int mi = 0; mi < 4; mi++)
#pragma unroll
        for (int ni = 0; ni < 4; ni++)
#pragma unroll
            for (int r = 0; r < 4; r++) acc[mi][ni][r] = 0.0f;

    uint4 cA[2], nA[2], cB[2], nB[2];
    auto ldg = [&](int kt, uint4* bA, uint4* bB) {
#pragma unroll
        for (int i = 0; i < 2; i++) {
            int idx = t + i * 256, row = idx >> 2, quad = idx & 3;
            bA[i] = *reinterpret_cast<const uint4*>(Ah + (long long)(brow + row) * lda + kt + quad * 8);
            bB[i] = *reinterpret_cast<const uint4*>(Bh + (long long)(bcol + row) * ldb + kt + quad * 8);
        }
    };
    auto sts = [&](const uint4* bA, const uint4* bB) {
#pragma unroll
        for (int i = 0; i < 2; i++) {
            int idx = t + i * 256, row = idx >> 2, quad = idx & 3;
            int base = row * 16 + ((quad ^ ((row >> 1) & 3)) << 2);
            *reinterpret_cast<uint4*>(&AsH[base]) = bA[i];
            *reinterpret_cast<uint4*>(&BsH[base]) = bB[i];
        }
    };

    ldg(0, cA, cB);
    sts(cA, cB);
    __syncthreads();

    for (int kt = 0; kt < K; kt += 32) {
        const bool more = (kt + 32) < K;
        if (more) ldg(kt + 32, nA, nB);
#pragma unroll
        for (int ks = 0; ks < 2; ks++) {
            const int k0 = ks * 8 + tig, k1 = k0 + 4;
            uint32_t bH[4][2];
#pragma unroll
            for (int ni = 0; ni < 4; ni++) {
                int n0 = n_off + ni * 8 + gid;
                bH[ni][0] = BsH[swz(n0, k0)];
                bH[ni][1] = BsH[swz(n0, k1)];
            }
#pragma unroll
            for (int mi = 0; mi < 4; mi++) {
                int m0 = m_off + mi * 16 + gid;
                uint32_t aH[4] = {AsH[swz(m0, k0)], AsH[swz(m0 + 8, k0)],
                                  AsH[swz(m0, k1)], AsH[swz(m0 + 8, k1)]};
#pragma unroll
                for (int ni = 0; ni < 4; ni++)
                    mma16(acc[mi][ni], aH, bH[ni]);
            }
        }
        __syncthreads();
        if (more) { sts(nA, nB); __syncthreads(); }
    }

#pragma unroll
    for (int mi = 0; mi < 4; mi++)
#pragma unroll
        for (int ni = 0; ni < 4; ni++) {
            int m = brow + m_off + mi * 16 + gid;
            int n = bcol + n_off + ni * 8 + 2 * tig;
            float b0 = 0.f, b1 = 0.f;
            if (bias) { b0 = bias[n]; b1 = bias[n + 1]; }
#pragma unroll
            for (int h = 0; h < 2; h++) {
                long long r = m + h * 8;
                float vx = acc[mi][ni][h * 2 + 0] + b0;
                float vy = acc[mi][ni][h * 2 + 1] + b1;
                if (C) *reinterpret_cast<float2*>(C + r * ldc + n) = make_float2(vx, vy);
                if (Ch) *reinterpret_cast<uint32_t*>(Ch + r * ldc + n) = h2pack(vx, vy);
            }
        }
}

// ---------------------------------------------------------------------------
// Flash v2: warps tile M only (warp w -> rows w*16..+15); P stays in registers.
// grid (SS/128, BB*NHEADS), 256 thr. smem: Q 32K + K 32K + V 34K + mask 512B.
// ---------------------------------------------------------------------------
#define F2_WORDS (8192 + 8192 + 8704 + 128)
#define F2_BYTES (F2_WORDS * 4)

__global__ __launch_bounds__(256, 1)
void flash2_kernel(const hf* __restrict__ qkv, const int* __restrict__ mask,
                   hf* __restrict__ ctx, int ldctx)
{
    extern __shared__ __align__(16) uint32_t sm[];
    uint32_t* Qs = sm;              // 4 BT panels x 2048
    uint32_t* Ks = sm + 8192;
    uint32_t* Vs = sm + 16384;      // 4 NN panels x 2176
    float* maskadd = (float*)(sm + 25088);

    const int t = threadIdx.x, lane = t & 31, warp = t >> 5;
    const int gid = lane >> 2, tig = lane & 3;
    const int m_off = warp * 16;
    const int bh = blockIdx.y, b = bh >> 3, h = bh & 7;
    const int q0 = blockIdx.x * 128;
    const long long ld = 3 * HH;
    const hf* Qg = qkv + ((long long)(b * SS) + q0) * ld + h * HD;
    const hf* Kg = qkv + (long long)(b * SS) * ld + HH + h * HD;
    const hf* Vg = qkv + (long long)(b * SS) * ld + 2 * HH + h * HD;

    // Q once
#pragma unroll
    for (int c = 0; c < 4; c++)
#pragma unroll
        for (int i = 0; i < 2; i++) {
            int idx = t + i * 256, row = idx >> 2, quad = idx & 3;
            int base = row * 16 + ((quad ^ ((row >> 1) & 3)) << 2);
            *reinterpret_cast<uint4*>(&Qs[c * 2048 + base]) =
                *reinterpret_cast<const uint4*>(Qg + (long long)row * ld + c * 32 + quad * 8);
        }

    float m0 = -1e30f, m1 = -1e30f, l0 = 0.f, l1 = 0.f;
    float oacc[16][4];
#pragma unroll
    for (int ni = 0; ni < 16; ni++)
#pragma unroll
        for (int r = 0; r < 4; r++) oacc[ni][r] = 0.0f;

    for (int kt = 0; kt < 16; kt++) {
        const int key0 = kt * 128;
#pragma unroll
        for (int c = 0; c < 4; c++)
#pragma unroll
            for (int i = 0; i < 2; i++) {
                int idx = t + i * 256, row = idx >> 2, quad = idx & 3;
                int base = row * 16 + ((quad ^ ((row >> 1) & 3)) << 2);
                *reinterpret_cast<uint4*>(&Ks[c * 2048 + base]) =
                    *reinterpret_cast<const uint4*>(Kg + (long long)(key0 + row) * ld + c * 32 + quad * 8);
            }
#pragma unroll
        for (int c = 0; c < 4; c++)
#pragma unroll
            for (int i = 0; i < 2; i++) {
                int idx = t + i * 256, kp = idx >> 5, q = idx & 31;
                const hf* p0 = Vg + (long long)(key0 + c * 32 + 2 * kp) * ld + q * 4;
                uint2 e = *reinterpret_cast<const uint2*>(p0);
                uint2 o = *reinterpret_cast<const uint2*>(p0 + ld);
                uint4 w;
                w.x = __byte_perm(e.x, o.x, 0x5410);
                w.y = __byte_perm(e.x, o.x, 0x7632);
                w.z = __byte_perm(e.y, o.y, 0x5410);
                w.w = __byte_perm(e.y, o.y, 0x7632);
                *reinterpret_cast<uint4*>(&Vs[c * 2176 + kp * 136 + q * 4]) = w;
            }
        if (t < 128) maskadd[t] = (mask[b * SS + key0 + t] != 0) ? 0.0f : -1e9f;
        __syncthreads();

        // ---- S = Q K^T : warp rows m_off..+15, all 128 cols ----
        float sacc[16][4];
#pragma unroll
        for (int ni = 0; ni < 16; ni++)
#pragma unroll
            for (int r = 0; r < 4; r++) sacc[ni][r] = 0.0f;
#pragma unroll
        for (int c = 0; c < 4; c++) {
            const uint32_t* As = Qs + c * 2048;
            const uint32_t* Bs = Ks + c * 2048;
#pragma unroll
            for (int ks = 0; ks < 2; ks++) {
                const int k0 = ks * 8 + tig, k1 = k0 + 4;
                int mr = m_off + gid;
                uint32_t aH[4] = {As[swz(mr, k0)], As[swz(mr + 8, k0)],
                                  As[swz(mr, k1)], As[swz(mr + 8, k1)]};
#pragma unroll
                for (int ni = 0; ni < 16; ni++) {
                    int n0 = ni * 8 + gid;
                    uint32_t bH[2] = {Bs[swz(n0, k0)], Bs[swz(n0, k1)]};
                    mma16(sacc[ni], aH, bH);
                }
            }
        }

        // ---- scale + mask + row-max (quad-local) ----
        float tm0 = -1e30f, tm1 = -1e30f;
#pragma unroll
        for (int ni = 0; ni < 16; ni++) {
            float ma = maskadd[ni * 8 + 2 * tig], mb = maskadd[ni * 8 + 2 * tig + 1];
            float s0 = sacc[ni][0] * 0.08838834764831843f + ma;
            float s1 = sacc[ni][1] * 0.08838834764831843f + mb;
            float s2 = sacc[ni][2] * 0.08838834764831843f + ma;
            float s3 = sacc[ni][3] * 0.08838834764831843f + mb;
            sacc[ni][0] = s0; sacc[ni][1] = s1; sacc[ni][2] = s2; sacc[ni][3] = s3;
            tm0 = fmaxf(tm0, fmaxf(s0, s1));
            tm1 = fmaxf(tm1, fmaxf(s2, s3));
        }
        tm0 = fmaxf(tm0, __shfl_xor_sync(0xffffffff, tm0, 1));
        tm0 = fmaxf(tm0, __shfl_xor_sync(0xffffffff, tm0, 2));
        tm1 = fmaxf(tm1, __shfl_xor_sync(0xffffffff, tm1, 1));
        tm1 = fmaxf(tm1, __shfl_xor_sync(0xffffffff, tm1, 2));
        float mn0 = fmaxf(m0, tm0), mn1 = fmaxf(m1, tm1);
        float f0 = __expf(m0 - mn0), f1 = __expf(m1 - mn1);
        m0 = mn0; m1 = mn1;
#pragma unroll
        for (int ni = 0; ni < 16; ni++) {
            oacc[ni][0] *= f0; oacc[ni][1] *= f0;
            oacc[ni][2] *= f1; oacc[ni][3] *= f1;
        }

        // ---- per k-block: exp -> P regs -> PV mma ----
        float tl0 = 0.f, tl1 = 0.f;
#pragma unroll
        for (int c = 0; c < 4; c++) {
            const uint32_t* Bs = Vs + c * 2176;
#pragma unroll
            for (int ks = 0; ks < 2; ks++) {
                const int j = c * 2 + ks;
                float p00 = __expf(sacc[2*j][0]   - mn0), p01 = __expf(sacc[2*j][1]   - mn0);
                float p02 = __expf(sacc[2*j][2]   - mn1), p03 = __expf(sacc[2*j][3]   - mn1);
                float p10 = __expf(sacc[2*j+1][0] - mn0), p11 = __expf(sacc[2*j+1][1] - mn0);
                float p12 = __expf(sacc[2*j+1][2] - mn1), p13 = __expf(sacc[2*j+1][3] - mn1);
                tl0 += p00 + p01 + p10 + p11;
                tl1 += p02 + p03 + p12 + p13;
                uint32_t aP[4] = {h2pack(p00, p01), h2pack(p02, p03),
                                  h2pack(p10, p11), h2pack(p12, p13)};
                const int k0 = ks * 8 + tig, k1 = k0 + 4;
#pragma unroll
                for (int ni = 0; ni < 16; ni++) {
                    int n0 = ni * 8 + gid;
                    uint32_t bV[2] = {Bs[k0 * 136 + n0], Bs[k1 * 136 + n0]};
                    mma16(oacc[ni], aP, bV);
                }
            }
        }
        tl0 += __shfl_xor_sync(0xffffffff, tl0, 1);
        tl0 += __shfl_xor_sync(0xffffffff, tl0, 2);
        tl1 += __shfl_xor_sync(0xffffffff, tl1, 1);
        tl1 += __shfl_xor_sync(0xffffffff, tl1, 2);
        l0 = l0 * f0 + tl0;
        l1 = l1 * f1 + tl1;
        __syncthreads();
    }

    // ---- epilogue ----
    const float inv0 = 1.0f / l0, inv1 = 1.0f / l1;
    const long long r0 = (long long)(b * SS + q0 + m_off + gid) * ldctx + h * HD;
    const long long r1 = r0 + 8LL * ldctx;
#pragma unroll
    for (int ni = 0; ni < 16; ni++) {
        int n = ni * 8 + 2 * tig;
        *reinterpret_cast<uint32_t*>(ctx + r0 + n) = h2pack(oacc[ni][0] * inv0, oacc[ni][1] * inv0);
        *reinterpret_cast<uint32_t*>(ctx + r1 + n) = h2pack(oacc[ni][2] * inv1, oacc[ni][3] * inv1);
    }
}

// ---------------- elementwise ----------------
__global__ void cvt_kernel(const float* __restrict__ W, hf* __restrict__ Wh, int n4)
{
    int i = blockIdx.x * 256 + threadIdx.x;
    if (i >= n4) return;
    float4 v = reinterpret_cast<const float4*>(W)[i];
    reinterpret_cast<uint32_t*>(Wh)[i * 2 + 0] = h2pack(v.x, v.y);
    reinterpret_cast<uint32_t*>(Wh)[i * 2 + 1] = h2pack(v.z, v.w);
}

// x = hidden + pos -> fp16 into combined buffer [row][2048], cols 0..1023
__global__ void add_pos_cvt(const float* __restrict__ h, const float* __restrict__ p,
                            hf* __restrict__ xa)
{
    long long i = (long long)blockIdx.x * 256 + threadIdx.x;   // float4 idx
    const long long P4 = (long long)SS * HH / 4;
    float4 hv = reinterpret_cast<const float4*>(h)[i];
    float4 pv = reinterpret_cast<const float4*>(p)[i % P4];
    long long row = i >> 8, c4 = i & 255;
    uint32_t* dst = reinterpret_cast<uint32_t*>(xa + row * 2048 + c4 * 4);
    dst[0] = h2pack(hv.x + pv.x, hv.y + pv.y);
    dst[1] = h2pack(hv.z + pv.z, hv.w + pv.w);
}

__global__ void ln_relu_kernel(float* __restrict__ X, const float* __restrict__ g,
                               const float* __restrict__ beta, int width, hf* Xh)
{
    const int row = blockIdx.x, t = threadIdx.x;
    float v = X[(long long)row * width + t];
    __shared__ float red[256];
    red[t] = v; __syncthreads();
    for (int s = blockDim.x >> 1; s > 0; s >>= 1) { if (t < s) red[t] += red[t + s]; __syncthreads(); }
    const float mu = red[0] / width; __syncthreads();
    const float d = v - mu;
    red[t] = d * d; __syncthreads();
    for (int s = blockDim.x >> 1; s > 0; s >>= 1) { if (t < s) red[t] += red[t + s]; __syncthreads(); }
    const float var = red[0] / width;
    float y = d * rsqrtf(var + 1e-5f) * g[t] + beta[t];
    y = fmaxf(y, 0.0f);
    X[(long long)row * width + t] = y;
    if (Xh) Xh[(long long)row * width + t] = __float2half_rn(y);
}

// fused: LN(128) + ReLU + dot(w3) + importance + clamp + mask
__global__ void final2_kernel(const float* __restrict__ H2, const float* __restrict__ g,
                              const float* __restrict__ beta,
                              const float* __restrict__ w3, const float* __restrict__ b3,
                              const int* __restrict__ tok, const int* __restrict__ mask,
                              const float* __restrict__ table, float* __restrict__ out)
{
    const int row = blockIdx.x, t = threadIdx.x;
    float v = H2[(long long)row * 128 + t];
    __shared__ float red[128];
    red[t] = v; __syncthreads();
    for (int s = 64; s > 0; s >>= 1) { if (t < s) red[t] += red[t + s]; __syncthreads(); }
    const float mu = red[0] / 128.0f; __syncthreads();
    const float d = v - mu;
    red[t] = d * d; __syncthreads();
    for (int s = 64; s > 0; s >>= 1) { if (t < s) red[t] += red[t + s]; __syncthreads(); }
    const float var = red[0] / 128.0f;
    __syncthreads();
    float y = fmaxf(d * rsqrtf(var + 1e-5f) * g[t] + beta[t], 0.0f);
    red[t] = y * w3[t]; __syncthreads();
    for (int s = 64; s > 0; s >>= 1) { if (t < s) red[t] += red[t + s]; __syncthreads(); }
    if (t == 0) {
        float base = red[0] + b3[0];
        float w = base * (1.0f + table[tok[row]]);
        w = fminf(fmaxf(w, 0.1f), 5.0f);
        out[row] = (mask[row] != 0) ? w : 0.0f;
    }
}

// ---------------- launch ----------------
extern "C" void kernel_launch(void* const* d_in, const int* in_sizes, int n_in,
                              void* d_out, int out_size)
{
    const float* hidden = (const float*)d_in[0];
    const int*   tok    = (const int*)d_in[1];
    const int*   mask   = (const int*)d_in[2];
    const float* pos    = (const float*)d_in[3];
    const float* in_w   = (const float*)d_in[4];
    const float* in_b   = (const float*)d_in[5];
    const float* out_w  = (const float*)d_in[6];
    const float* out_b  = (const float*)d_in[7];
    const float* w1     = (const float*)d_in[8];
    const float* b1     = (const float*)d_in[9];
    const float* g1     = (const float*)d_in[10];
    const float* be1    = (const float*)d_in[11];
    const float* w2     = (const float*)d_in[12];
    const float* b2     = (const float*)d_in[13];
    const float* g2     = (const float*)d_in[14];
    const float* be2    = (const float*)d_in[15];
    const float* w3     = (const float*)d_in[16];
    const float* b3     = (const float*)d_in[17];
    const float* table  = (const float*)d_in[18];
    float* out = (float*)d_out;

    float *h1, *h2;
    hf *xa,*qh,*ch,*hh,*iwh,*owh,*w1h,*w2h;
    { void* p;
      cudaGetSymbolAddress(&p, g_h1);  h1 = (float*)p;
      cudaGetSymbolAddress(&p, g_h2);  h2 = (float*)p;
      cudaGetSymbolAddress(&p, g_xa);  xa = (hf*)p;
      cudaGetSymbolAddress(&p, g_qh);  qh = (hf*)p;
      cudaGetSymbolAddress(&p, g_ch);  ch = (hf*)p;
      cudaGetSymbolAddress(&p, g_hh);  hh = (hf*)p;
      cudaGetSymbolAddress(&p, g_iwh); iwh = (hf*)p;
      cudaGetSymbolAddress(&p, g_owh); owh = (hf*)p;
      cudaGetSymbolAddress(&p, g_w1h); w1h = (hf*)p;
      cudaGetSymbolAddress(&p, g_w2h); w2h = (hf*)p;
    }
    cudaFuncSetAttribute(flash2_kernel, cudaFuncAttributeMaxDynamicSharedMemorySize, F2_BYTES);

    cvt_kernel<<<(3*HH*HH/4 + 255)/256, 256>>>(in_w, iwh, 3*HH*HH/4);
    cvt_kernel<<<(HH*HH/4 + 255)/256, 256>>>(out_w, owh, HH*HH/4);
    cvt_kernel<<<(METAD*2*HH/4 + 255)/256, 256>>>(w1, w1h, METAD*2*HH/4);
    cvt_kernel<<<((METAD/2)*METAD/4 + 255)/256, 256>>>(w2, w2h, (METAD/2)*METAD/4);
    add_pos_cvt<<<ROWS*HH/4/256, 256>>>(hidden, pos, xa);

    // qkv = x @ in_w^T + in_b   (A from combined buffer, lda 2048)
    gmma<<<dim3(24, 64, 1), 256>>>(xa, iwh, nullptr, qh,
                                   HH, 2*HH, HH, 3*HH, in_b);

    // fused attention
    flash2_kernel<<<dim3(SS/128, BB*NHEADS), 256, F2_BYTES>>>(qh, mask, ch, HH);

    // attended = ctx @ out_w^T + out_b  -> combined buffer cols 1024.. (ldc 2048)
    gmma<<<dim3(8, 64, 1), 256>>>(ch, owh, nullptr, xa + HH,
                                  HH, HH, HH, 2*HH, out_b);

    // h1 = [x|att] @ w1^T + b1   (single K=2048 GEMM)
    gmma<<<dim3(2, 64, 1), 256>>>(xa, w1h, h1, nullptr,
                                  2*HH, 2*HH, 2*HH, METAD, b1);

    ln_relu_kernel<<<ROWS, METAD>>>(h1, g1, be1, METAD, hh);

    // h2 = h1 @ w2^T + b2
    gmma<<<dim3(1, 64, 1), 256>>>(hh, w2h, h2, nullptr,
                                  METAD, METAD, METAD, METAD/2, b2);

    // fused LN + head
    final2_kernel<<<ROWS, 128>>>(h2, g2, be2, w3, b3, tok, mask, table, out);
}

// round 15
// speedup vs baseline: 4.1587x; 1.0500x over previous
#include <cuda_runtime.h>
#include <cuda_fp16.h>
#include <math.h>
#include <stdint.h>

#define BB 4
#define SS 2048
#define HH 1024
#define NHEADS 8
#define HD 128
#define ROWS (BB*SS)
#define METAD 256

typedef __half hf;

// ---------------- scratch ----------------
__device__ float g_h1 [(size_t)ROWS*METAD];
__device__ float g_h2 [(size_t)ROWS*(METAD/2)];
__device__ float g_beff[METAD];
__device__ uint4 g_xa  [(size_t)ROWS*2*HH/8];     // [x | ctx] fp16, ld 2048
__device__ uint4 g_qh  [(size_t)ROWS*3*HH/8];
__device__ uint4 g_hh  [(size_t)ROWS*METAD/8];
__device__ uint4 g_iwh [(size_t)3*HH*HH/8];
__device__ uint4 g_owh [(size_t)HH*HH/8];
__device__ uint4 g_w2h [(size_t)(METAD/2)*METAD/8];
__device__ uint4 g_wcomb[(size_t)METAD*2*HH/8];   // [w1a | W_eff] fp16, ld 2048
__device__ uint4 g_w1bh [(size_t)METAD*HH/8];     // w1b fp16, ld 1024

// ---------------- helpers ----------------
__device__ __forceinline__ void mma16(float c[4], const uint32_t a[4], const uint32_t b[2]) {
    asm volatile("mma.sync.aligned.m16n8k16.row.col.f32.f16.f16.f32 "
        "{%0,%1,%2,%3}, {%4,%5,%6,%7}, {%8,%9}, {%0,%1,%2,%3};"
        : "+f"(c[0]), "+f"(c[1]), "+f"(c[2]), "+f"(c[3])
        : "r"(a[0]), "r"(a[1]), "r"(a[2]), "r"(a[3]), "r"(b[0]), "r"(b[1]));
}
__device__ __forceinline__ int swz(int m, int kw) {
    int g = kw >> 2, j = kw & 3;
    return m * 16 + ((g ^ ((m >> 1) & 3)) << 2) + j;
}
__device__ __forceinline__ uint32_t h2pack(float a, float b) {
    __half2 p = __floats2half2_rn(a, b);
    return *reinterpret_cast<uint32_t*>(&p);
}
__device__ __forceinline__ uint32_t smem_u32(const void* p) {
    uint32_t a;
    asm("{ .reg .u64 t; cvta.to.shared.u64 t, %1; cvt.u32.u64 %0, t; }" : "=r"(a) : "l"(p));
    return a;
}
__device__ __forceinline__ void cp16(uint32_t d, const void* s) {
    asm volatile("cp.async.cg.shared.global [%0], [%1], 16;" :: "r"(d), "l"(s) : "memory");
}
__device__ __forceinline__ void cp_commit() { asm volatile("cp.async.commit_group;" ::: "memory"); }
__device__ __forceinline__ void cp_wait0()  { asm volatile("cp.async.wait_group 0;" ::: "memory"); }
__device__ __forceinline__ void cp_wait1()  { asm volatile("cp.async.wait_group 1;" ::: "memory"); }
#define LDSM4T(r, a) \
    asm volatile("ldmatrix.sync.aligned.m8n8.x4.trans.shared.b16 {%0,%1,%2,%3}, [%4];" \
        : "=r"((r)[0]), "=r"((r)[1]), "=r"((r)[2]), "=r"((r)[3]) : "r"(a))

// ---------------------------------------------------------------------------
// fp16 GEMM. BT: B=[N,K]; NN: B=[K,N]. Tile 128x128, ktile 32, 256 thr.
// ---------------------------------------------------------------------------
template<bool BT>
__global__ __launch_bounds__(256)
void gmma(const hf* __restrict__ Ah, const hf* __restrict__ Bh,
          float* __restrict__ C, hf* __restrict__ Ch,
          int K, int lda, int ldb, int ldc,
          const float* __restrict__ bias)
{
    __shared__ __align__(16) uint32_t AsH[128 * 16];
    __shared__ __align__(16) uint32_t BsH[16 * 136];

    const int t = threadIdx.x, lane = t & 31, warp = t >> 5;
    const int gid = lane >> 2, tig = lane & 3;
    const int m_off = (warp >> 2) * 64, n_off = (warp & 3) * 32;
    const int brow = blockIdx.y * 128, bcol = blockIdx.x * 128;

    float acc[4][4][4];
#pragma unroll
    for (int mi = 0; mi < 4; mi++)
#pragma unroll
        for (int ni = 0; ni < 4; ni++)
#pragma unroll
            for (int r = 0; r < 4; r++) acc[mi][ni][r] = 0.0f;

    uint4 cA[2], nA[2], cB[2], nB[2];
    uint2 cB2[2][2], nB2[2][2];

    auto ldg = [&](int kt, uint4* bA, uint4* bB, uint2 (*bB2)[2]) {
#pragma unroll
        for (int i = 0; i < 2; i++) {
            int idx = t + i * 256, row = idx >> 2, quad = idx & 3;
            bA[i] = *reinterpret_cast<const uint4*>(Ah + (long long)(brow + row) * lda + kt + quad * 8);
        }
        if (BT) {
#pragma unroll
            for (int i = 0; i < 2; i++) {
                int idx = t + i * 256, row = idx >> 2, quad = idx & 3;
                bB[i] = *reinterpret_cast<const uint4*>(Bh + (long long)(bcol + row) * ldb + kt + quad * 8);
            }
        } else {
#pragma unroll
            for (int i = 0; i < 2; i++) {
                int idx = t + i * 256, kp = idx >> 5, q = idx & 31;
                const hf* p0 = Bh + (long long)(kt + 2 * kp) * ldb + bcol + q * 4;
                bB2[i][0] = *reinterpret_cast<const uint2*>(p0);
                bB2[i][1] = *reinterpret_cast<const uint2*>(p0 + ldb);
            }
        }
    };
    auto sts = [&](const uint4* bA, const uint4* bB, const uint2 (*bB2)[2]) {
#pragma unroll
        for (int i = 0; i < 2; i++) {
            int idx = t + i * 256, row = idx >> 2, quad = idx & 3;
            int base = row * 16 + ((quad ^ ((row >> 1) & 3)) << 2);
            *reinterpret_cast<uint4*>(&AsH[base]) = bA[i];
        }
        if (BT) {
#pragma unroll
            for (int i = 0; i < 2; i++) {
                int idx = t + i * 256, row = idx >> 2, quad = idx & 3;
                int base = row * 16 + ((quad ^ ((row >> 1) & 3)) << 2);
                *reinterpret_cast<uint4*>(&BsH[base]) = bB[i];
            }
        } else {
#pragma unroll
            for (int i = 0; i < 2; i++) {
                int idx = t + i * 256, kp = idx >> 5, q = idx & 31;
                uint4 h;
                h.x = __byte_perm(bB2[i][0].x, bB2[i][1].x, 0x5410);
                h.y = __byte_perm(bB2[i][0].x, bB2[i][1].x, 0x7632);
                h.z = __byte_perm(bB2[i][0].y, bB2[i][1].y, 0x5410);
                h.w = __byte_perm(bB2[i][0].y, bB2[i][1].y, 0x7632);
                *reinterpret_cast<uint4*>(&BsH[kp * 136 + q * 4]) = h;
            }
        }
    };

    ldg(0, cA, cB, cB2);
    sts(cA, cB, cB2);
    __syncthreads();

    for (int kt = 0; kt < K; kt += 32) {
        const bool more = (kt + 32) < K;
        if (more) ldg(kt + 32, nA, nB, nB2);
#pragma unroll
        for (int ks = 0; ks < 2; ks++) {
            const int k0 = ks * 8 + tig, k1 = k0 + 4;
            uint32_t bH[4][2];
#pragma unroll
            for (int ni = 0; ni < 4; ni++) {
                int n0 = n_off + ni * 8 + gid;
                if (BT) { bH[ni][0] = BsH[swz(n0, k0)]; bH[ni][1] = BsH[swz(n0, k1)]; }
                else    { bH[ni][0] = BsH[k0 * 136 + n0]; bH[ni][1] = BsH[k1 * 136 + n0]; }
            }
#pragma unroll
            for (int mi = 0; mi < 4; mi++) {
                int m0 = m_off + mi * 16 + gid;
                uint32_t aH[4] = {AsH[swz(m0, k0)], AsH[swz(m0 + 8, k0)],
                                  AsH[swz(m0, k1)], AsH[swz(m0 + 8, k1)]};
#pragma unroll
                for (int ni = 0; ni < 4; ni++)
                    mma16(acc[mi][ni], aH, bH[ni]);
            }
        }
        __syncthreads();
        if (more) { sts(nA, nB, nB2); __syncthreads(); }
    }

#pragma unroll
    for (int mi = 0; mi < 4; mi++)
#pragma unroll
        for (int ni = 0; ni < 4; ni++) {
            int m = brow + m_off + mi * 16 + gid;
            int n = bcol + n_off + ni * 8 + 2 * tig;
            float b0 = 0.f, b1 = 0.f;
            if (bias) { b0 = bias[n]; b1 = bias[n + 1]; }
#pragma unroll
            for (int h = 0; h < 2; h++) {
                long long r = m + h * 8;
                float vx = acc[mi][ni][h * 2 + 0] + b0;
                float vy = acc[mi][ni][h * 2 + 1] + b1;
                if (C) *reinterpret_cast<float2*>(C + r * ldc + n) = make_float2(vx, vy);
                if (Ch) *reinterpret_cast<uint32_t*>(Ch + r * ldc + n) = h2pack(vx, vy);
            }
        }
}

// ---------------------------------------------------------------------------
// Flash v3: register-P; cp.async double-buffered K (swizzled) + V (raw+LDSM4T).
// smem words: Q 8192 | K 2x8192 | V 2x8704 | mask 2x128  = 42240
// ---------------------------------------------------------------------------
#define F3_WORDS 42240
#define F3_BYTES (F3_WORDS * 4)

__global__ __launch_bounds__(256, 1)
void flash3_kernel(const hf* __restrict__ qkv, const int* __restrict__ mask,
                   hf* __restrict__ ctx, int ldctx)
{
    extern __shared__ __align__(16) uint32_t sm[];
    uint32_t* Qs = sm;
    uint32_t* Ks = sm + 8192;
    float* maskadd = (float*)(sm + 41984);
    const uint32_t smb = smem_u32(sm);

    const int t = threadIdx.x, lane = t & 31, warp = t >> 5;
    const int gid = lane >> 2, tig = lane & 3;
    const int m_off = warp * 16;
    const int krl = (lane & 7) + ((lane >> 3) & 1) * 8;
    const int nc8 = ((lane >> 4) & 1) * 8;
    const int bh = blockIdx.y, b = bh >> 3, h = bh & 7;
    const int q0 = blockIdx.x * 128;
    const long long ld = 3 * HH;
    const hf* Qg = qkv + ((long long)(b * SS) + q0) * ld + h * HD;
    const hf* Kg = qkv + (long long)(b * SS) * ld + HH + h * HD;
    const hf* Vg = qkv + (long long)(b * SS) * ld + 2 * HH + h * HD;

    // Q once
#pragma unroll
    for (int c = 0; c < 4; c++)
#pragma unroll
        for (int i = 0; i < 2; i++) {
            int idx = t + i * 256, row = idx >> 2, quad = idx & 3;
            int base = row * 16 + ((quad ^ ((row >> 1) & 3)) << 2);
            *reinterpret_cast<uint4*>(&Qs[c * 2048 + base]) =
                *reinterpret_cast<const uint4*>(Qg + (long long)row * ld + c * 32 + quad * 8);
        }

    auto prefetch = [&](int kt) {
        const int buf = kt & 1;
        const int key0 = kt * 128;
        const uint32_t kbase = smb + 32768 + buf * 32768;
        const uint32_t vbase = smb + 98304 + buf * 34816;
#pragma unroll
        for (int c = 0; c < 4; c++)
#pragma unroll
            for (int i = 0; i < 2; i++) {
                int id = t + i * 256, row = id >> 2, quad = id & 3;
                uint32_t d = kbase + c * 8192 + row * 64 + ((quad ^ ((row >> 1) & 3)) << 4);
                cp16(d, Kg + (long long)(key0 + row) * ld + c * 32 + quad * 8);
            }
#pragma unroll
        for (int c = 0; c < 4; c++)
#pragma unroll
            for (int i = 0; i < 2; i++) {
                int id = t + i * 256, row = id >> 4, seg = id & 15;
                uint32_t d = vbase + c * 8704 + row * 272 + seg * 16;
                cp16(d, Vg + (long long)(key0 + c * 32 + row) * ld + seg * 8);
            }
        cp_commit();
        if (t < 128) maskadd[buf * 128 + t] = (mask[b * SS + key0 + t] != 0) ? 0.0f : -1e9f;
    };

    float m0 = -1e30f, m1 = -1e30f, l0 = 0.f, l1 = 0.f;
    float oacc[16][4];
#pragma unroll
    for (int ni = 0; ni < 16; ni++)
#pragma unroll
        for (int r = 0; r < 4; r++) oacc[ni][r] = 0.0f;

    prefetch(0);

    for (int kt = 0; kt < 16; kt++) {
        const int buf = kt & 1;
        if (kt + 1 < 16) { prefetch(kt + 1); cp_wait1(); } else cp_wait0();
        __syncthreads();

        // ---- S = Q K^T ----
        float sacc[16][4];
#pragma unroll
        for (int ni = 0; ni < 16; ni++)
#pragma unroll
            for (int r = 0; r < 4; r++) sacc[ni][r] = 0.0f;
#pragma unroll
        for (int c = 0; c < 4; c++) {
            const uint32_t* As = Qs + c * 2048;
            const uint32_t* Bs = Ks + buf * 8192 + c * 2048;
#pragma unroll
            for (int ks = 0; ks < 2; ks++) {
                const int k0 = ks * 8 + tig, k1 = k0 + 4;
                int mr = m_off + gid;
                uint32_t aH[4] = {As[swz(mr, k0)], As[swz(mr + 8, k0)],
                                  As[swz(mr, k1)], As[swz(mr + 8, k1)]};
#pragma unroll
                for (int ni = 0; ni < 16; ni++) {
                    int n0 = ni * 8 + gid;
                    uint32_t bH[2] = {Bs[swz(n0, k0)], Bs[swz(n0, k1)]};
                    mma16(sacc[ni], aH, bH);
                }
            }
        }

        // ---- scale + mask + row-max ----
        const float* mrow = maskadd + buf * 128;
        float tm0 = -1e30f, tm1 = -1e30f;
#pragma unroll
        for (int ni = 0; ni < 16; ni++) {
            float ma = mrow[ni * 8 + 2 * tig], mb = mrow[ni * 8 + 2 * tig + 1];
            float s0 = sacc[ni][0] * 0.08838834764831843f + ma;
            float s1 = sacc[ni][1] * 0.08838834764831843f + mb;
            float s2 = sacc[ni][2] * 0.08838834764831843f + ma;
            float s3 = sacc[ni][3] * 0.08838834764831843f + mb;
            sacc[ni][0] = s0; sacc[ni][1] = s1; sacc[ni][2] = s2; sacc[ni][3] = s3;
            tm0 = fmaxf(tm0, fmaxf(s0, s1));
            tm1 = fmaxf(tm1, fmaxf(s2, s3));
        }
        tm0 = fmaxf(tm0, __shfl_xor_sync(0xffffffff, tm0, 1));
        tm0 = fmaxf(tm0, __shfl_xor_sync(0xffffffff, tm0, 2));
        tm1 = fmaxf(tm1, __shfl_xor_sync(0xffffffff, tm1, 1));
        tm1 = fmaxf(tm1, __shfl_xor_sync(0xffffffff, tm1, 2));
        float mn0 = fmaxf(m0, tm0), mn1 = fmaxf(m1, tm1);
        float f0 = __expf(m0 - mn0), f1 = __expf(m1 - mn1);
        m0 = mn0; m1 = mn1;
#pragma unroll
        for (int ni = 0; ni < 16; ni++) {
            oacc[ni][0] *= f0; oacc[ni][1] *= f0;
            oacc[ni][2] *= f1; oacc[ni][3] *= f1;
        }

        // ---- exp -> P regs -> PV (V raw + LDSM4T) ----
        float tl0 = 0.f, tl1 = 0.f;
#pragma unroll
        for (int c = 0; c < 4; c++) {
            const uint32_t vpan = smb + 98304 + buf * 34816 + c * 8704;
#pragma unroll
            for (int ks = 0; ks < 2; ks++) {
                const int j = c * 2 + ks;
                float p00 = __expf(sacc[2*j][0]   - mn0), p01 = __expf(sacc[2*j][1]   - mn0);
                float p02 = __expf(sacc[2*j][2]   - mn1), p03 = __expf(sacc[2*j][3]   - mn1);
                float p10 = __expf(sacc[2*j+1][0] - mn0), p11 = __expf(sacc[2*j+1][1] - mn0);
                float p12 = __expf(sacc[2*j+1][2] - mn1), p13 = __expf(sacc[2*j+1][3] - mn1);
                tl0 += p00 + p01 + p10 + p11;
                tl1 += p02 + p03 + p12 + p13;
                uint32_t aP[4] = {h2pack(p00, p01), h2pack(p02, p03),
                                  h2pack(p10, p11), h2pack(p12, p13)};
                const uint32_t rbase = vpan + (ks * 16 + krl) * 272 + nc8 * 2;
#pragma unroll
                for (int p = 0; p < 8; p++) {
                    uint32_t bv[4];
                    LDSM4T(bv, rbase + p * 32);
                    mma16(oacc[2 * p],     aP, bv);
                    mma16(oacc[2 * p + 1], aP, bv + 2);
                }
            }
        }
        tl0 += __shfl_xor_sync(0xffffffff, tl0, 1);
        tl0 += __shfl_xor_sync(0xffffffff, tl0, 2);
        tl1 += __shfl_xor_sync(0xffffffff, tl1, 1);
        tl1 += __shfl_xor_sync(0xffffffff, tl1, 2);
        l0 = l0 * f0 + tl0;
        l1 = l1 * f1 + tl1;
        __syncthreads();
    }

    // ---- epilogue ----
    const float inv0 = 1.0f / l0, inv1 = 1.0f / l1;
    const long long r0 = (long long)(b * SS + q0 + m_off + gid) * ldctx + h * HD;
    const long long r1 = r0 + 8LL * ldctx;
#pragma unroll
    for (int ni = 0; ni < 16; ni++) {
        int n = ni * 8 + 2 * tig;
        *reinterpret_cast<uint32_t*>(ctx + r0 + n) = h2pack(oacc[ni][0] * inv0, oacc[ni][1] * inv0);
        *reinterpret_cast<uint32_t*>(ctx + r1 + n) = h2pack(oacc[ni][2] * inv1, oacc[ni][3] * inv1);
    }
}

// ---------------- elementwise ----------------
__global__ void cvt_kernel(const float* __restrict__ W, hf* __restrict__ Wh, int n4)
{
    int i = blockIdx.x * 256 + threadIdx.x;
    if (i >= n4) return;
    float4 v = reinterpret_cast<const float4*>(W)[i];
    reinterpret_cast<uint32_t*>(Wh)[i * 2 + 0] = h2pack(v.x, v.y);
    reinterpret_cast<uint32_t*>(Wh)[i * 2 + 1] = h2pack(v.z, v.w);
}

// w1 [256][2048]: cols 0..1023 -> wcomb (ld 2048); cols 1024.. -> w1bh (ld 1024)
__global__ void cvt_w1_kernel(const float* __restrict__ w1, hf* __restrict__ wcomb,
                              hf* __restrict__ w1bh)
{
    int i = blockIdx.x * 256 + threadIdx.x;   // 4-float groups; 131072 total
    float4 v = reinterpret_cast<const float4*>(w1)[i];
    int col = (i * 4) & 2047, row = (i * 4) >> 11;
    uint32_t a = h2pack(v.x, v.y), bb = h2pack(v.z, v.w);
    uint32_t* d;
    if (col < 1024) d = reinterpret_cast<uint32_t*>(wcomb + (long long)row * 2048 + col);
    else            d = reinterpret_cast<uint32_t*>(w1bh + (long long)row * 1024 + col - 1024);
    d[0] = a; d[1] = bb;
}

// beff[i] = b1[i] + sum_j w1[i][1024+j] * out_b[j]
__global__ void beff_kernel(const float* __restrict__ w1, const float* __restrict__ b1,
                            const float* __restrict__ out_b, float* __restrict__ beff)
{
    const int i = blockIdx.x, t = threadIdx.x;
    float s = 0.f;
    for (int k = t; k < 1024; k += 256) s += w1[(long long)i * 2048 + 1024 + k] * out_b[k];
    __shared__ float red[256];
    red[t] = s; __syncthreads();
    for (int st = 128; st > 0; st >>= 1) { if (t < st) red[t] += red[t + st]; __syncthreads(); }
    if (t == 0) beff[i] = b1[i] + red[0];
}

__global__ void add_pos_cvt(const float* __restrict__ h, const float* __restrict__ p,
                            hf* __restrict__ xa)
{
    long long i = (long long)blockIdx.x * 256 + threadIdx.x;
    const long long P4 = (long long)SS * HH / 4;
    float4 hv = reinterpret_cast<const float4*>(h)[i];
    float4 pv = reinterpret_cast<const float4*>(p)[i % P4];
    long long row = i >> 8, c4 = i & 255;
    uint32_t* dst = reinterpret_cast<uint32_t*>(xa + row * 2048 + c4 * 4);
    dst[0] = h2pack(hv.x + pv.x, hv.y + pv.y);
    dst[1] = h2pack(hv.z + pv.z, hv.w + pv.w);
}

__global__ void ln_relu_kernel(float* __restrict__ X, const float* __restrict__ g,
                               const float* __restrict__ beta, int width, hf* Xh)
{
    const int row = blockIdx.x, t = threadIdx.x;
    float v = X[(long long)row * width + t];
    __shared__ float red[256];
    red[t] = v; __syncthreads();
    for (int s = blockDim.x >> 1; s > 0; s >>= 1) { if (t < s) red[t] += red[t + s]; __syncthreads(); }
    const float mu = red[0] / width; __syncthreads();
    const float d = v - mu;
    red[t] = d * d; __syncthreads();
    for (int s = blockDim.x >> 1; s > 0; s >>= 1) { if (t < s) red[t] += red[t + s]; __syncthreads(); }
    const float var = red[0] / width;
    float y = d * rsqrtf(var + 1e-5f) * g[t] + beta[t];
    y = fmaxf(y, 0.0f);
    X[(long long)row * width + t] = y;
    if (Xh) Xh[(long long)row * width + t] = __float2half_rn(y);
}

__global__ void final2_kernel(const float* __restrict__ H2, const float* __restrict__ g,
                              const float* __restrict__ beta,
                              const float* __restrict__ w3, const float* __restrict__ b3,
                              const int* __restrict__ tok, const int* __restrict__ mask,
                              const float* __restrict__ table, float* __restrict__ out)
{
    const int row = blockIdx.x, t = threadIdx.x;
    float v = H2[(long long)row * 128 + t];
    __shared__ float red[128];
    red[t] = v; __syncthreads();
    for (int s = 64; s > 0; s >>= 1) { if (t < s) red[t] += red[t + s]; __syncthreads(); }
    const float mu = red[0] / 128.0f; __syncthreads();
    const float d = v - mu;
    red[t] = d * d; __syncthreads();
    for (int s = 64; s > 0; s >>= 1) { if (t < s) red[t] += red[t + s]; __syncthreads(); }
    const float var = red[0] / 128.0f;
    __syncthreads();
    float y = fmaxf(d * rsqrtf(var + 1e-5f) * g[t] + beta[t], 0.0f);
    red[t] = y * w3[t]; __syncthreads();
    for (int s = 64; s > 0; s >>= 1) { if (t < s) red[t] += red[t + s]; __syncthreads(); }
    if (t == 0) {
        float base = red[0] + b3[0];
        float w = base * (1.0f + table[tok[row]]);
        w = fminf(fmaxf(w, 0.1f), 5.0f);
        out[row] = (mask[row] != 0) ? w : 0.0f;
    }
}

// ---------------- launch ----------------
extern "C" void kernel_launch(void* const* d_in, const int* in_sizes, int n_in,
                              void* d_out, int out_size)
{
    const float* hidden = (const float*)d_in[0];
    const int*   tok    = (const int*)d_in[1];
    const int*   mask   = (const int*)d_in[2];
    const float* pos    = (const float*)d_in[3];
    const float* in_w   = (const float*)d_in[4];
    const float* in_b   = (const float*)d_in[5];
    const float* out_w  = (const float*)d_in[6];
    const float* out_b  = (const float*)d_in[7];
    const float* w1     = (const float*)d_in[8];
    const float* b1     = (const float*)d_in[9];
    const float* g1     = (const float*)d_in[10];
    const float* be1    = (const float*)d_in[11];
    const float* w2     = (const float*)d_in[12];
    const float* b2     = (const float*)d_in[13];
    const float* g2     = (const float*)d_in[14];
    const float* be2    = (const float*)d_in[15];
    const float* w3     = (const float*)d_in[16];
    const float* b3     = (const float*)d_in[17];
    const float* table  = (const float*)d_in[18];
    float* out = (float*)d_out;

    float *h1, *h2, *beff;
    hf *xa,*qh,*hh,*iwh,*owh,*w2h,*wcomb,*w1bh;
    { void* p;
      cudaGetSymbolAddress(&p, g_h1);   h1 = (float*)p;
      cudaGetSymbolAddress(&p, g_h2);   h2 = (float*)p;
      cudaGetSymbolAddress(&p, g_beff); beff = (float*)p;
      cudaGetSymbolAddress(&p, g_xa);   xa = (hf*)p;
      cudaGetSymbolAddress(&p, g_qh);   qh = (hf*)p;
      cudaGetSymbolAddress(&p, g_hh);   hh = (hf*)p;
      cudaGetSymbolAddress(&p, g_iwh);  iwh = (hf*)p;
      cudaGetSymbolAddress(&p, g_owh);  owh = (hf*)p;
      cudaGetSymbolAddress(&p, g_w2h);  w2h = (hf*)p;
      cudaGetSymbolAddress(&p, g_wcomb); wcomb = (hf*)p;
      cudaGetSymbolAddress(&p, g_w1bh); w1bh = (hf*)p;
    }
    cudaFuncSetAttribute(flash3_kernel, cudaFuncAttributeMaxDynamicSharedMemorySize, F3_BYTES);

    cvt_kernel<<<(3*HH*HH/4 + 255)/256, 256>>>(in_w, iwh, 3*HH*HH/4);
    cvt_kernel<<<(HH*HH/4 + 255)/256, 256>>>(out_w, owh, HH*HH/4);
    cvt_kernel<<<((METAD/2)*METAD/4 + 255)/256, 256>>>(w2, w2h, (METAD/2)*METAD/4);
    cvt_w1_kernel<<<512, 256>>>(w1, wcomb, w1bh);
    beff_kernel<<<METAD, 256>>>(w1, b1, out_b, beff);
    add_pos_cvt<<<ROWS*HH/4/256, 256>>>(hidden, pos, xa);

    // W_eff = w1b @ ow  (NN): wcomb[:,1024:] = fp16(W_eff)
    gmma<false><<<dim3(8, 2, 1), 256>>>(w1bh, owh, nullptr, wcomb + HH,
                                        HH, HH, HH, 2*HH, nullptr);

    // qkv = x @ in_w^T + in_b
    gmma<true><<<dim3(24, 64, 1), 256>>>(xa, iwh, nullptr, qh,
                                         HH, 2*HH, HH, 3*HH, in_b);

    // fused attention -> ctx into combined buffer cols 1024..
    flash3_kernel<<<dim3(SS/128, BB*NHEADS), 256, F3_BYTES>>>(qh, mask, xa + HH, 2*HH);

    // h1 = [x|ctx] @ [w1a|W_eff]^T + beff
    gmma<true><<<dim3(2, 64, 1), 256>>>(xa, wcomb, h1, nullptr,
                                        2*HH, 2*HH, 2*HH, METAD, beff);

    ln_relu_kernel<<<ROWS, METAD>>>(h1, g1, be1, METAD, hh);

    // h2 = h1 @ w2^T + b2
    gmma<true><<<dim3(1, 64, 1), 256>>>(hh, w2h, h2, nullptr,
                                        METAD, METAD, METAD, METAD/2, b2);

    final2_kernel<<<ROWS, 128>>>(h2, g2, be2, w3, b3, tok, mask, table, out);
}

// round 16
// speedup vs baseline: 4.1949x; 1.0087x over previous
#include <cuda_runtime.h>
#include <cuda_fp16.h>
#include <math.h>
#include <stdint.h>

#define BB 4
#define SS 2048
#define HH 1024
#define NHEADS 8
#define HD 128
#define ROWS (BB*SS)
#define METAD 256

typedef __half hf;

// ---------------- scratch ----------------
__device__ float g_h2 [(size_t)ROWS*(METAD/2)];
__device__ float g_beff[METAD];
__device__ uint4 g_xa  [(size_t)ROWS*2*HH/8];     // [x | ctx] fp16, ld 2048
__device__ uint4 g_qh  [(size_t)ROWS*3*HH/8];
__device__ uint4 g_hh  [(size_t)ROWS*METAD/8];    // h1 fp16 (pre->post LN in place)
__device__ uint4 g_iwh [(size_t)3*HH*HH/8];
__device__ uint4 g_owh [(size_t)HH*HH/8];
__device__ uint4 g_w2h [(size_t)(METAD/2)*METAD/8];
__device__ uint4 g_wcomb[(size_t)METAD*2*HH/8];   // [w1a | W_eff] fp16, ld 2048
__device__ uint4 g_w1bh [(size_t)METAD*HH/8];     // w1b fp16, ld 1024

// ---------------- helpers ----------------
__device__ __forceinline__ void mma16(float c[4], const uint32_t a[4], const uint32_t b[2]) {
    asm volatile("mma.sync.aligned.m16n8k16.row.col.f32.f16.f16.f32 "
        "{%0,%1,%2,%3}, {%4,%5,%6,%7}, {%8,%9}, {%0,%1,%2,%3};"
        : "+f"(c[0]), "+f"(c[1]), "+f"(c[2]), "+f"(c[3])
        : "r"(a[0]), "r"(a[1]), "r"(a[2]), "r"(a[3]), "r"(b[0]), "r"(b[1]));
}
// fp16-accumulator variant (S = QK^T experiment)
__device__ __forceinline__ void mma16h(uint32_t c[2], const uint32_t a[4], const uint32_t b[2]) {
    asm volatile("mma.sync.aligned.m16n8k16.row.col.f16.f16.f16.f16 "
        "{%0,%1}, {%2,%3,%4,%5}, {%6,%7}, {%0,%1};"
        : "+r"(c[0]), "+r"(c[1])
        : "r"(a[0]), "r"(a[1]), "r"(a[2]), "r"(a[3]), "r"(b[0]), "r"(b[1]));
}
__device__ __forceinline__ int swz(int m, int kw) {
    int g = kw >> 2, j = kw & 3;
    return m * 16 + ((g ^ ((m >> 1) & 3)) << 2) + j;
}
__device__ __forceinline__ uint32_t h2pack(float a, float b) {
    __half2 p = __floats2half2_rn(a, b);
    return *reinterpret_cast<uint32_t*>(&p);
}
__device__ __forceinline__ uint32_t smem_u32(const void* p) {
    uint32_t a;
    asm("{ .reg .u64 t; cvta.to.shared.u64 t, %1; cvt.u32.u64 %0, t; }" : "=r"(a) : "l"(p));
    return a;
}
__device__ __forceinline__ void cp16(uint32_t d, const void* s) {
    asm volatile("cp.async.cg.shared.global [%0], [%1], 16;" :: "r"(d), "l"(s) : "memory");
}
__device__ __forceinline__ void cp_commit() { asm volatile("cp.async.commit_group;" ::: "memory"); }
__device__ __forceinline__ void cp_wait0()  { asm volatile("cp.async.wait_group 0;" ::: "memory"); }
__device__ __forceinline__ void cp_wait1()  { asm volatile("cp.async.wait_group 1;" ::: "memory"); }
#define LDSM4T(r, a) \
    asm volatile("ldmatrix.sync.aligned.m8n8.x4.trans.shared.b16 {%0,%1,%2,%3}, [%4];" \
        : "=r"((r)[0]), "=r"((r)[1]), "=r"((r)[2]), "=r"((r)[3]) : "r"(a))

// ---------------------------------------------------------------------------
// fp16 GEMM. BT: B=[N,K]; NN: B=[K,N]. Tile 128x128, ktile 32, 256 thr.
// ---------------------------------------------------------------------------
template<bool BT>
__global__ __launch_bounds__(256)
void gmma(const hf* __restrict__ Ah, const hf* __restrict__ Bh,
          float* __restrict__ C, hf* __restrict__ Ch,
          int K, int lda, int ldb, int ldc,
          const float* __restrict__ bias)
{
    __shared__ __align__(16) uint32_t AsH[128 * 16];
    __shared__ __align__(16) uint32_t BsH[16 * 136];

    const int t = threadIdx.x, lane = t & 31, warp = t >> 5;
    const int gid = lane >> 2, tig = lane & 3;
    const int m_off = (warp >> 2) * 64, n_off = (warp & 3) * 32;
    const int brow = blockIdx.y * 128, bcol = blockIdx.x * 128;

    float acc[4][4][4];
#pragma unroll
    for (int mi = 0; mi < 4; mi++)
#pragma unroll
        for (int ni = 0; ni < 4; ni++)
#pragma unroll
            for (int r = 0; r < 4; r++) acc[mi][ni][r] = 0.0f;

    uint4 cA[2], nA[2], cB[2], nB[2];
    uint2 cB2[2][2], nB2[2][2];

    auto ldg = [&](int kt, uint4* bA, uint4* bB, uint2 (*bB2)[2]) {
#pragma unroll
        for (int i = 0; i < 2; i++) {
            int idx = t + i * 256, row = idx >> 2, quad = idx & 3;
            bA[i] = *reinterpret_cast<const uint4*>(Ah + (long long)(brow + row) * lda + kt + quad * 8);
        }
        if (BT) {
#pragma unroll
            for (int i = 0; i < 2; i++) {
                int idx = t + i * 256, row = idx >> 2, quad = idx & 3;
                bB[i] = *reinterpret_cast<const uint4*>(Bh + (long long)(bcol + row) * ldb + kt + quad * 8);
            }
        } else {
#pragma unroll
            for (int i = 0; i < 2; i++) {
                int idx = t + i * 256, kp = idx >> 5, q = idx & 31;
                const hf* p0 = Bh + (long long)(kt + 2 * kp) * ldb + bcol + q * 4;
                bB2[i][0] = *reinterpret_cast<const uint2*>(p0);
                bB2[i][1] = *reinterpret_cast<const uint2*>(p0 + ldb);
            }
        }
    };
    auto sts = [&](const uint4* bA, const uint4* bB, const uint2 (*bB2)[2]) {
#pragma unroll
        for (int i = 0; i < 2; i++) {
            int idx = t + i * 256, row = idx >> 2, quad = idx & 3;
            int base = row * 16 + ((quad ^ ((row >> 1) & 3)) << 2);
            *reinterpret_cast<uint4*>(&AsH[base]) = bA[i];
        }
        if (BT) {
#pragma unroll
            for (int i = 0; i < 2; i++) {
                int idx = t + i * 256, row = idx >> 2, quad = idx & 3;
                int base = row * 16 + ((quad ^ ((row >> 1) & 3)) << 2);
                *reinterpret_cast<uint4*>(&BsH[base]) = bB[i];
            }
        } else {
#pragma unroll
            for (int i = 0; i < 2; i++) {
                int idx = t + i * 256, kp = idx >> 5, q = idx & 31;
                uint4 h;
                h.x = __byte_perm(bB2[i][0].x, bB2[i][1].x, 0x5410);
                h.y = __byte_perm(bB2[i][0].x, bB2[i][1].x, 0x7632);
                h.z = __byte_perm(bB2[i][0].y, bB2[i][1].y, 0x5410);
                h.w = __byte_perm(bB2[i][0].y, bB2[i][1].y, 0x7632);
                *reinterpret_cast<uint4*>(&BsH[kp * 136 + q * 4]) = h;
            }
        }
    };

    ldg(0, cA, cB, cB2);
    sts(cA, cB, cB2);
    __syncthreads();

    for (int kt = 0; kt < K; kt += 32) {
        const bool more = (kt + 32) < K;
        if (more) ldg(kt + 32, nA, nB, nB2);
#pragma unroll
        for (int ks = 0; ks < 2; ks++) {
            const int k0 = ks * 8 + tig, k1 = k0 + 4;
            uint32_t bH[4][2];
#pragma unroll
            for (int ni = 0; ni < 4; ni++) {
                int n0 = n_off + ni * 8 + gid;
                if (BT) { bH[ni][0] = BsH[swz(n0, k0)]; bH[ni][1] = BsH[swz(n0, k1)]; }
                else    { bH[ni][0] = BsH[k0 * 136 + n0]; bH[ni][1] = BsH[k1 * 136 + n0]; }
            }
#pragma unroll
            for (int mi = 0; mi < 4; mi++) {
                int m0 = m_off + mi * 16 + gid;
                uint32_t aH[4] = {AsH[swz(m0, k0)], AsH[swz(m0 + 8, k0)],
                                  AsH[swz(m0, k1)], AsH[swz(m0 + 8, k1)]};
#pragma unroll
                for (int ni = 0; ni < 4; ni++)
                    mma16(acc[mi][ni], aH, bH[ni]);
            }
        }
        __syncthreads();
        if (more) { sts(nA, nB, nB2); __syncthreads(); }
    }

#pragma unroll
    for (int mi = 0; mi < 4; mi++)
#pragma unroll
        for (int ni = 0; ni < 4; ni++) {
            int m = brow + m_off + mi * 16 + gid;
            int n = bcol + n_off + ni * 8 + 2 * tig;
            float b0 = 0.f, b1 = 0.f;
            if (bias) { b0 = bias[n]; b1 = bias[n + 1]; }
#pragma unroll
            for (int h = 0; h < 2; h++) {
                long long r = m + h * 8;
                float vx = acc[mi][ni][h * 2 + 0] + b0;
                float vy = acc[mi][ni][h * 2 + 1] + b1;
                if (C) *reinterpret_cast<float2*>(C + r * ldc + n) = make_float2(vx, vy);
                if (Ch) *reinterpret_cast<uint32_t*>(Ch + r * ldc + n) = h2pack(vx, vy);
            }
        }
}

// ---------------------------------------------------------------------------
// Flash v4: register-P, cp.async double-buffered K/V, S-MMA with fp16 accum.
// smem words: Q 8192 | K 2x8192 | V 2x8704 | mask 2x128  = 42240
// ---------------------------------------------------------------------------
#define F3_WORDS 42240
#define F3_BYTES (F3_WORDS * 4)

__global__ __launch_bounds__(256, 1)
void flash4_kernel(const hf* __restrict__ qkv, const int* __restrict__ mask,
                   hf* __restrict__ ctx, int ldctx)
{
    extern __shared__ __align__(16) uint32_t sm[];
    uint32_t* Qs = sm;
    uint32_t* Ks = sm + 8192;
    float* maskadd = (float*)(sm + 41984);
    const uint32_t smb = smem_u32(sm);

    const int t = threadIdx.x, lane = t & 31, warp = t >> 5;
    const int gid = lane >> 2, tig = lane & 3;
    const int m_off = warp * 16;
    const int krl = (lane & 7) + ((lane >> 3) & 1) * 8;
    const int nc8 = ((lane >> 4) & 1) * 8;
    const int bh = blockIdx.y, b = bh >> 3, h = bh & 7;
    const int q0 = blockIdx.x * 128;
    const long long ld = 3 * HH;
    const hf* Qg = qkv + ((long long)(b * SS) + q0) * ld + h * HD;
    const hf* Kg = qkv + (long long)(b * SS) * ld + HH + h * HD;
    const hf* Vg = qkv + (long long)(b * SS) * ld + 2 * HH + h * HD;

    // Q once
#pragma unroll
    for (int c = 0; c < 4; c++)
#pragma unroll
        for (int i = 0; i < 2; i++) {
            int idx = t + i * 256, row = idx >> 2, quad = idx & 3;
            int base = row * 16 + ((quad ^ ((row >> 1) & 3)) << 2);
            *reinterpret_cast<uint4*>(&Qs[c * 2048 + base]) =
                *reinterpret_cast<const uint4*>(Qg + (long long)row * ld + c * 32 + quad * 8);
        }

    auto prefetch = [&](int kt) {
        const int buf = kt & 1;
        const int key0 = kt * 128;
        const uint32_t kbase = smb + 32768 + buf * 32768;
        const uint32_t vbase = smb + 98304 + buf * 34816;
#pragma unroll
        for (int c = 0; c < 4; c++)
#pragma unroll
            for (int i = 0; i < 2; i++) {
                int id = t + i * 256, row = id >> 2, quad = id & 3;
                uint32_t d = kbase + c * 8192 + row * 64 + ((quad ^ ((row >> 1) & 3)) << 4);
                cp16(d, Kg + (long long)(key0 + row) * ld + c * 32 + quad * 8);
            }
#pragma unroll
        for (int c = 0; c < 4; c++)
#pragma unroll
            for (int i = 0; i < 2; i++) {
                int id = t + i * 256, row = id >> 4, seg = id & 15;
                uint32_t d = vbase + c * 8704 + row * 272 + seg * 16;
                cp16(d, Vg + (long long)(key0 + c * 32 + row) * ld + seg * 8);
            }
        cp_commit();
        if (t < 128) maskadd[buf * 128 + t] = (mask[b * SS + key0 + t] != 0) ? 0.0f : -1e9f;
    };

    float m0 = -1e30f, m1 = -1e30f, l0 = 0.f, l1 = 0.f;
    float oacc[16][4];
#pragma unroll
    for (int ni = 0; ni < 16; ni++)
#pragma unroll
        for (int r = 0; r < 4; r++) oacc[ni][r] = 0.0f;

    prefetch(0);

    for (int kt = 0; kt < 16; kt++) {
        const int buf = kt & 1;
        if (kt + 1 < 16) { prefetch(kt + 1); cp_wait1(); } else cp_wait0();
        __syncthreads();

        // ---- S = Q K^T (fp16 accumulators) ----
        uint32_t sacc2[16][2];
#pragma unroll
        for (int ni = 0; ni < 16; ni++) { sacc2[ni][0] = 0u; sacc2[ni][1] = 0u; }
#pragma unroll
        for (int c = 0; c < 4; c++) {
            const uint32_t* As = Qs + c * 2048;
            const uint32_t* Bs = Ks + buf * 8192 + c * 2048;
#pragma unroll
            for (int ks = 0; ks < 2; ks++) {
                const int k0 = ks * 8 + tig, k1 = k0 + 4;
                int mr = m_off + gid;
                uint32_t aH[4] = {As[swz(mr, k0)], As[swz(mr + 8, k0)],
                                  As[swz(mr, k1)], As[swz(mr + 8, k1)]};
#pragma unroll
                for (int ni = 0; ni < 16; ni++) {
                    int n0 = ni * 8 + gid;
                    uint32_t bH[2] = {Bs[swz(n0, k0)], Bs[swz(n0, k1)]};
                    mma16h(sacc2[ni], aH, bH);
                }
            }
        }

        // ---- unpack + scale + mask + row-max ----
        const float* mrow = maskadd + buf * 128;
        float sacc[16][4];
        float tm0 = -1e30f, tm1 = -1e30f;
#pragma unroll
        for (int ni = 0; ni < 16; ni++) {
            float2 v01 = __half22float2(*reinterpret_cast<__half2*>(&sacc2[ni][0]));
            float2 v23 = __half22float2(*reinterpret_cast<__half2*>(&sacc2[ni][1]));
            float ma = mrow[ni * 8 + 2 * tig], mb = mrow[ni * 8 + 2 * tig + 1];
            float s0 = v01.x * 0.08838834764831843f + ma;
            float s1 = v01.y * 0.08838834764831843f + mb;
            float s2 = v23.x * 0.08838834764831843f + ma;
            float s3 = v23.y * 0.08838834764831843f + mb;
            sacc[ni][0] = s0; sacc[ni][1] = s1; sacc[ni][2] = s2; sacc[ni][3] = s3;
            tm0 = fmaxf(tm0, fmaxf(s0, s1));
            tm1 = fmaxf(tm1, fmaxf(s2, s3));
        }
        tm0 = fmaxf(tm0, __shfl_xor_sync(0xffffffff, tm0, 1));
        tm0 = fmaxf(tm0, __shfl_xor_sync(0xffffffff, tm0, 2));
        tm1 = fmaxf(tm1, __shfl_xor_sync(0xffffffff, tm1, 1));
        tm1 = fmaxf(tm1, __shfl_xor_sync(0xffffffff, tm1, 2));
        float mn0 = fmaxf(m0, tm0), mn1 = fmaxf(m1, tm1);
        float f0 = __expf(m0 - mn0), f1 = __expf(m1 - mn1);
        m0 = mn0; m1 = mn1;
#pragma unroll
        for (int ni = 0; ni < 16; ni++) {
            oacc[ni][0] *= f0; oacc[ni][1] *= f0;
            oacc[ni][2] *= f1; oacc[ni][3] *= f1;
        }

        // ---- exp -> P regs -> PV (V raw + LDSM4T, f32 accum) ----
        float tl0 = 0.f, tl1 = 0.f;
#pragma unroll
        for (int c = 0; c < 4; c++) {
            const uint32_t vpan = smb + 98304 + buf * 34816 + c * 8704;
#pragma unroll
            for (int ks = 0; ks < 2; ks++) {
                const int j = c * 2 + ks;
                float p00 = __expf(sacc[2*j][0]   - mn0), p01 = __expf(sacc[2*j][1]   - mn0);
                float p02 = __expf(sacc[2*j][2]   - mn1), p03 = __expf(sacc[2*j][3]   - mn1);
                float p10 = __expf(sacc[2*j+1][0] - mn0), p11 = __expf(sacc[2*j+1][1] - mn0);
                float p12 = __expf(sacc[2*j+1][2] - mn1), p13 = __expf(sacc[2*j+1][3] - mn1);
                tl0 += p00 + p01 + p10 + p11;
                tl1 += p02 + p03 + p12 + p13;
                uint32_t aP[4] = {h2pack(p00, p01), h2pack(p02, p03),
                                  h2pack(p10, p11), h2pack(p12, p13)};
                const uint32_t rbase = vpan + (ks * 16 + krl) * 272 + nc8 * 2;
#pragma unroll
                for (int p = 0; p < 8; p++) {
                    uint32_t bv[4];
                    LDSM4T(bv, rbase + p * 32);
                    mma16(oacc[2 * p],     aP, bv);
                    mma16(oacc[2 * p + 1], aP, bv + 2);
                }
            }
        }
        tl0 += __shfl_xor_sync(0xffffffff, tl0, 1);
        tl0 += __shfl_xor_sync(0xffffffff, tl0, 2);
        tl1 += __shfl_xor_sync(0xffffffff, tl1, 1);
        tl1 += __shfl_xor_sync(0xffffffff, tl1, 2);
        l0 = l0 * f0 + tl0;
        l1 = l1 * f1 + tl1;
        __syncthreads();
    }

    // ---- epilogue ----
    const float inv0 = 1.0f / l0, inv1 = 1.0f / l1;
    const long long r0 = (long long)(b * SS + q0 + m_off + gid) * ldctx + h * HD;
    const long long r1 = r0 + 8LL * ldctx;
#pragma unroll
    for (int ni = 0; ni < 16; ni++) {
        int n = ni * 8 + 2 * tig;
        *reinterpret_cast<uint32_t*>(ctx + r0 + n) = h2pack(oacc[ni][0] * inv0, oacc[ni][1] * inv0);
        *reinterpret_cast<uint32_t*>(ctx + r1 + n) = h2pack(oacc[ni][2] * inv1, oacc[ni][3] * inv1);
    }
}

// ---------------------------------------------------------------------------
// Fused prep: all weight cvts + w1 split + beff + add_pos. Block-range dispatch.
// blocks: [0,3072) in_w | [3072,4096) out_w | [4096,4128) w2 |
//         [4128,4640) w1 split | [4640,4896) beff | [4896,13088) add_pos
// ---------------------------------------------------------------------------
__global__ void prep_kernel(const float* __restrict__ in_w, hf* __restrict__ iwh,
                            const float* __restrict__ out_w, hf* __restrict__ owh,
                            const float* __restrict__ w2, hf* __restrict__ w2h,
                            const float* __restrict__ w1, hf* __restrict__ wcomb,
                            hf* __restrict__ w1bh,
                            const float* __restrict__ b1, const float* __restrict__ out_b,
                            float* __restrict__ beff,
                            const float* __restrict__ hidden, const float* __restrict__ pos,
                            hf* __restrict__ xa)
{
    const int blk = blockIdx.x, t = threadIdx.x;
    if (blk < 3072) {
        int i = blk * 256 + t;
        float4 v = reinterpret_cast<const float4*>(in_w)[i];
        reinterpret_cast<uint32_t*>(iwh)[i * 2 + 0] = h2pack(v.x, v.y);
        reinterpret_cast<uint32_t*>(iwh)[i * 2 + 1] = h2pack(v.z, v.w);
    } else if (blk < 4096) {
        int i = (blk - 3072) * 256 + t;
        float4 v = reinterpret_cast<const float4*>(out_w)[i];
        reinterpret_cast<uint32_t*>(owh)[i * 2 + 0] = h2pack(v.x, v.y);
        reinterpret_cast<uint32_t*>(owh)[i * 2 + 1] = h2pack(v.z, v.w);
    } else if (blk < 4128) {
        int i = (blk - 4096) * 256 + t;
        float4 v = reinterpret_cast<const float4*>(w2)[i];
        reinterpret_cast<uint32_t*>(w2h)[i * 2 + 0] = h2pack(v.x, v.y);
        reinterpret_cast<uint32_t*>(w2h)[i * 2 + 1] = h2pack(v.z, v.w);
    } else if (blk < 4640) {
        int i = (blk - 4128) * 256 + t;
        float4 v = reinterpret_cast<const float4*>(w1)[i];
        int col = (i * 4) & 2047, row = (i * 4) >> 11;
        uint32_t a = h2pack(v.x, v.y), bb = h2pack(v.z, v.w);
        uint32_t* d;
        if (col < 1024) d = reinterpret_cast<uint32_t*>(wcomb + (long long)row * 2048 + col);
        else            d = reinterpret_cast<uint32_t*>(w1bh + (long long)row * 1024 + col - 1024);
        d[0] = a; d[1] = bb;
    } else if (blk < 4896) {
        const int i = blk - 4640;
        float s = 0.f;
        for (int k = t; k < 1024; k += 256) s += w1[(long long)i * 2048 + 1024 + k] * out_b[k];
        __shared__ float red[256];
        red[t] = s; __syncthreads();
        for (int st = 128; st > 0; st >>= 1) { if (t < st) red[t] += red[t + st]; __syncthreads(); }
        if (t == 0) beff[i] = b1[i] + red[0];
    } else {
        long long i = (long long)(blk - 4896) * 256 + t;
        const long long P4 = (long long)SS * HH / 4;
        float4 hv = reinterpret_cast<const float4*>(hidden)[i];
        float4 pv = reinterpret_cast<const float4*>(pos)[i % P4];
        long long row = i >> 8, c4 = i & 255;
        uint32_t* dst = reinterpret_cast<uint32_t*>(xa + row * 2048 + c4 * 4);
        dst[0] = h2pack(hv.x + pv.x, hv.y + pv.y);
        dst[1] = h2pack(hv.z + pv.z, hv.w + pv.w);
    }
}

// in-place fp16 LN+ReLU, width 256
__global__ void ln_relu_hf(hf* __restrict__ X, const float* __restrict__ g,
                           const float* __restrict__ beta)
{
    const int row = blockIdx.x, t = threadIdx.x;
    float v = __half2float(X[(long long)row * 256 + t]);
    __shared__ float red[256];
    red[t] = v; __syncthreads();
    for (int s = 128; s > 0; s >>= 1) { if (t < s) red[t] += red[t + s]; __syncthreads(); }
    const float mu = red[0] / 256.0f; __syncthreads();
    const float d = v - mu;
    red[t] = d * d; __syncthreads();
    for (int s = 128; s > 0; s >>= 1) { if (t < s) red[t] += red[t + s]; __syncthreads(); }
    const float var = red[0] / 256.0f;
    float y = fmaxf(d * rsqrtf(var + 1e-5f) * g[t] + beta[t], 0.0f);
    X[(long long)row * 256 + t] = __float2half_rn(y);
}

__global__ void final2_kernel(const float* __restrict__ H2, const float* __restrict__ g,
                              const float* __restrict__ beta,
                              const float* __restrict__ w3, const float* __restrict__ b3,
                              const int* __restrict__ tok, const int* __restrict__ mask,
                              const float* __restrict__ table, float* __restrict__ out)
{
    const int row = blockIdx.x, t = threadIdx.x;
    float v = H2[(long long)row * 128 + t];
    __shared__ float red[128];
    red[t] = v; __syncthreads();
    for (int s = 64; s > 0; s >>= 1) { if (t < s) red[t] += red[t + s]; __syncthreads(); }
    const float mu = red[0] / 128.0f; __syncthreads();
    const float d = v - mu;
    red[t] = d * d; __syncthreads();
    for (int s = 64; s > 0; s >>= 1) { if (t < s) red[t] += red[t + s]; __syncthreads(); }
    const float var = red[0] / 128.0f;
    __syncthreads();
    float y = fmaxf(d * rsqrtf(var + 1e-5f) * g[t] + beta[t], 0.0f);
    red[t] = y * w3[t]; __syncthreads();
    for (int s = 64; s > 0; s >>= 1) { if (t < s) red[t] += red[t + s]; __syncthreads(); }
    if (t == 0) {
        float base = red[0] + b3[0];
        float w = base * (1.0f + table[tok[row]]);
        w = fminf(fmaxf(w, 0.1f), 5.0f);
        out[row] = (mask[row] != 0) ? w : 0.0f;
    }
}

// ---------------- launch ----------------
extern "C" void kernel_launch(void* const* d_in, const int* in_sizes, int n_in,
                              void* d_out, int out_size)
{
    const float* hidden = (const float*)d_in[0];
    const int*   tok    = (const int*)d_in[1];
    const int*   mask   = (const int*)d_in[2];
    const float* pos    = (const float*)d_in[3];
    const float* in_w   = (const float*)d_in[4];
    const float* in_b   = (const float*)d_in[5];
    const float* out_w  = (const float*)d_in[6];
    const float* out_b  = (const float*)d_in[7];
    const float* w1     = (const float*)d_in[8];
    const float* b1     = (const float*)d_in[9];
    const float* g1     = (const float*)d_in[10];
    const float* be1    = (const float*)d_in[11];
    const float* w2     = (const float*)d_in[12];
    const float* b2     = (const float*)d_in[13];
    const float* g2     = (const float*)d_in[14];
    const float* be2    = (const float*)d_in[15];
    const float* w3     = (const float*)d_in[16];
    const float* b3     = (const float*)d_in[17];
    const float* table  = (const float*)d_in[18];
    float* out = (float*)d_out;

    float *h2, *beff;
    hf *xa,*qh,*hh,*iwh,*owh,*w2h,*wcomb,*w1bh;
    { void* p;
      cudaGetSymbolAddress(&p, g_h2);   h2 = (float*)p;
      cudaGetSymbolAddress(&p, g_beff); beff = (float*)p;
      cudaGetSymbolAddress(&p, g_xa);   xa = (hf*)p;
      cudaGetSymbolAddress(&p, g_qh);   qh = (hf*)p;
      cudaGetSymbolAddress(&p, g_hh);   hh = (hf*)p;
      cudaGetSymbolAddress(&p, g_iwh);  iwh = (hf*)p;
      cudaGetSymbolAddress(&p, g_owh);  owh = (hf*)p;
      cudaGetSymbolAddress(&p, g_w2h);  w2h = (hf*)p;
      cudaGetSymbolAddress(&p, g_wcomb); wcomb = (hf*)p;
      cudaGetSymbolAddress(&p, g_w1bh); w1bh = (hf*)p;
    }
    cudaFuncSetAttribute(flash4_kernel, cudaFuncAttributeMaxDynamicSharedMemorySize, F3_BYTES);

    // fused prep (all cvts + w1 split + beff + add_pos)
    prep_kernel<<<13088, 256>>>(in_w, iwh, out_w, owh, w2, w2h, w1, wcomb, w1bh,
                                b1, out_b, beff, hidden, pos, xa);

    // W_eff = w1b @ ow  (NN): wcomb[:,1024:] = fp16(W_eff)
    gmma<false><<<dim3(8, 2, 1), 256>>>(w1bh, owh, nullptr, wcomb + HH,
                                        HH, HH, HH, 2*HH, nullptr);

    // qkv = x @ in_w^T + in_b
    gmma<true><<<dim3(24, 64, 1), 256>>>(xa, iwh, nullptr, qh,
                                         HH, 2*HH, HH, 3*HH, in_b);

    // fused attention -> ctx into combined buffer cols 1024..
    flash4_kernel<<<dim3(SS/128, BB*NHEADS), 256, F3_BYTES>>>(qh, mask, xa + HH, 2*HH);

    // h1 = [x|ctx] @ [w1a|W_eff]^T + beff   (fp16 out)
    gmma<true><<<dim3(2, 64, 1), 256>>>(xa, wcomb, nullptr, hh,
                                        2*HH, 2*HH, 2*HH, METAD, beff);

    ln_relu_hf<<<ROWS, 256>>>(hh, g1, be1);

    // h2 = h1 @ w2^T + b2
    gmma<true><<<dim3(1, 64, 1), 256>>>(hh, w2h, h2, nullptr,
                                        METAD, METAD, METAD, METAD/2, b2);

    final2_kernel<<<ROWS, 128>>>(h2, g2, be2, w3, b3, tok, mask, table, out);
}

// round 17
// speedup vs baseline: 4.4314x; 1.0564x over previous
#include <cuda_runtime.h>
#include <cuda_fp16.h>
#include <math.h>
#include <stdint.h>

#define BB 4
#define SS 2048
#define HH 1024
#define NHEADS 8
#define HD 128
#define ROWS (BB*SS)
#define METAD 256

typedef __half hf;

// ---------------- scratch ----------------
__device__ float g_beff[METAD];
__device__ uint4 g_xa  [(size_t)ROWS*2*HH/8];     // [x | ctx] fp16, ld 2048
__device__ uint4 g_qh  [(size_t)ROWS*3*HH/8];
__device__ uint4 g_hh  [(size_t)ROWS*METAD/8];    // h1 fp16 (pre->post LN in place)
__device__ uint4 g_iwh [(size_t)3*HH*HH/8];
__device__ uint4 g_owh [(size_t)HH*HH/8];
__device__ uint4 g_w2h [(size_t)(METAD/2)*METAD/8];
__device__ uint4 g_wcomb[(size_t)METAD*2*HH/8];   // [w1a | W_eff] fp16, ld 2048
__device__ uint4 g_w1bh [(size_t)METAD*HH/8];     // w1b fp16, ld 1024

// ---------------- helpers ----------------
__device__ __forceinline__ void mma16(float c[4], const uint32_t a[4], const uint32_t b[2]) {
    asm volatile("mma.sync.aligned.m16n8k16.row.col.f32.f16.f16.f32 "
        "{%0,%1,%2,%3}, {%4,%5,%6,%7}, {%8,%9}, {%0,%1,%2,%3};"
        : "+f"(c[0]), "+f"(c[1]), "+f"(c[2]), "+f"(c[3])
        : "r"(a[0]), "r"(a[1]), "r"(a[2]), "r"(a[3]), "r"(b[0]), "r"(b[1]));
}
__device__ __forceinline__ void mma16h(uint32_t c[2], const uint32_t a[4], const uint32_t b[2]) {
    asm volatile("mma.sync.aligned.m16n8k16.row.col.f16.f16.f16.f16 "
        "{%0,%1}, {%2,%3,%4,%5}, {%6,%7}, {%0,%1};"
        : "+r"(c[0]), "+r"(c[1])
        : "r"(a[0]), "r"(a[1]), "r"(a[2]), "r"(a[3]), "r"(b[0]), "r"(b[1]));
}
__device__ __forceinline__ int swz(int m, int kw) {
    int g = kw >> 2, j = kw & 3;
    return m * 16 + ((g ^ ((m >> 1) & 3)) << 2) + j;
}
__device__ __forceinline__ uint32_t h2pack(float a, float b) {
    __half2 p = __floats2half2_rn(a, b);
    return *reinterpret_cast<uint32_t*>(&p);
}
__device__ __forceinline__ uint32_t smem_u32(const void* p) {
    uint32_t a;
    asm("{ .reg .u64 t; cvta.to.shared.u64 t, %1; cvt.u32.u64 %0, t; }" : "=r"(a) : "l"(p));
    return a;
}
__device__ __forceinline__ void cp16(uint32_t d, const void* s) {
    asm volatile("cp.async.cg.shared.global [%0], [%1], 16;" :: "r"(d), "l"(s) : "memory");
}
__device__ __forceinline__ void cp_commit() { asm volatile("cp.async.commit_group;" ::: "memory"); }
__device__ __forceinline__ void cp_wait0()  { asm volatile("cp.async.wait_group 0;" ::: "memory"); }
#define LDSM4T(r, a) \
    asm volatile("ldmatrix.sync.aligned.m8n8.x4.trans.shared.b16 {%0,%1,%2,%3}, [%4];" \
        : "=r"((r)[0]), "=r"((r)[1]), "=r"((r)[2]), "=r"((r)[3]) : "r"(a))

// ---------------------------------------------------------------------------
// fp16 GEMM. BT: B=[N,K]; NN: B=[K,N]. Tile 128x128, ktile 32, 256 thr.
// ---------------------------------------------------------------------------
template<bool BT>
__global__ __launch_bounds__(256)
void gmma(const hf* __restrict__ Ah, const hf* __restrict__ Bh,
          float* __restrict__ C, hf* __restrict__ Ch,
          int K, int lda, int ldb, int ldc,
          const float* __restrict__ bias)
{
    __shared__ __align__(16) uint32_t AsH[128 * 16];
    __shared__ __align__(16) uint32_t BsH[16 * 136];

    const int t = threadIdx.x, lane = t & 31, warp = t >> 5;
    const int gid = lane >> 2, tig = lane & 3;
    const int m_off = (warp >> 2) * 64, n_off = (warp & 3) * 32;
    const int brow = blockIdx.y * 128, bcol = blockIdx.x * 128;

    float acc[4][4][4];
#pragma unroll
    for (int mi = 0; mi < 4; mi++)
#pragma unroll
        for (int ni = 0; ni < 4; ni++)
#pragma unroll
            for (int r = 0; r < 4; r++) acc[mi][ni][r] = 0.0f;

    uint4 cA[2], nA[2], cB[2], nB[2];
    uint2 cB2[2][2], nB2[2][2];

    auto ldg = [&](int kt, uint4* bA, uint4* bB, uint2 (*bB2)[2]) {
#pragma unroll
        for (int i = 0; i < 2; i++) {
            int idx = t + i * 256, row = idx >> 2, quad = idx & 3;
            bA[i] = *reinterpret_cast<const uint4*>(Ah + (long long)(brow + row) * lda + kt + quad * 8);
        }
        if (BT) {
#pragma unroll
            for (int i = 0; i < 2; i++) {
                int idx = t + i * 256, row = idx >> 2, quad = idx & 3;
                bB[i] = *reinterpret_cast<const uint4*>(Bh + (long long)(bcol + row) * ldb + kt + quad * 8);
            }
        } else {
#pragma unroll
            for (int i = 0; i < 2; i++) {
                int idx = t + i * 256, kp = idx >> 5, q = idx & 31;
                const hf* p0 = Bh + (long long)(kt + 2 * kp) * ldb + bcol + q * 4;
                bB2[i][0] = *reinterpret_cast<const uint2*>(p0);
                bB2[i][1] = *reinterpret_cast<const uint2*>(p0 + ldb);
            }
        }
    };
    auto sts = [&](const uint4* bA, const uint4* bB, const uint2 (*bB2)[2]) {
#pragma unroll
        for (int i = 0; i < 2; i++) {
            int idx = t + i * 256, row = idx >> 2, quad = idx & 3;
            int base = row * 16 + ((quad ^ ((row >> 1) & 3)) << 2);
            *reinterpret_cast<uint4*>(&AsH[base]) = bA[i];
        }
        if (BT) {
#pragma unroll
            for (int i = 0; i < 2; i++) {
                int idx = t + i * 256, row = idx >> 2, quad = idx & 3;
                int base = row * 16 + ((quad ^ ((row >> 1) & 3)) << 2);
                *reinterpret_cast<uint4*>(&BsH[base]) = bB[i];
            }
        } else {
#pragma unroll
            for (int i = 0; i < 2; i++) {
                int idx = t + i * 256, kp = idx >> 5, q = idx & 31;
                uint4 h;
                h.x = __byte_perm(bB2[i][0].x, bB2[i][1].x, 0x5410);
                h.y = __byte_perm(bB2[i][0].x, bB2[i][1].x, 0x7632);
                h.z = __byte_perm(bB2[i][0].y, bB2[i][1].y, 0x5410);
                h.w = __byte_perm(bB2[i][0].y, bB2[i][1].y, 0x7632);
                *reinterpret_cast<uint4*>(&BsH[kp * 136 + q * 4]) = h;
            }
        }
    };

    ldg(0, cA, cB, cB2);
    sts(cA, cB, cB2);
    __syncthreads();

    for (int kt = 0; kt < K; kt += 32) {
        const bool more = (kt + 32) < K;
        if (more) ldg(kt + 32, nA, nB, nB2);
#pragma unroll
        for (int ks = 0; ks < 2; ks++) {
            const int k0 = ks * 8 + tig, k1 = k0 + 4;
            uint32_t bH[4][2];
#pragma unroll
            for (int ni = 0; ni < 4; ni++) {
                int n0 = n_off + ni * 8 + gid;
                if (BT) { bH[ni][0] = BsH[swz(n0, k0)]; bH[ni][1] = BsH[swz(n0, k1)]; }
                else    { bH[ni][0] = BsH[k0 * 136 + n0]; bH[ni][1] = BsH[k1 * 136 + n0]; }
            }
#pragma unroll
            for (int mi = 0; mi < 4; mi++) {
                int m0 = m_off + mi * 16 + gid;
                uint32_t aH[4] = {AsH[swz(m0, k0)], AsH[swz(m0 + 8, k0)],
                                  AsH[swz(m0, k1)], AsH[swz(m0 + 8, k1)]};
#pragma unroll
                for (int ni = 0; ni < 4; ni++)
                    mma16(acc[mi][ni], aH, bH[ni]);
            }
        }
        __syncthreads();
        if (more) { sts(nA, nB, nB2); __syncthreads(); }
    }

#pragma unroll
    for (int mi = 0; mi < 4; mi++)
#pragma unroll
        for (int ni = 0; ni < 4; ni++) {
            int m = brow + m_off + mi * 16 + gid;
            int n = bcol + n_off + ni * 8 + 2 * tig;
            float b0 = 0.f, b1 = 0.f;
            if (bias) { b0 = bias[n]; b1 = bias[n + 1]; }
#pragma unroll
            for (int h = 0; h < 2; h++) {
                long long r = m + h * 8;
                float vx = acc[mi][ni][h * 2 + 0] + b0;
                float vy = acc[mi][ni][h * 2 + 1] + b1;
                if (C) *reinterpret_cast<float2*>(C + r * ldc + n) = make_float2(vx, vy);
                if (Ch) *reinterpret_cast<uint32_t*>(Ch + r * ldc + n) = h2pack(vx, vy);
            }
        }
}

// ---------------------------------------------------------------------------
// Flash v5: 128 thr / 4 warps, 64-row q-tile, single-buffer K/V, 2 CTAs/SM.
// smem words: Q 4096 | K 8192 | V 8704 | mask 128  = 21120 (84.5 KB)
// ---------------------------------------------------------------------------
#define F5_WORDS 21120
#define F5_BYTES (F5_WORDS * 4)

__global__ __launch_bounds__(128, 2)
void flash5_kernel(const hf* __restrict__ qkv, const int* __restrict__ mask,
                   hf* __restrict__ ctx, int ldctx)
{
    extern __shared__ __align__(16) uint32_t sm[];
    uint32_t* Qs = sm;              // 4 panels x 1024
    uint32_t* Ks = sm + 4096;       // 4 panels x 2048
    float* maskadd = (float*)(sm + 20992);
    const uint32_t smb = smem_u32(sm);
    const uint32_t vbase = smb + 12288 * 4;   // V: 4 panels x 2176 words

    const int t = threadIdx.x, lane = t & 31, warp = t >> 5;
    const int gid = lane >> 2, tig = lane & 3;
    const int m_off = warp * 16;
    const int krl = (lane & 7) + ((lane >> 3) & 1) * 8;
    const int nc8 = ((lane >> 4) & 1) * 8;
    const int bh = blockIdx.y, b = bh >> 3, h = bh & 7;
    const int q0 = blockIdx.x * 64;
    const long long ld = 3 * HH;
    const hf* Qg = qkv + ((long long)(b * SS) + q0) * ld + h * HD;
    const hf* Kg = qkv + (long long)(b * SS) * ld + HH + h * HD;
    const hf* Vg = qkv + (long long)(b * SS) * ld + 2 * HH + h * HD;

    // Q once (64 rows)
#pragma unroll
    for (int c = 0; c < 4; c++)
#pragma unroll
        for (int i = 0; i < 2; i++) {
            int idx = t + i * 128, row = idx >> 2, quad = idx & 3;
            int base = row * 16 + ((quad ^ ((row >> 1) & 3)) << 2);
            *reinterpret_cast<uint4*>(&Qs[c * 1024 + base]) =
                *reinterpret_cast<const uint4*>(Qg + (long long)row * ld + c * 32 + quad * 8);
        }

    float m0 = -1e30f, m1 = -1e30f, l0 = 0.f, l1 = 0.f;
    float oacc[16][4];
#pragma unroll
    for (int ni = 0; ni < 16; ni++)
#pragma unroll
        for (int r = 0; r < 4; r++) oacc[ni][r] = 0.0f;

    for (int kt = 0; kt < 16; kt++) {
        const int key0 = kt * 128;
        // K tile (BT panels, 128 rows)
#pragma unroll
        for (int c = 0; c < 4; c++)
#pragma unroll
            for (int i = 0; i < 4; i++) {
                int id = t + i * 128, row = id >> 2, quad = id & 3;
                uint32_t d = smb + 16384 + c * 8192 + row * 64 + ((quad ^ ((row >> 1) & 3)) << 4);
                cp16(d, Kg + (long long)(key0 + row) * ld + c * 32 + quad * 8);
            }
        // V tile (raw [k][n], 4 panels of 32 k-rows)
#pragma unroll
        for (int c = 0; c < 4; c++)
#pragma unroll
            for (int i = 0; i < 4; i++) {
                int id = t + i * 128, row = id >> 4, seg = id & 15;
                uint32_t d = vbase + c * 8704 + row * 272 + seg * 16;
                cp16(d, Vg + (long long)(key0 + c * 32 + row) * ld + seg * 8);
            }
        cp_commit();
        maskadd[t] = (mask[b * SS + key0 + t] != 0) ? 0.0f : -1e9f;
        cp_wait0();
        __syncthreads();

        // ---- S = Q K^T (fp16 accum) ----
        uint32_t sacc2[16][2];
#pragma unroll
        for (int ni = 0; ni < 16; ni++) { sacc2[ni][0] = 0u; sacc2[ni][1] = 0u; }
#pragma unroll
        for (int c = 0; c < 4; c++) {
            const uint32_t* As = Qs + c * 1024;
            const uint32_t* Bs = Ks + c * 2048;
#pragma unroll
            for (int ks = 0; ks < 2; ks++) {
                const int k0 = ks * 8 + tig, k1 = k0 + 4;
                int mr = m_off + gid;
                uint32_t aH[4] = {As[swz(mr, k0)], As[swz(mr + 8, k0)],
                                  As[swz(mr, k1)], As[swz(mr + 8, k1)]};
#pragma unroll
                for (int ni = 0; ni < 16; ni++) {
                    int n0 = ni * 8 + gid;
                    uint32_t bH[2] = {Bs[swz(n0, k0)], Bs[swz(n0, k1)]};
                    mma16h(sacc2[ni], aH, bH);
                }
            }
        }

        // ---- unpack + scale + mask + row-max ----
        float sacc[16][4];
        float tm0 = -1e30f, tm1 = -1e30f;
#pragma unroll
        for (int ni = 0; ni < 16; ni++) {
            float2 v01 = __half22float2(*reinterpret_cast<__half2*>(&sacc2[ni][0]));
            float2 v23 = __half22float2(*reinterpret_cast<__half2*>(&sacc2[ni][1]));
            float ma = maskadd[ni * 8 + 2 * tig], mb = maskadd[ni * 8 + 2 * tig + 1];
            float s0 = v01.x * 0.08838834764831843f + ma;
            float s1 = v01.y * 0.08838834764831843f + mb;
            float s2 = v23.x * 0.08838834764831843f + ma;
            float s3 = v23.y * 0.08838834764831843f + mb;
            sacc[ni][0] = s0; sacc[ni][1] = s1; sacc[ni][2] = s2; sacc[ni][3] = s3;
            tm0 = fmaxf(tm0, fmaxf(s0, s1));
            tm1 = fmaxf(tm1, fmaxf(s2, s3));
        }
        tm0 = fmaxf(tm0, __shfl_xor_sync(0xffffffff, tm0, 1));
        tm0 = fmaxf(tm0, __shfl_xor_sync(0xffffffff, tm0, 2));
        tm1 = fmaxf(tm1, __shfl_xor_sync(0xffffffff, tm1, 1));
        tm1 = fmaxf(tm1, __shfl_xor_sync(0xffffffff, tm1, 2));
        float mn0 = fmaxf(m0, tm0), mn1 = fmaxf(m1, tm1);
        float f0 = __expf(m0 - mn0), f1 = __expf(m1 - mn1);
        m0 = mn0; m1 = mn1;
#pragma unroll
        for (int ni = 0; ni < 16; ni++) {
            oacc[ni][0] *= f0; oacc[ni][1] *= f0;
            oacc[ni][2] *= f1; oacc[ni][3] *= f1;
        }

        // ---- exp -> P regs -> PV (V raw + LDSM4T, f32 accum) ----
        float tl0 = 0.f, tl1 = 0.f;
#pragma unroll
        for (int c = 0; c < 4; c++) {
            const uint32_t vpan = vbase + c * 8704;
#pragma unroll
            for (int ks = 0; ks < 2; ks++) {
                const int j = c * 2 + ks;
                float p00 = __expf(sacc[2*j][0]   - mn0), p01 = __expf(sacc[2*j][1]   - mn0);
                float p02 = __expf(sacc[2*j][2]   - mn1), p03 = __expf(sacc[2*j][3]   - mn1);
                float p10 = __expf(sacc[2*j+1][0] - mn0), p11 = __expf(sacc[2*j+1][1] - mn0);
                float p12 = __expf(sacc[2*j+1][2] - mn1), p13 = __expf(sacc[2*j+1][3] - mn1);
                tl0 += p00 + p01 + p10 + p11;
                tl1 += p02 + p03 + p12 + p13;
                uint32_t aP[4] = {h2pack(p00, p01), h2pack(p02, p03),
                                  h2pack(p10, p11), h2pack(p12, p13)};
                const uint32_t rbase = vpan + (ks * 16 + krl) * 272 + nc8 * 2;
#pragma unroll
                for (int p = 0; p < 8; p++) {
                    uint32_t bv[4];
                    LDSM4T(bv, rbase + p * 32);
                    mma16(oacc[2 * p],     aP, bv);
                    mma16(oacc[2 * p + 1], aP, bv + 2);
                }
            }
        }
        tl0 += __shfl_xor_sync(0xffffffff, tl0, 1);
        tl0 += __shfl_xor_sync(0xffffffff, tl0, 2);
        tl1 += __shfl_xor_sync(0xffffffff, tl1, 1);
        tl1 += __shfl_xor_sync(0xffffffff, tl1, 2);
        l0 = l0 * f0 + tl0;
        l1 = l1 * f1 + tl1;
        __syncthreads();
    }

    // ---- epilogue ----
    const float inv0 = 1.0f / l0, inv1 = 1.0f / l1;
    const long long r0 = (long long)(b * SS + q0 + m_off + gid) * ldctx + h * HD;
    const long long r1 = r0 + 8LL * ldctx;
#pragma unroll
    for (int ni = 0; ni < 16; ni++) {
        int n = ni * 8 + 2 * tig;
        *reinterpret_cast<uint32_t*>(ctx + r0 + n) = h2pack(oacc[ni][0] * inv0, oacc[ni][1] * inv0);
        *reinterpret_cast<uint32_t*>(ctx + r1 + n) = h2pack(oacc[ni][2] * inv1, oacc[ni][3] * inv1);
    }
}

// ---------------------------------------------------------------------------
// h2 GEMM (128 rows x 128 cols, K=256) + LN(128) + ReLU + head, fused.
// grid (1, 64), 256 thr. h2 tile staged in smem (pad 129).
// ---------------------------------------------------------------------------
__global__ __launch_bounds__(256)
void h2final_kernel(const hf* __restrict__ Ah, const hf* __restrict__ Bh,
                    const float* __restrict__ b2,
                    const float* __restrict__ g2, const float* __restrict__ be2,
                    const float* __restrict__ w3, const float* __restrict__ b3,
                    const int* __restrict__ tok, const int* __restrict__ mask,
                    const float* __restrict__ table, float* __restrict__ out)
{
    __shared__ __align__(16) uint32_t AsH[128 * 16];
    __shared__ __align__(16) uint32_t BsH[128 * 16];
    __shared__ float h2s[128 * 129];

    const int t = threadIdx.x, lane = t & 31, warp = t >> 5;
    const int gid = lane >> 2, tig = lane & 3;
    const int m_off = (warp >> 2) * 64, n_off = (warp & 3) * 32;
    const int brow = blockIdx.y * 128;

    float acc[4][4][4];
#pragma unroll
    for (int mi = 0; mi < 4; mi++)
#pragma unroll
        for (int ni = 0; ni < 4; ni++)
#pragma unroll
            for (int r = 0; r < 4; r++) acc[mi][ni][r] = 0.0f;

    for (int kt = 0; kt < METAD; kt += 32) {
#pragma unroll
        for (int i = 0; i < 2; i++) {
            int idx = t + i * 256, row = idx >> 2, quad = idx & 3;
            int base = row * 16 + ((quad ^ ((row >> 1) & 3)) << 2);
            *reinterpret_cast<uint4*>(&AsH[base]) =
                *reinterpret_cast<const uint4*>(Ah + (long long)(brow + row) * METAD + kt + quad * 8);
            *reinterpret_cast<uint4*>(&BsH[base]) =
                *reinterpret_cast<const uint4*>(Bh + (long long)row * METAD + kt + quad * 8);
        }
        __syncthreads();
#pragma unroll
        for (int ks = 0; ks < 2; ks++) {
            const int k0 = ks * 8 + tig, k1 = k0 + 4;
            uint32_t bH[4][2];
#pragma unroll
            for (int ni = 0; ni < 4; ni++) {
                int n0 = n_off + ni * 8 + gid;
                bH[ni][0] = BsH[swz(n0, k0)];
                bH[ni][1] = BsH[swz(n0, k1)];
            }
#pragma unroll
            for (int mi = 0; mi < 4; mi++) {
                int m0 = m_off + mi * 16 + gid;
                uint32_t aH[4] = {AsH[swz(m0, k0)], AsH[swz(m0 + 8, k0)],
                                  AsH[swz(m0, k1)], AsH[swz(m0 + 8, k1)]};
#pragma unroll
                for (int ni = 0; ni < 4; ni++)
                    mma16(acc[mi][ni], aH, bH[ni]);
            }
        }
        __syncthreads();
    }

    // stage h2 tile (+bias) in smem
#pragma unroll
    for (int mi = 0; mi < 4; mi++)
#pragma unroll
        for (int ni = 0; ni < 4; ni++) {
            int m = m_off + mi * 16 + gid;
            int n = n_off + ni * 8 + 2 * tig;
            float b0 = b2[n], b1 = b2[n + 1];
#pragma unroll
            for (int h = 0; h < 2; h++) {
                h2s[(m + h * 8) * 129 + n]     = acc[mi][ni][h * 2 + 0] + b0;
                h2s[(m + h * 8) * 129 + n + 1] = acc[mi][ni][h * 2 + 1] + b1;
            }
        }
    __syncthreads();

    // LN(128)+ReLU+dot(w3)+head, one thread per row
    if (t < 128) {
        const float* r = h2s + t * 129;
        float s = 0.f;
#pragma unroll 8
        for (int c = 0; c < 128; c++) s += r[c];
        const float mu = s * (1.0f / 128.0f);
        float v = 0.f;
#pragma unroll 8
        for (int c = 0; c < 128; c++) { float d = r[c] - mu; v += d * d; }
        const float rstd = rsqrtf(v * (1.0f / 128.0f) + 1e-5f);
        float dot = 0.f;
#pragma unroll 8
        for (int c = 0; c < 128; c++) {
            float y = fmaxf((r[c] - mu) * rstd * g2[c] + be2[c], 0.0f);
            dot += y * w3[c];
        }
        const int row = brow + t;
        float base = dot + b3[0];
        float w = base * (1.0f + table[tok[row]]);
        w = fminf(fmaxf(w, 0.1f), 5.0f);
        out[row] = (mask[row] != 0) ? w : 0.0f;
    }
}

// ---------------------------------------------------------------------------
// Fused prep (unchanged from R16)
// ---------------------------------------------------------------------------
__global__ void prep_kernel(const float* __restrict__ in_w, hf* __restrict__ iwh,
                            const float* __restrict__ out_w, hf* __restrict__ owh,
                            const float* __restrict__ w2, hf* __restrict__ w2h,
                            const float* __restrict__ w1, hf* __restrict__ wcomb,
                            hf* __restrict__ w1bh,
                            const float* __restrict__ b1, const float* __restrict__ out_b,
                            float* __restrict__ beff,
                            const float* __restrict__ hidden, const float* __restrict__ pos,
                            hf* __restrict__ xa)
{
    const int blk = blockIdx.x, t = threadIdx.x;
    if (blk < 3072) {
        int i = blk * 256 + t;
        float4 v = reinterpret_cast<const float4*>(in_w)[i];
        reinterpret_cast<uint32_t*>(iwh)[i * 2 + 0] = h2pack(v.x, v.y);
        reinterpret_cast<uint32_t*>(iwh)[i * 2 + 1] = h2pack(v.z, v.w);
    } else if (blk < 4096) {
        int i = (blk - 3072) * 256 + t;
        float4 v = reinterpret_cast<const float4*>(out_w)[i];
        reinterpret_cast<uint32_t*>(owh)[i * 2 + 0] = h2pack(v.x, v.y);
        reinterpret_cast<uint32_t*>(owh)[i * 2 + 1] = h2pack(v.z, v.w);
    } else if (blk < 4128) {
        int i = (blk - 4096) * 256 + t;
        float4 v = reinterpret_cast<const float4*>(w2)[i];
        reinterpret_cast<uint32_t*>(w2h)[i * 2 + 0] = h2pack(v.x, v.y);
        reinterpret_cast<uint32_t*>(w2h)[i * 2 + 1] = h2pack(v.z, v.w);
    } else if (blk < 4640) {
        int i = (blk - 4128) * 256 + t;
        float4 v = reinterpret_cast<const float4*>(w1)[i];
        int col = (i * 4) & 2047, row = (i * 4) >> 11;
        uint32_t a = h2pack(v.x, v.y), bb = h2pack(v.z, v.w);
        uint32_t* d;
        if (col < 1024) d = reinterpret_cast<uint32_t*>(wcomb + (long long)row * 2048 + col);
        else            d = reinterpret_cast<uint32_t*>(w1bh + (long long)row * 1024 + col - 1024);
        d[0] = a; d[1] = bb;
    } else if (blk < 4896) {
        const int i = blk - 4640;
        float s = 0.f;
        for (int k = t; k < 1024; k += 256) s += w1[(long long)i * 2048 + 1024 + k] * out_b[k];
        __shared__ float red[256];
        red[t] = s; __syncthreads();
        for (int st = 128; st > 0; st >>= 1) { if (t < st) red[t] += red[t + st]; __syncthreads(); }
        if (t == 0) beff[i] = b1[i] + red[0];
    } else {
        long long i = (long long)(blk - 4896) * 256 + t;
        const long long P4 = (long long)SS * HH / 4;
        float4 hv = reinterpret_cast<const float4*>(hidden)[i];
        float4 pv = reinterpret_cast<const float4*>(pos)[i % P4];
        long long row = i >> 8, c4 = i & 255;
        uint32_t* dst = reinterpret_cast<uint32_t*>(xa + row * 2048 + c4 * 4);
        dst[0] = h2pack(hv.x + pv.x, hv.y + pv.y);
        dst[1] = h2pack(hv.z + pv.z, hv.w + pv.w);
    }
}

// in-place fp16 LN+ReLU, width 256
__global__ void ln_relu_hf(hf* __restrict__ X, const float* __restrict__ g,
                           const float* __restrict__ beta)
{
    const int row = blockIdx.x, t = threadIdx.x;
    float v = __half2float(X[(long long)row * 256 + t]);
    __shared__ float red[256];
    red[t] = v; __syncthreads();
    for (int s = 128; s > 0; s >>= 1) { if (t < s) red[t] += red[t + s]; __syncthreads(); }
    const float mu = red[0] / 256.0f; __syncthreads();
    const float d = v - mu;
    red[t] = d * d; __syncthreads();
    for (int s = 128; s > 0; s >>= 1) { if (t < s) red[t] += red[t + s]; __syncthreads(); }
    const float var = red[0] / 256.0f;
    float y = fmaxf(d * rsqrtf(var + 1e-5f) * g[t] + beta[t], 0.0f);
    X[(long long)row * 256 + t] = __float2half_rn(y);
}

// ---------------- launch ----------------
extern "C" void kernel_launch(void* const* d_in, const int* in_sizes, int n_in,
                              void* d_out, int out_size)
{
    const float* hidden = (const float*)d_in[0];
    const int*   tok    = (const int*)d_in[1];
    const int*   mask   = (const int*)d_in[2];
    const float* pos    = (const float*)d_in[3];
    const float* in_w   = (const float*)d_in[4];
    const float* in_b   = (const float*)d_in[5];
    const float* out_w  = (const float*)d_in[6];
    const float* out_b  = (const float*)d_in[7];
    const float* w1     = (const float*)d_in[8];
    const float* b1     = (const float*)d_in[9];
    const float* g1     = (const float*)d_in[10];
    const float* be1    = (const float*)d_in[11];
    const float* w2     = (const float*)d_in[12];
    const float* b2     = (const float*)d_in[13];
    const float* g2     = (const float*)d_in[14];
    const float* be2    = (const float*)d_in[15];
    const float* w3     = (const float*)d_in[16];
    const float* b3     = (const float*)d_in[17];
    const float* table  = (const float*)d_in[18];
    float* out = (float*)d_out;

    float *beff;
    hf *xa,*qh,*hh,*iwh,*owh,*w2h,*wcomb,*w1bh;
    { void* p;
      cudaGetSymbolAddress(&p, g_beff); beff = (float*)p;
      cudaGetSymbolAddress(&p, g_xa);   xa = (hf*)p;
      cudaGetSymbolAddress(&p, g_qh);   qh = (hf*)p;
      cudaGetSymbolAddress(&p, g_hh);   hh = (hf*)p;
      cudaGetSymbolAddress(&p, g_iwh);  iwh = (hf*)p;
      cudaGetSymbolAddress(&p, g_owh);  owh = (hf*)p;
      cudaGetSymbolAddress(&p, g_w2h);  w2h = (hf*)p;
      cudaGetSymbolAddress(&p, g_wcomb); wcomb = (hf*)p;
      cudaGetSymbolAddress(&p, g_w1bh); w1bh = (hf*)p;
    }
    cudaFuncSetAttribute(flash5_kernel, cudaFuncAttributeMaxDynamicSharedMemorySize, F5_BYTES);

    prep_kernel<<<13088, 256>>>(in_w, iwh, out_w, owh, w2, w2h, w1, wcomb, w1bh,
                                b1, out_b, beff, hidden, pos, xa);

    // W_eff = w1b @ ow (NN)
    gmma<false><<<dim3(8, 2, 1), 256>>>(w1bh, owh, nullptr, wcomb + HH,
                                        HH, HH, HH, 2*HH, nullptr);

    // qkv = x @ in_w^T + in_b
    gmma<true><<<dim3(24, 64, 1), 256>>>(xa, iwh, nullptr, qh,
                                         HH, 2*HH, HH, 3*HH, in_b);

    // fused attention -> ctx into combined buffer cols 1024..
    flash5_kernel<<<dim3(SS/64, BB*NHEADS), 128, F5_BYTES>>>(qh, mask, xa + HH, 2*HH);

    // h1 = [x|ctx] @ [w1a|W_eff]^T + beff  (fp16 out)
    gmma<true><<<dim3(2, 64, 1), 256>>>(xa, wcomb, nullptr, hh,
                                        2*HH, 2*HH, 2*HH, METAD, beff);

    ln_relu_hf<<<ROWS, 256>>>(hh, g1, be1);

    // fused h2 GEMM + LN + head
    h2final_kernel<<<dim3(1, 64, 1), 256>>>(hh, w2h, b2, g2, be2, w3, b3,
                                            tok, mask, table, out);
}